// round 1
// baseline (speedup 1.0000x reference)
#include <cuda_runtime.h>
#include <cstdint>
#include <cstddef>

// Problem dims (fixed by the reference)
#define BB 8
#define NN 4096
#define DD 1024
#define KSLOT 128
#define MTOT (BB * NN)        // 32768
#define NCHUNK 32             // NN / 128

// ---------------- scratch (static device globals; no allocs) ----------------
__device__ float g_bufA[(size_t)MTOT * DD];     // 128 MiB
__device__ float g_bufB[(size_t)MTOT * DD];     // 128 MiB
__device__ float g_logits[(size_t)MTOT * KSLOT];// 16 MiB
__device__ float g_pm[BB * NCHUNK * KSLOT];
__device__ float g_ps[BB * NCHUNK * KSLOT];
__device__ float g_M[BB * KSLOT];
__device__ float g_S[BB * KSLOT];

#define NEG_INF __int_as_float(0xff800000)

// ---------------- small helpers ----------------
__device__ __forceinline__ uint32_t f2tf32(float x) {
    uint32_t r;
    asm("cvt.rna.tf32.f32 %0, %1;" : "=r"(r) : "f"(x));
    return r;
}

__device__ __forceinline__ void mma_tf32(float* c,
                                         uint32_t a0, uint32_t a1, uint32_t a2, uint32_t a3,
                                         uint32_t b0, uint32_t b1) {
    asm volatile(
        "mma.sync.aligned.m16n8k8.row.col.f32.tf32.tf32.f32 "
        "{%0,%1,%2,%3}, {%4,%5,%6,%7}, {%8,%9}, {%0,%1,%2,%3};"
        : "+f"(c[0]), "+f"(c[1]), "+f"(c[2]), "+f"(c[3])
        : "r"(a0), "r"(a1), "r"(a2), "r"(a3), "r"(b0), "r"(b1));
}

__device__ __forceinline__ uint32_t smem_u32(const void* p) {
    return (uint32_t)__cvta_generic_to_shared(p);
}

#define CP_ASYNC16(dst, src) \
    asm volatile("cp.async.cg.shared.global [%0], [%1], 16;\n" ::"r"(dst), "l"(src))
#define CP_COMMIT() asm volatile("cp.async.commit_group;\n")
#define CP_WAIT(N_) asm volatile("cp.async.wait_group %0;\n" ::"n"(N_))

// ---------------- 3xTF32 NT GEMM: C[M,N] = A[M,K] * B[N,K]^T (+bias) ----------------
// BM=128 BN=128 BK=16, 256 threads, warps 4(m) x 2(n), warp tile 32x64
__global__ void __launch_bounds__(256, 1)
gemm3x_kernel(const float* __restrict__ A, const float* __restrict__ B,
              const float* __restrict__ bias, float* __restrict__ C,
              int M, int N, int K) {
    __shared__ float As[2][128][20];
    __shared__ float Bs[2][128][20];

    const int tid  = threadIdx.x;
    const int lane = tid & 31;
    const int warp = tid >> 5;
    const int wm   = warp & 3;   // 0..3
    const int wn   = warp >> 2;  // 0..1
    const int g    = lane >> 2;  // 0..7
    const int t    = lane & 3;   // 0..3

    const int brow = blockIdx.y * 128;
    const int bcol = blockIdx.x * 128;

    float acc[2][8][4];
#pragma unroll
    for (int i = 0; i < 2; ++i)
#pragma unroll
        for (int j = 0; j < 8; ++j)
#pragma unroll
            for (int q = 0; q < 4; ++q) acc[i][j][q] = 0.f;

    const int r0 = tid >> 2;         // 0..63
    const int kc = (tid & 3) * 4;    // 0,4,8,12
    const int ktiles = K / 16;

    auto issue = [&](int kt, int s) {
        const float* Ag = A + (size_t)(brow + r0) * K + kt * 16 + kc;
        const float* Bg = B + (size_t)(bcol + r0) * K + kt * 16 + kc;
        CP_ASYNC16(smem_u32(&As[s][r0][kc]),      Ag);
        CP_ASYNC16(smem_u32(&As[s][r0 + 64][kc]), Ag + (size_t)64 * K);
        CP_ASYNC16(smem_u32(&Bs[s][r0][kc]),      Bg);
        CP_ASYNC16(smem_u32(&Bs[s][r0 + 64][kc]), Bg + (size_t)64 * K);
    };

    issue(0, 0);
    CP_COMMIT();

    for (int kt = 0; kt < ktiles; ++kt) {
        const int cur = kt & 1;
        if (kt + 1 < ktiles) {
            issue(kt + 1, (kt + 1) & 1);
            CP_COMMIT();
            CP_WAIT(1);
        } else {
            CP_WAIT(0);
        }
        __syncthreads();

#pragma unroll
        for (int ks = 0; ks < 2; ++ks) {
            const int kb = ks * 8;

            uint32_t ah[2][4], al[2][4];
#pragma unroll
            for (int mt = 0; mt < 2; ++mt) {
                const int row = wm * 32 + mt * 16 + g;
                float v0 = As[cur][row][kb + t];
                float v1 = As[cur][row + 8][kb + t];
                float v2 = As[cur][row][kb + t + 4];
                float v3 = As[cur][row + 8][kb + t + 4];
                ah[mt][0] = f2tf32(v0); al[mt][0] = f2tf32(v0 - __uint_as_float(ah[mt][0]));
                ah[mt][1] = f2tf32(v1); al[mt][1] = f2tf32(v1 - __uint_as_float(ah[mt][1]));
                ah[mt][2] = f2tf32(v2); al[mt][2] = f2tf32(v2 - __uint_as_float(ah[mt][2]));
                ah[mt][3] = f2tf32(v3); al[mt][3] = f2tf32(v3 - __uint_as_float(ah[mt][3]));
            }

            uint32_t bh[8][2], bl[8][2];
#pragma unroll
            for (int nt = 0; nt < 8; ++nt) {
                const int col = wn * 64 + nt * 8 + g;
                float v0 = Bs[cur][col][kb + t];
                float v1 = Bs[cur][col][kb + t + 4];
                bh[nt][0] = f2tf32(v0); bl[nt][0] = f2tf32(v0 - __uint_as_float(bh[nt][0]));
                bh[nt][1] = f2tf32(v1); bl[nt][1] = f2tf32(v1 - __uint_as_float(bh[nt][1]));
            }

#pragma unroll
            for (int mt = 0; mt < 2; ++mt)
#pragma unroll
                for (int nt = 0; nt < 8; ++nt) {
                    mma_tf32(acc[mt][nt], al[mt][0], al[mt][1], al[mt][2], al[mt][3],
                             bh[nt][0], bh[nt][1]);
                    mma_tf32(acc[mt][nt], ah[mt][0], ah[mt][1], ah[mt][2], ah[mt][3],
                             bl[nt][0], bl[nt][1]);
                    mma_tf32(acc[mt][nt], ah[mt][0], ah[mt][1], ah[mt][2], ah[mt][3],
                             bh[nt][0], bh[nt][1]);
                }
        }
        __syncthreads();
    }

    // epilogue
#pragma unroll
    for (int mt = 0; mt < 2; ++mt) {
        const int row = brow + wm * 32 + mt * 16 + g;
#pragma unroll
        for (int nt = 0; nt < 8; ++nt) {
            const int col = bcol + wn * 64 + nt * 8 + t * 2;
            float c0 = acc[mt][nt][0], c1 = acc[mt][nt][1];
            float c2 = acc[mt][nt][2], c3 = acc[mt][nt][3];
            if (bias) {
                float b0 = bias[col], b1 = bias[col + 1];
                c0 += b0; c1 += b1; c2 += b0; c3 += b1;
            }
            *reinterpret_cast<float2*>(C + (size_t)row * N + col) = make_float2(c0, c1);
            *reinterpret_cast<float2*>(C + (size_t)(row + 8) * N + col) = make_float2(c2, c3);
        }
    }
}

// ---------------- LayerNorm over last dim (D=1024), one row per block ----------------
__global__ void ln_kernel(const float* __restrict__ x, const float* __restrict__ gg,
                          const float* __restrict__ bb, float* __restrict__ y) {
    const int row = blockIdx.x;
    const int tid = threadIdx.x;  // 256
    const float4 v = reinterpret_cast<const float4*>(x + (size_t)row * DD)[tid];

    __shared__ float red[8];
    float s = v.x + v.y + v.z + v.w;
#pragma unroll
    for (int o = 16; o > 0; o >>= 1) s += __shfl_xor_sync(0xffffffffu, s, o);
    if ((tid & 31) == 0) red[tid >> 5] = s;
    __syncthreads();
    float tot = 0.f;
#pragma unroll
    for (int i = 0; i < 8; ++i) tot += red[i];
    const float mean = tot * (1.f / DD);

    const float dx = v.x - mean, dy = v.y - mean, dz = v.z - mean, dw = v.w - mean;
    float q = dx * dx + dy * dy + dz * dz + dw * dw;
#pragma unroll
    for (int o = 16; o > 0; o >>= 1) q += __shfl_xor_sync(0xffffffffu, q, o);
    __syncthreads();
    if ((tid & 31) == 0) red[tid >> 5] = q;
    __syncthreads();
    float qtot = 0.f;
#pragma unroll
    for (int i = 0; i < 8; ++i) qtot += red[i];
    const float r = rsqrtf(qtot * (1.f / DD) + 1e-5f);

    const float4 g4 = reinterpret_cast<const float4*>(gg)[tid];
    const float4 b4 = reinterpret_cast<const float4*>(bb)[tid];
    float4 o;
    o.x = dx * r * g4.x + b4.x;
    o.y = dy * r * g4.y + b4.y;
    o.z = dz * r * g4.z + b4.z;
    o.w = dw * r * g4.w + b4.w;
    reinterpret_cast<float4*>(y + (size_t)row * DD)[tid] = o;
}

// ---------------- final: out = relu(LN(h) + x_residual) ----------------
__global__ void final_kernel(const float* __restrict__ h, const float* __restrict__ xres,
                             const float* __restrict__ gg, const float* __restrict__ bb,
                             float* __restrict__ out) {
    const int row = blockIdx.x;
    const int tid = threadIdx.x;  // 256
    const float4 v = reinterpret_cast<const float4*>(h + (size_t)row * DD)[tid];

    __shared__ float red[8];
    float s = v.x + v.y + v.z + v.w;
#pragma unroll
    for (int o = 16; o > 0; o >>= 1) s += __shfl_xor_sync(0xffffffffu, s, o);
    if ((tid & 31) == 0) red[tid >> 5] = s;
    __syncthreads();
    float tot = 0.f;
#pragma unroll
    for (int i = 0; i < 8; ++i) tot += red[i];
    const float mean = tot * (1.f / DD);

    const float dx = v.x - mean, dy = v.y - mean, dz = v.z - mean, dw = v.w - mean;
    float q = dx * dx + dy * dy + dz * dz + dw * dw;
#pragma unroll
    for (int o = 16; o > 0; o >>= 1) q += __shfl_xor_sync(0xffffffffu, q, o);
    __syncthreads();
    if ((tid & 31) == 0) red[tid >> 5] = q;
    __syncthreads();
    float qtot = 0.f;
#pragma unroll
    for (int i = 0; i < 8; ++i) qtot += red[i];
    const float r = rsqrtf(qtot * (1.f / DD) + 1e-5f);

    const float4 g4 = reinterpret_cast<const float4*>(gg)[tid];
    const float4 b4 = reinterpret_cast<const float4*>(bb)[tid];
    const float4 xv = reinterpret_cast<const float4*>(xres + (size_t)row * DD)[tid];
    float4 o;
    o.x = fmaxf(dx * r * g4.x + b4.x + xv.x, 0.f);
    o.y = fmaxf(dy * r * g4.y + b4.y + xv.y, 0.f);
    o.z = fmaxf(dz * r * g4.z + b4.z + xv.z, 0.f);
    o.w = fmaxf(dw * r * g4.w + b4.w + xv.w, 0.f);
    reinterpret_cast<float4*>(out + (size_t)row * DD)[tid] = o;
}

// ---------------- softmax over positions (axis=N), 3 passes ----------------
// pass1: per (b, chunk-of-128-n, k): online max / scaled-sum partials. Coalesced rows.
__global__ void softmax_pass1(const float* __restrict__ logits) {
    const int b = blockIdx.x;
    const int c = blockIdx.y;
    const int k = threadIdx.x;  // 128
    const float* p = logits + ((size_t)b * NN + (size_t)c * 128) * KSLOT + k;
    float m = NEG_INF, s = 0.f;
#pragma unroll 4
    for (int r = 0; r < 128; ++r) {
        const float v = p[(size_t)r * KSLOT];
        const float mn = fmaxf(m, v);
        s = s * expf(m - mn) + expf(v - mn);
        m = mn;
    }
    g_pm[(b * NCHUNK + c) * KSLOT + k] = m;
    g_ps[(b * NCHUNK + c) * KSLOT + k] = s;
}

// pass2: combine 32 chunk partials per (b,k)
__global__ void softmax_pass2() {
    const int b = blockIdx.x;
    const int k = threadIdx.x;  // 128
    float M = NEG_INF;
#pragma unroll
    for (int c = 0; c < NCHUNK; ++c) M = fmaxf(M, g_pm[(b * NCHUNK + c) * KSLOT + k]);
    float S = 0.f;
#pragma unroll
    for (int c = 0; c < NCHUNK; ++c)
        S += g_ps[(b * NCHUNK + c) * KSLOT + k] * expf(g_pm[(b * NCHUNK + c) * KSLOT + k] - M);
    g_M[b * KSLOT + k] = M;
    g_S[b * KSLOT + k] = S;
}

// pass3: p = exp(a-M)/S, then L1-normalize across K per (b,n). One (b,n) per block.
__global__ void softmax_pass3(float* __restrict__ logits) {
    const int idx = blockIdx.x;       // 0..32767
    const int b = idx >> 12;          // /4096
    const int k = threadIdx.x;        // 128
    const size_t off = (size_t)idx * KSLOT + k;
    const float p = expf(logits[off] - g_M[b * KSLOT + k]) / g_S[b * KSLOT + k];

    float s = p;
#pragma unroll
    for (int o = 16; o > 0; o >>= 1) s += __shfl_xor_sync(0xffffffffu, s, o);
    __shared__ float red[4];
    if ((k & 31) == 0) red[k >> 5] = s;
    __syncthreads();
    const float tot = red[0] + red[1] + red[2] + red[3];
    logits[off] = p / (1e-9f + tot);
}

// ---------------- launch ----------------
extern "C" void kernel_launch(void* const* d_in, const int* in_sizes, int n_in,
                              void* d_out, int out_size) {
    const float* x     = (const float*)d_in[0];
    const float* ln_g  = (const float*)d_in[1];
    const float* ln_b  = (const float*)d_in[2];
    const float* w_in  = (const float*)d_in[3];
    const float* b_in  = (const float*)d_in[4];
    const float* w0    = (const float*)d_in[5];
    const float* w1    = (const float*)d_in[6];
    const float* w_out = (const float*)d_in[7];
    const float* og    = (const float*)d_in[8];
    const float* ob    = (const float*)d_in[9];
    float* out = (float*)d_out;

    static float* bufA   = nullptr;
    static float* bufB   = nullptr;
    static float* logits = nullptr;
    if (!bufA) {
        cudaGetSymbolAddress((void**)&bufA, g_bufA);
        cudaGetSymbolAddress((void**)&bufB, g_bufB);
        cudaGetSymbolAddress((void**)&logits, g_logits);
    }

    // 1) xn = LN(x)
    ln_kernel<<<MTOT, 256>>>(x, ln_g, ln_b, bufA);
    // 2) h1 = xn @ w_in^T + b_in      (32768 x 1024 x 1024)
    gemm3x_kernel<<<dim3(DD / 128, MTOT / 128), 256>>>(bufA, w_in, b_in, bufB, MTOT, DD, DD);
    // 3) logits = h1 @ w0^T           (32768 x 128 x 1024)
    gemm3x_kernel<<<dim3(1, MTOT / 128), 256>>>(bufB, w0, nullptr, logits, MTOT, KSLOT, DD);
    // 4) softmax over N, then L1 over K
    softmax_pass1<<<dim3(BB, NCHUNK), 128>>>(logits);
    softmax_pass2<<<BB, 128>>>();
    softmax_pass3<<<MTOT, 128>>>(logits);
    // 5) h2 = a @ w1^T                (32768 x 1024 x 128)
    gemm3x_kernel<<<dim3(DD / 128, MTOT / 128), 256>>>(logits, w1, nullptr, bufA, MTOT, DD, KSLOT);
    // 6) h3 = h2 @ w_out^T            (32768 x 1024 x 1024)
    gemm3x_kernel<<<dim3(DD / 128, MTOT / 128), 256>>>(bufA, w_out, nullptr, bufB, MTOT, DD, DD);
    // 7) out = relu(LN(h3) + x)
    final_kernel<<<MTOT, 256>>>(bufB, x, og, ob, out);
}

// round 3
// speedup vs baseline: 4.0482x; 4.0482x over previous
#include <cuda_runtime.h>
#include <cstdint>
#include <cstddef>

// Problem dims (fixed by the reference)
#define BB 8
#define NN 4096
#define DD 1024
#define KSLOT 128
#define MTOT (BB * NN)        // 32768
#define NCHUNK 32             // NN / 128

// ---------------- scratch (static device globals; no allocs) ----------------
__device__ float g_bufA[(size_t)MTOT * DD];     // xn (LN(x)) — 128 MiB
__device__ float g_bufB[(size_t)MTOT * DD];     // h3 — 128 MiB
__device__ float g_logits[(size_t)MTOT * KSLOT];// 16 MiB
__device__ float g_pm[BB * NCHUNK * KSLOT];
__device__ float g_ps[BB * NCHUNK * KSLOT];
__device__ float g_M[BB * KSLOT];
__device__ float g_S[BB * KSLOT];
// fused weights
__device__ float g_winT[(size_t)DD * DD];       // w_in^T  (d, e)
__device__ float g_Wa[(size_t)KSLOT * DD];      // (w0 @ w_in)  (128 x 1024), [k,d]
__device__ float g_ba[KSLOT];                   // w0 @ b_in
__device__ float g_w1t[(size_t)KSLOT * DD];     // w1^T (128 x 1024), [k,d]
__device__ float g_Wb[(size_t)DD * KSLOT];      // (w_out @ w1) (1024 x 128), [e,k]

#define NEG_INF __int_as_float(0xff800000)

// ---------------- small helpers ----------------
__device__ __forceinline__ uint32_t f2tf32(float x) {
    uint32_t r;
    asm("cvt.rna.tf32.f32 %0, %1;" : "=r"(r) : "f"(x));
    return r;
}

__device__ __forceinline__ void mma_tf32(float* c,
                                         uint32_t a0, uint32_t a1, uint32_t a2, uint32_t a3,
                                         uint32_t b0, uint32_t b1) {
    asm volatile(
        "mma.sync.aligned.m16n8k8.row.col.f32.tf32.tf32.f32 "
        "{%0,%1,%2,%3}, {%4,%5,%6,%7}, {%8,%9}, {%0,%1,%2,%3};"
        : "+f"(c[0]), "+f"(c[1]), "+f"(c[2]), "+f"(c[3])
        : "r"(a0), "r"(a1), "r"(a2), "r"(a3), "r"(b0), "r"(b1));
}

__device__ __forceinline__ uint32_t smem_u32(const void* p) {
    return (uint32_t)__cvta_generic_to_shared(p);
}

#define CP_ASYNC16(dst, src) \
    asm volatile("cp.async.cg.shared.global [%0], [%1], 16;\n" ::"r"(dst), "l"(src))
#define CP_COMMIT() asm volatile("cp.async.commit_group;\n")
#define CP_WAIT(N_) asm volatile("cp.async.wait_group %0;\n" ::"n"(N_))

// ---------------- 3xTF32 NT GEMM: C[M,N] = A[M,K] * B[N,K]^T (+bias) ----------------
// BM=128 BN=128 BK=16, 256 threads, warps 4(m) x 2(n), warp tile 32x64
__global__ void __launch_bounds__(256, 1)
gemm3x_kernel(const float* __restrict__ A, const float* __restrict__ B,
              const float* __restrict__ bias, float* __restrict__ C,
              int M, int N, int K) {
    __shared__ float As[2][128][20];
    __shared__ float Bs[2][128][20];

    const int tid  = threadIdx.x;
    const int lane = tid & 31;
    const int warp = tid >> 5;
    const int wm   = warp & 3;   // 0..3
    const int wn   = warp >> 2;  // 0..1
    const int g    = lane >> 2;  // 0..7
    const int t    = lane & 3;   // 0..3

    const int brow = blockIdx.y * 128;
    const int bcol = blockIdx.x * 128;

    float acc[2][8][4];
#pragma unroll
    for (int i = 0; i < 2; ++i)
#pragma unroll
        for (int j = 0; j < 8; ++j)
#pragma unroll
            for (int q = 0; q < 4; ++q) acc[i][j][q] = 0.f;

    const int r0 = tid >> 2;         // 0..63
    const int kc = (tid & 3) * 4;    // 0,4,8,12
    const int ktiles = K / 16;

    auto issue = [&](int kt, int s) {
        const float* Ag = A + (size_t)(brow + r0) * K + kt * 16 + kc;
        const float* Bg = B + (size_t)(bcol + r0) * K + kt * 16 + kc;
        CP_ASYNC16(smem_u32(&As[s][r0][kc]),      Ag);
        CP_ASYNC16(smem_u32(&As[s][r0 + 64][kc]), Ag + (size_t)64 * K);
        CP_ASYNC16(smem_u32(&Bs[s][r0][kc]),      Bg);
        CP_ASYNC16(smem_u32(&Bs[s][r0 + 64][kc]), Bg + (size_t)64 * K);
    };

    issue(0, 0);
    CP_COMMIT();

    for (int kt = 0; kt < ktiles; ++kt) {
        const int cur = kt & 1;
        if (kt + 1 < ktiles) {
            issue(kt + 1, (kt + 1) & 1);
            CP_COMMIT();
            CP_WAIT(1);
        } else {
            CP_WAIT(0);
        }
        __syncthreads();

#pragma unroll
        for (int ks = 0; ks < 2; ++ks) {
            const int kb = ks * 8;

            uint32_t ah[2][4], al[2][4];
#pragma unroll
            for (int mt = 0; mt < 2; ++mt) {
                const int row = wm * 32 + mt * 16 + g;
                float v0 = As[cur][row][kb + t];
                float v1 = As[cur][row + 8][kb + t];
                float v2 = As[cur][row][kb + t + 4];
                float v3 = As[cur][row + 8][kb + t + 4];
                ah[mt][0] = f2tf32(v0); al[mt][0] = f2tf32(v0 - __uint_as_float(ah[mt][0]));
                ah[mt][1] = f2tf32(v1); al[mt][1] = f2tf32(v1 - __uint_as_float(ah[mt][1]));
                ah[mt][2] = f2tf32(v2); al[mt][2] = f2tf32(v2 - __uint_as_float(ah[mt][2]));
                ah[mt][3] = f2tf32(v3); al[mt][3] = f2tf32(v3 - __uint_as_float(ah[mt][3]));
            }

            uint32_t bh[8][2], bl[8][2];
#pragma unroll
            for (int nt = 0; nt < 8; ++nt) {
                const int col = wn * 64 + nt * 8 + g;
                float v0 = Bs[cur][col][kb + t];
                float v1 = Bs[cur][col][kb + t + 4];
                bh[nt][0] = f2tf32(v0); bl[nt][0] = f2tf32(v0 - __uint_as_float(bh[nt][0]));
                bh[nt][1] = f2tf32(v1); bl[nt][1] = f2tf32(v1 - __uint_as_float(bh[nt][1]));
            }

#pragma unroll
            for (int mt = 0; mt < 2; ++mt)
#pragma unroll
                for (int nt = 0; nt < 8; ++nt) {
                    mma_tf32(acc[mt][nt], al[mt][0], al[mt][1], al[mt][2], al[mt][3],
                             bh[nt][0], bh[nt][1]);
                    mma_tf32(acc[mt][nt], ah[mt][0], ah[mt][1], ah[mt][2], ah[mt][3],
                             bl[nt][0], bl[nt][1]);
                    mma_tf32(acc[mt][nt], ah[mt][0], ah[mt][1], ah[mt][2], ah[mt][3],
                             bh[nt][0], bh[nt][1]);
                }
        }
        __syncthreads();
    }

    // epilogue
#pragma unroll
    for (int mt = 0; mt < 2; ++mt) {
        const int row = brow + wm * 32 + mt * 16 + g;
#pragma unroll
        for (int nt = 0; nt < 8; ++nt) {
            const int col = bcol + wn * 64 + nt * 8 + t * 2;
            float c0 = acc[mt][nt][0], c1 = acc[mt][nt][1];
            float c2 = acc[mt][nt][2], c3 = acc[mt][nt][3];
            if (bias) {
                float b0 = bias[col], b1 = bias[col + 1];
                c0 += b0; c1 += b1; c2 += b0; c3 += b1;
            }
            *reinterpret_cast<float2*>(C + (size_t)row * N + col) = make_float2(c0, c1);
            *reinterpret_cast<float2*>(C + (size_t)(row + 8) * N + col) = make_float2(c2, c3);
        }
    }
}

// ---------------- weight prep ----------------
// generic transpose: src (R x C) -> dst (C x R)
__global__ void transpose_kernel(const float* __restrict__ src, float* __restrict__ dst,
                                 int R, int C) {
    __shared__ float tile[32][33];
    const int x = blockIdx.x * 32 + threadIdx.x;  // col in src
    const int y = blockIdx.y * 32 + threadIdx.y;  // row in src
    if (x < C && y < R) tile[threadIdx.y][threadIdx.x] = src[(size_t)y * C + x];
    __syncthreads();
    const int xo = blockIdx.y * 32 + threadIdx.x; // col in dst (= row in src)
    const int yo = blockIdx.x * 32 + threadIdx.y; // row in dst (= col in src)
    if (xo < R && yo < C) dst[(size_t)yo * R + xo] = tile[threadIdx.x][threadIdx.y];
}

// ba[k] = sum_e w0[k,e] * b_in[e]
__global__ void fuse_bias_kernel(const float* __restrict__ w0, const float* __restrict__ b_in,
                                 float* __restrict__ ba) {
    const int k = threadIdx.x;  // 128
    const float4* wr = reinterpret_cast<const float4*>(w0 + (size_t)k * DD);
    const float4* br = reinterpret_cast<const float4*>(b_in);
    float s = 0.f;
#pragma unroll 4
    for (int i = 0; i < DD / 4; ++i) {
        const float4 w = wr[i];
        const float4 b = br[i];
        s += w.x * b.x + w.y * b.y + w.z * b.z + w.w * b.w;
    }
    ba[k] = s;
}

// ---------------- LayerNorm over last dim (D=1024), one row per block ----------------
__global__ void ln_kernel(const float* __restrict__ x, const float* __restrict__ gg,
                          const float* __restrict__ bb, float* __restrict__ y) {
    const int row = blockIdx.x;
    const int tid = threadIdx.x;  // 256
    const float4 v = reinterpret_cast<const float4*>(x + (size_t)row * DD)[tid];

    __shared__ float red[8];
    float s = v.x + v.y + v.z + v.w;
#pragma unroll
    for (int o = 16; o > 0; o >>= 1) s += __shfl_xor_sync(0xffffffffu, s, o);
    if ((tid & 31) == 0) red[tid >> 5] = s;
    __syncthreads();
    float tot = 0.f;
#pragma unroll
    for (int i = 0; i < 8; ++i) tot += red[i];
    const float mean = tot * (1.f / DD);

    const float dx = v.x - mean, dy = v.y - mean, dz = v.z - mean, dw = v.w - mean;
    float q = dx * dx + dy * dy + dz * dz + dw * dw;
#pragma unroll
    for (int o = 16; o > 0; o >>= 1) q += __shfl_xor_sync(0xffffffffu, q, o);
    __syncthreads();
    if ((tid & 31) == 0) red[tid >> 5] = q;
    __syncthreads();
    float qtot = 0.f;
#pragma unroll
    for (int i = 0; i < 8; ++i) qtot += red[i];
    const float r = rsqrtf(qtot * (1.f / DD) + 1e-5f);

    const float4 g4 = reinterpret_cast<const float4*>(gg)[tid];
    const float4 b4 = reinterpret_cast<const float4*>(bb)[tid];
    float4 o;
    o.x = dx * r * g4.x + b4.x;
    o.y = dy * r * g4.y + b4.y;
    o.z = dz * r * g4.z + b4.z;
    o.w = dw * r * g4.w + b4.w;
    reinterpret_cast<float4*>(y + (size_t)row * DD)[tid] = o;
}

// ---------------- final: out = relu(LN(h) + x_residual) ----------------
__global__ void final_kernel(const float* __restrict__ h, const float* __restrict__ xres,
                             const float* __restrict__ gg, const float* __restrict__ bb,
                             float* __restrict__ out) {
    const int row = blockIdx.x;
    const int tid = threadIdx.x;  // 256
    const float4 v = reinterpret_cast<const float4*>(h + (size_t)row * DD)[tid];

    __shared__ float red[8];
    float s = v.x + v.y + v.z + v.w;
#pragma unroll
    for (int o = 16; o > 0; o >>= 1) s += __shfl_xor_sync(0xffffffffu, s, o);
    if ((tid & 31) == 0) red[tid >> 5] = s;
    __syncthreads();
    float tot = 0.f;
#pragma unroll
    for (int i = 0; i < 8; ++i) tot += red[i];
    const float mean = tot * (1.f / DD);

    const float dx = v.x - mean, dy = v.y - mean, dz = v.z - mean, dw = v.w - mean;
    float q = dx * dx + dy * dy + dz * dz + dw * dw;
#pragma unroll
    for (int o = 16; o > 0; o >>= 1) q += __shfl_xor_sync(0xffffffffu, q, o);
    __syncthreads();
    if ((tid & 31) == 0) red[tid >> 5] = q;
    __syncthreads();
    float qtot = 0.f;
#pragma unroll
    for (int i = 0; i < 8; ++i) qtot += red[i];
    const float r = rsqrtf(qtot * (1.f / DD) + 1e-5f);

    const float4 g4 = reinterpret_cast<const float4*>(gg)[tid];
    const float4 b4 = reinterpret_cast<const float4*>(bb)[tid];
    const float4 xv = reinterpret_cast<const float4*>(xres + (size_t)row * DD)[tid];
    float4 o;
    o.x = fmaxf(dx * r * g4.x + b4.x + xv.x, 0.f);
    o.y = fmaxf(dy * r * g4.y + b4.y + xv.y, 0.f);
    o.z = fmaxf(dz * r * g4.z + b4.z + xv.z, 0.f);
    o.w = fmaxf(dw * r * g4.w + b4.w + xv.w, 0.f);
    reinterpret_cast<float4*>(out + (size_t)row * DD)[tid] = o;
}

// ---------------- softmax over positions (axis=N), 3 passes ----------------
__global__ void softmax_pass1(const float* __restrict__ logits) {
    const int b = blockIdx.x;
    const int c = blockIdx.y;
    const int k = threadIdx.x;  // 128
    const float* p = logits + ((size_t)b * NN + (size_t)c * 128) * KSLOT + k;
    float m = NEG_INF, s = 0.f;
#pragma unroll 4
    for (int r = 0; r < 128; ++r) {
        const float v = p[(size_t)r * KSLOT];
        const float mn = fmaxf(m, v);
        s = s * expf(m - mn) + expf(v - mn);
        m = mn;
    }
    g_pm[(b * NCHUNK + c) * KSLOT + k] = m;
    g_ps[(b * NCHUNK + c) * KSLOT + k] = s;
}

__global__ void softmax_pass2() {
    const int b = blockIdx.x;
    const int k = threadIdx.x;  // 128
    float M = NEG_INF;
#pragma unroll
    for (int c = 0; c < NCHUNK; ++c) M = fmaxf(M, g_pm[(b * NCHUNK + c) * KSLOT + k]);
    float S = 0.f;
#pragma unroll
    for (int c = 0; c < NCHUNK; ++c)
        S += g_ps[(b * NCHUNK + c) * KSLOT + k] * expf(g_pm[(b * NCHUNK + c) * KSLOT + k] - M);
    g_M[b * KSLOT + k] = M;
    g_S[b * KSLOT + k] = S;
}

__global__ void softmax_pass3(float* __restrict__ logits) {
    const int idx = blockIdx.x;       // 0..32767
    const int b = idx >> 12;          // /4096
    const int k = threadIdx.x;        // 128
    const size_t off = (size_t)idx * KSLOT + k;
    const float p = expf(logits[off] - g_M[b * KSLOT + k]) / g_S[b * KSLOT + k];

    float s = p;
#pragma unroll
    for (int o = 16; o > 0; o >>= 1) s += __shfl_xor_sync(0xffffffffu, s, o);
    __shared__ float red[4];
    if ((k & 31) == 0) red[k >> 5] = s;
    __syncthreads();
    const float tot = red[0] + red[1] + red[2] + red[3];
    logits[off] = p / (1e-9f + tot);
}

// ---------------- launch ----------------
extern "C" void kernel_launch(void* const* d_in, const int* in_sizes, int n_in,
                              void* d_out, int out_size) {
    const float* x     = (const float*)d_in[0];
    const float* ln_g  = (const float*)d_in[1];
    const float* ln_b  = (const float*)d_in[2];
    const float* w_in  = (const float*)d_in[3];
    const float* b_in  = (const float*)d_in[4];
    const float* w0    = (const float*)d_in[5];
    const float* w1    = (const float*)d_in[6];
    const float* w_out = (const float*)d_in[7];
    const float* og    = (const float*)d_in[8];
    const float* ob    = (const float*)d_in[9];
    float* out = (float*)d_out;

    static float* bufA = nullptr; static float* bufB = nullptr;
    static float* logits = nullptr;
    static float* winT = nullptr;
    static float* Wa = nullptr; static float* ba = nullptr;
    static float* w1t = nullptr; static float* Wb = nullptr;
    if (!bufA) {
        cudaGetSymbolAddress((void**)&bufA, g_bufA);
        cudaGetSymbolAddress((void**)&bufB, g_bufB);
        cudaGetSymbolAddress((void**)&logits, g_logits);
        cudaGetSymbolAddress((void**)&winT, g_winT);
        cudaGetSymbolAddress((void**)&Wa, g_Wa);
        cudaGetSymbolAddress((void**)&ba, g_ba);
        cudaGetSymbolAddress((void**)&w1t, g_w1t);
        cudaGetSymbolAddress((void**)&Wb, g_Wb);
    }

    // ---- weight fusion (tiny) ----
    // winT[d,e] = w_in[e,d]
    transpose_kernel<<<dim3(DD / 32, DD / 32), dim3(32, 32)>>>(w_in, winT, DD, DD);
    // Wa[k,d] = sum_e w0[k,e] * winT[d,e]   (= w0 @ w_in)
    gemm3x_kernel<<<dim3(DD / 128, 1), 256>>>(w0, winT, nullptr, Wa, KSLOT, DD, DD);
    // ba[k] = sum_e w0[k,e] * b_in[e]
    fuse_bias_kernel<<<1, 128>>>(w0, b_in, ba);
    // w1t[k,d] = w1[d,k]
    transpose_kernel<<<dim3(KSLOT / 32, DD / 32), dim3(32, 32)>>>(w1, w1t, DD, KSLOT);
    // Wb[e,k] = sum_d w_out[e,d] * w1t[k,d]  (= w_out @ w1), (DD x KSLOT) row-major
    gemm3x_kernel<<<dim3(KSLOT / 128, DD / 128), 256>>>(w_out, w1t, nullptr, Wb, DD, KSLOT, DD);

    // ---- main path ----
    // 1) xn = LN(x)
    ln_kernel<<<MTOT, 256>>>(x, ln_g, ln_b, bufA);
    // 2) logits = xn @ Wa^T + ba        (32768 x 128 x 1024)
    gemm3x_kernel<<<dim3(1, MTOT / 128), 256>>>(bufA, Wa, ba, logits, MTOT, KSLOT, DD);
    // 3) softmax over N, then L1 over K
    softmax_pass1<<<dim3(BB, NCHUNK), 128>>>(logits);
    softmax_pass2<<<BB, 128>>>();
    softmax_pass3<<<MTOT, 128>>>(logits);
    // 4) h3 = a @ Wb^T                  (32768 x 1024 x 128)
    gemm3x_kernel<<<dim3(DD / 128, MTOT / 128), 256>>>(logits, Wb, nullptr, bufB, MTOT, DD, KSLOT);
    // 5) out = relu(LN(h3) + x)
    final_kernel<<<MTOT, 256>>>(bufB, x, og, ob, out);
}

// round 4
// speedup vs baseline: 4.6258x; 1.1427x over previous
#include <cuda_runtime.h>
#include <cstdint>
#include <cstddef>

#define BB 8
#define NN 4096
#define DD 1024
#define KSLOT 128
#define MTOT (BB * NN)        // 32768
#define NCHUNK 32             // NN / 128

// ---------------- scratch ----------------
__device__ float g_bufB[(size_t)MTOT * DD];     // h3 — 128 MiB
__device__ float g_logits[(size_t)MTOT * KSLOT];// 16 MiB
__device__ float g_pm[BB * NCHUNK * KSLOT];
__device__ float g_ps[BB * NCHUNK * KSLOT];
__device__ float g_M[BB * KSLOT];
__device__ float g_S[BB * KSLOT];
// fused weights
__device__ float g_winT[(size_t)DD * DD];       // w_in^T (d,e)
__device__ float g_Wa[(size_t)KSLOT * DD];      // w0 @ w_in   [k,d]
__device__ float g_Wag[(size_t)KSLOT * DD];     // Wa * g[d]   [k,d]
__device__ float g_ba[KSLOT];                   // w0 @ b_in
__device__ float g_wsum[KSLOT];                 // sum_d Wag[k,d]
__device__ float g_cb[KSLOT];                   // sum_d ln_b[d]*Wa[k,d] + ba[k]
__device__ float g_w1t[(size_t)KSLOT * DD];     // w1^T [k,d]
__device__ float g_Wb[(size_t)DD * KSLOT];      // w_out @ w1 [e,k]

#define NEG_INF __int_as_float(0xff800000)

__device__ __forceinline__ uint32_t f2tf32(float x) {
    uint32_t r;
    asm("cvt.rna.tf32.f32 %0, %1;" : "=r"(r) : "f"(x));
    return r;
}

__device__ __forceinline__ void mma_tf32(float* c,
                                         uint32_t a0, uint32_t a1, uint32_t a2, uint32_t a3,
                                         uint32_t b0, uint32_t b1) {
    asm volatile(
        "mma.sync.aligned.m16n8k8.row.col.f32.tf32.tf32.f32 "
        "{%0,%1,%2,%3}, {%4,%5,%6,%7}, {%8,%9}, {%0,%1,%2,%3};"
        : "+f"(c[0]), "+f"(c[1]), "+f"(c[2]), "+f"(c[3])
        : "r"(a0), "r"(a1), "r"(a2), "r"(a3), "r"(b0), "r"(b1));
}

__device__ __forceinline__ uint32_t smem_u32(const void* p) {
    return (uint32_t)__cvta_generic_to_shared(p);
}

#define CP_ASYNC16(dst, src) \
    asm volatile("cp.async.cg.shared.global [%0], [%1], 16;\n" ::"r"(dst), "l"(src))
#define CP_COMMIT() asm volatile("cp.async.commit_group;\n")
#define CP_WAIT(N_) asm volatile("cp.async.wait_group %0;\n" ::"n"(N_))

// ---------------- NT GEMM template: C[M,N] = A[M,K] * B[N,K]^T (+bias) ----------------
// SPLIT=3: hh + lh + hl.  SPLIT=2: hh + lh (drop a_hi*b_lo).
template <int SPLIT>
__global__ void __launch_bounds__(256, 1)
gemm3x_kernel(const float* __restrict__ A, const float* __restrict__ B,
              const float* __restrict__ bias, float* __restrict__ C,
              int M, int N, int K) {
    __shared__ float As[2][128][20];
    __shared__ float Bs[2][128][20];

    const int tid  = threadIdx.x;
    const int lane = tid & 31;
    const int warp = tid >> 5;
    const int wm   = warp & 3;
    const int wn   = warp >> 2;
    const int g    = lane >> 2;
    const int t    = lane & 3;

    const int brow = blockIdx.y * 128;
    const int bcol = blockIdx.x * 128;

    float acc[2][8][4];
#pragma unroll
    for (int i = 0; i < 2; ++i)
#pragma unroll
        for (int j = 0; j < 8; ++j)
#pragma unroll
            for (int q = 0; q < 4; ++q) acc[i][j][q] = 0.f;

    const int r0 = tid >> 2;
    const int kc = (tid & 3) * 4;
    const int ktiles = K / 16;

    auto issue = [&](int kt, int s) {
        const float* Ag = A + (size_t)(brow + r0) * K + kt * 16 + kc;
        const float* Bg = B + (size_t)(bcol + r0) * K + kt * 16 + kc;
        CP_ASYNC16(smem_u32(&As[s][r0][kc]),      Ag);
        CP_ASYNC16(smem_u32(&As[s][r0 + 64][kc]), Ag + (size_t)64 * K);
        CP_ASYNC16(smem_u32(&Bs[s][r0][kc]),      Bg);
        CP_ASYNC16(smem_u32(&Bs[s][r0 + 64][kc]), Bg + (size_t)64 * K);
    };

    issue(0, 0);
    CP_COMMIT();

    for (int kt = 0; kt < ktiles; ++kt) {
        const int cur = kt & 1;
        if (kt + 1 < ktiles) {
            issue(kt + 1, (kt + 1) & 1);
            CP_COMMIT();
            CP_WAIT(1);
        } else {
            CP_WAIT(0);
        }
        __syncthreads();

#pragma unroll
        for (int ks = 0; ks < 2; ++ks) {
            const int kb = ks * 8;

            uint32_t ah[2][4], al[2][4];
#pragma unroll
            for (int mt = 0; mt < 2; ++mt) {
                const int row = wm * 32 + mt * 16 + g;
                float v0 = As[cur][row][kb + t];
                float v1 = As[cur][row + 8][kb + t];
                float v2 = As[cur][row][kb + t + 4];
                float v3 = As[cur][row + 8][kb + t + 4];
                ah[mt][0] = f2tf32(v0); al[mt][0] = f2tf32(v0 - __uint_as_float(ah[mt][0]));
                ah[mt][1] = f2tf32(v1); al[mt][1] = f2tf32(v1 - __uint_as_float(ah[mt][1]));
                ah[mt][2] = f2tf32(v2); al[mt][2] = f2tf32(v2 - __uint_as_float(ah[mt][2]));
                ah[mt][3] = f2tf32(v3); al[mt][3] = f2tf32(v3 - __uint_as_float(ah[mt][3]));
            }

            uint32_t bh[8][2], bl[8][2];
#pragma unroll
            for (int nt = 0; nt < 8; ++nt) {
                const int col = wn * 64 + nt * 8 + g;
                float v0 = Bs[cur][col][kb + t];
                float v1 = Bs[cur][col][kb + t + 4];
                bh[nt][0] = f2tf32(v0);
                bh[nt][1] = f2tf32(v1);
                if (SPLIT == 3) {
                    bl[nt][0] = f2tf32(v0 - __uint_as_float(bh[nt][0]));
                    bl[nt][1] = f2tf32(v1 - __uint_as_float(bh[nt][1]));
                }
            }

#pragma unroll
            for (int mt = 0; mt < 2; ++mt)
#pragma unroll
                for (int nt = 0; nt < 8; ++nt) {
                    mma_tf32(acc[mt][nt], al[mt][0], al[mt][1], al[mt][2], al[mt][3],
                             bh[nt][0], bh[nt][1]);
                    if (SPLIT == 3)
                        mma_tf32(acc[mt][nt], ah[mt][0], ah[mt][1], ah[mt][2], ah[mt][3],
                                 bl[nt][0], bl[nt][1]);
                    mma_tf32(acc[mt][nt], ah[mt][0], ah[mt][1], ah[mt][2], ah[mt][3],
                             bh[nt][0], bh[nt][1]);
                }
        }
        __syncthreads();
    }

#pragma unroll
    for (int mt = 0; mt < 2; ++mt) {
        const int row = brow + wm * 32 + mt * 16 + g;
#pragma unroll
        for (int nt = 0; nt < 8; ++nt) {
            const int col = bcol + wn * 64 + nt * 8 + t * 2;
            float c0 = acc[mt][nt][0], c1 = acc[mt][nt][1];
            float c2 = acc[mt][nt][2], c3 = acc[mt][nt][3];
            if (bias) {
                float b0 = bias[col], b1 = bias[col + 1];
                c0 += b0; c1 += b1; c2 += b0; c3 += b1;
            }
            *reinterpret_cast<float2*>(C + (size_t)row * N + col) = make_float2(c0, c1);
            *reinterpret_cast<float2*>(C + (size_t)(row + 8) * N + col) = make_float2(c2, c3);
        }
    }
}

// ---------------- fused LN + logits GEMM ----------------
// L[m,k] = r_m * ( sum_d x[m,d]*Wag[k,d]  -  mean_m * wsum[k] ) + cb[k]
// grid (1, MTOT/128); N == KSLOT == 128 exactly one column tile.
__global__ void __launch_bounds__(256, 1)
gemm_ln_logits(const float* __restrict__ X, const float* __restrict__ Wag,
               const float* __restrict__ wsum, const float* __restrict__ cb,
               float* __restrict__ L) {
    __shared__ float As[2][128][20];
    __shared__ float Bs[2][128][20];
    __shared__ float sm_mean[128];
    __shared__ float sm_rstd[128];

    const int tid  = threadIdx.x;
    const int lane = tid & 31;
    const int warp = tid >> 5;
    const int wm   = warp & 3;
    const int wn   = warp >> 2;
    const int g    = lane >> 2;
    const int t    = lane & 3;

    const int brow = blockIdx.y * 128;
    const int K = DD;

    float acc[2][8][4];
#pragma unroll
    for (int i = 0; i < 2; ++i)
#pragma unroll
        for (int j = 0; j < 8; ++j)
#pragma unroll
            for (int q = 0; q < 4; ++q) acc[i][j][q] = 0.f;

    const int r0 = tid >> 2;
    const int kc = (tid & 3) * 4;
    const int ktiles = K / 16;

    float sumA = 0.f, sqA = 0.f, sumB = 0.f, sqB = 0.f;  // rows r0, r0+64

    auto issue = [&](int kt, int s) {
        const float* Ag = X + (size_t)(brow + r0) * K + kt * 16 + kc;
        const float* Bg = Wag + (size_t)r0 * K + kt * 16 + kc;   // bcol = 0
        CP_ASYNC16(smem_u32(&As[s][r0][kc]),      Ag);
        CP_ASYNC16(smem_u32(&As[s][r0 + 64][kc]), Ag + (size_t)64 * K);
        CP_ASYNC16(smem_u32(&Bs[s][r0][kc]),      Bg);
        CP_ASYNC16(smem_u32(&Bs[s][r0 + 64][kc]), Bg + (size_t)64 * K);
    };

    issue(0, 0);
    CP_COMMIT();

    for (int kt = 0; kt < ktiles; ++kt) {
        const int cur = kt & 1;
        if (kt + 1 < ktiles) {
            issue(kt + 1, (kt + 1) & 1);
            CP_COMMIT();
            CP_WAIT(1);
        } else {
            CP_WAIT(0);
        }
        __syncthreads();

        // row-stat accumulation for LN (each thread: 4 cols of rows r0, r0+64)
        {
            const float4 va = *reinterpret_cast<const float4*>(&As[cur][r0][kc]);
            const float4 vb = *reinterpret_cast<const float4*>(&As[cur][r0 + 64][kc]);
            sumA += va.x + va.y + va.z + va.w;
            sqA  += va.x * va.x + va.y * va.y + va.z * va.z + va.w * va.w;
            sumB += vb.x + vb.y + vb.z + vb.w;
            sqB  += vb.x * vb.x + vb.y * vb.y + vb.z * vb.z + vb.w * vb.w;
        }

#pragma unroll
        for (int ks = 0; ks < 2; ++ks) {
            const int kb = ks * 8;

            uint32_t ah[2][4], al[2][4];
#pragma unroll
            for (int mt = 0; mt < 2; ++mt) {
                const int row = wm * 32 + mt * 16 + g;
                float v0 = As[cur][row][kb + t];
                float v1 = As[cur][row + 8][kb + t];
                float v2 = As[cur][row][kb + t + 4];
                float v3 = As[cur][row + 8][kb + t + 4];
                ah[mt][0] = f2tf32(v0); al[mt][0] = f2tf32(v0 - __uint_as_float(ah[mt][0]));
                ah[mt][1] = f2tf32(v1); al[mt][1] = f2tf32(v1 - __uint_as_float(ah[mt][1]));
                ah[mt][2] = f2tf32(v2); al[mt][2] = f2tf32(v2 - __uint_as_float(ah[mt][2]));
                ah[mt][3] = f2tf32(v3); al[mt][3] = f2tf32(v3 - __uint_as_float(ah[mt][3]));
            }

            uint32_t bh[8][2], bl[8][2];
#pragma unroll
            for (int nt = 0; nt < 8; ++nt) {
                const int col = wn * 64 + nt * 8 + g;
                float v0 = Bs[cur][col][kb + t];
                float v1 = Bs[cur][col][kb + t + 4];
                bh[nt][0] = f2tf32(v0); bl[nt][0] = f2tf32(v0 - __uint_as_float(bh[nt][0]));
                bh[nt][1] = f2tf32(v1); bl[nt][1] = f2tf32(v1 - __uint_as_float(bh[nt][1]));
            }

#pragma unroll
            for (int mt = 0; mt < 2; ++mt)
#pragma unroll
                for (int nt = 0; nt < 8; ++nt) {
                    mma_tf32(acc[mt][nt], al[mt][0], al[mt][1], al[mt][2], al[mt][3],
                             bh[nt][0], bh[nt][1]);
                    mma_tf32(acc[mt][nt], ah[mt][0], ah[mt][1], ah[mt][2], ah[mt][3],
                             bl[nt][0], bl[nt][1]);
                    mma_tf32(acc[mt][nt], ah[mt][0], ah[mt][1], ah[mt][2], ah[mt][3],
                             bh[nt][0], bh[nt][1]);
                }
        }
        __syncthreads();
    }

    // reduce row stats across the 4 threads sharing r0 (lane bits 0..1)
#pragma unroll
    for (int o = 1; o <= 2; o <<= 1) {
        sumA += __shfl_xor_sync(0xffffffffu, sumA, o);
        sqA  += __shfl_xor_sync(0xffffffffu, sqA, o);
        sumB += __shfl_xor_sync(0xffffffffu, sumB, o);
        sqB  += __shfl_xor_sync(0xffffffffu, sqB, o);
    }
    if ((tid & 3) == 0) {
        const float mA = sumA * (1.f / DD);
        const float mB = sumB * (1.f / DD);
        sm_mean[r0]      = mA;
        sm_mean[r0 + 64] = mB;
        sm_rstd[r0]      = rsqrtf(sqA * (1.f / DD) - mA * mA + 1e-5f);
        sm_rstd[r0 + 64] = rsqrtf(sqB * (1.f / DD) - mB * mB + 1e-5f);
    }
    __syncthreads();

#pragma unroll
    for (int mt = 0; mt < 2; ++mt) {
        const int lrow0 = wm * 32 + mt * 16 + g;
        const float m0 = sm_mean[lrow0],     r0s = sm_rstd[lrow0];
        const float m1 = sm_mean[lrow0 + 8], r1s = sm_rstd[lrow0 + 8];
        const int row = brow + lrow0;
#pragma unroll
        for (int nt = 0; nt < 8; ++nt) {
            const int col = wn * 64 + nt * 8 + t * 2;
            const float ws0 = wsum[col], ws1 = wsum[col + 1];
            const float cb0 = cb[col],   cb1 = cb[col + 1];
            float c0 = r0s * (acc[mt][nt][0] - m0 * ws0) + cb0;
            float c1 = r0s * (acc[mt][nt][1] - m0 * ws1) + cb1;
            float c2 = r1s * (acc[mt][nt][2] - m1 * ws0) + cb0;
            float c3 = r1s * (acc[mt][nt][3] - m1 * ws1) + cb1;
            *reinterpret_cast<float2*>(L + (size_t)row * KSLOT + col) = make_float2(c0, c1);
            *reinterpret_cast<float2*>(L + (size_t)(row + 8) * KSLOT + col) = make_float2(c2, c3);
        }
    }
}

// ---------------- weight prep ----------------
__global__ void transpose_kernel(const float* __restrict__ src, float* __restrict__ dst,
                                 int R, int C) {
    __shared__ float tile[32][33];
    const int x = blockIdx.x * 32 + threadIdx.x;
    const int y = blockIdx.y * 32 + threadIdx.y;
    if (x < C && y < R) tile[threadIdx.y][threadIdx.x] = src[(size_t)y * C + x];
    __syncthreads();
    const int xo = blockIdx.y * 32 + threadIdx.x;
    const int yo = blockIdx.x * 32 + threadIdx.y;
    if (xo < R && yo < C) dst[(size_t)yo * R + xo] = tile[threadIdx.x][threadIdx.y];
}

__global__ void fuse_bias_kernel(const float* __restrict__ w0, const float* __restrict__ b_in,
                                 float* __restrict__ ba) {
    const int k = threadIdx.x;  // 128
    const float4* wr = reinterpret_cast<const float4*>(w0 + (size_t)k * DD);
    const float4* br = reinterpret_cast<const float4*>(b_in);
    float s = 0.f;
#pragma unroll 4
    for (int i = 0; i < DD / 4; ++i) {
        const float4 w = wr[i];
        const float4 b = br[i];
        s += w.x * b.x + w.y * b.y + w.z * b.z + w.w * b.w;
    }
    ba[k] = s;
}

// Wag[k,d] = Wa[k,d]*g[d]; wsum[k] = sum_d Wag; cb[k] = sum_d ln_b[d]*Wa[k,d] + ba[k]
// one block (256 thr) per k
__global__ void prep_wag_kernel(const float* __restrict__ Wa, const float* __restrict__ gg,
                                const float* __restrict__ bb, const float* __restrict__ ba,
                                float* __restrict__ Wag, float* __restrict__ wsum,
                                float* __restrict__ cb) {
    const int k = blockIdx.x;
    const int tid = threadIdx.x;  // 256
    const float4 w = reinterpret_cast<const float4*>(Wa + (size_t)k * DD)[tid];
    const float4 g4 = reinterpret_cast<const float4*>(gg)[tid];
    const float4 b4 = reinterpret_cast<const float4*>(bb)[tid];
    float4 wg;
    wg.x = w.x * g4.x; wg.y = w.y * g4.y; wg.z = w.z * g4.z; wg.w = w.w * g4.w;
    reinterpret_cast<float4*>(Wag + (size_t)k * DD)[tid] = wg;

    float s = wg.x + wg.y + wg.z + wg.w;
    float c = w.x * b4.x + w.y * b4.y + w.z * b4.z + w.w * b4.w;
#pragma unroll
    for (int o = 16; o > 0; o >>= 1) {
        s += __shfl_xor_sync(0xffffffffu, s, o);
        c += __shfl_xor_sync(0xffffffffu, c, o);
    }
    __shared__ float rs[8], rc[8];
    if ((tid & 31) == 0) { rs[tid >> 5] = s; rc[tid >> 5] = c; }
    __syncthreads();
    if (tid == 0) {
        float S = 0.f, C = 0.f;
#pragma unroll
        for (int i = 0; i < 8; ++i) { S += rs[i]; C += rc[i]; }
        wsum[k] = S;
        cb[k] = C + ba[k];
    }
}

// ---------------- final: out = relu(LN(h) + x_residual) ----------------
__global__ void final_kernel(const float* __restrict__ h, const float* __restrict__ xres,
                             const float* __restrict__ gg, const float* __restrict__ bb,
                             float* __restrict__ out) {
    const int row = blockIdx.x;
    const int tid = threadIdx.x;  // 256
    const float4 v = reinterpret_cast<const float4*>(h + (size_t)row * DD)[tid];

    __shared__ float red[8];
    float s = v.x + v.y + v.z + v.w;
#pragma unroll
    for (int o = 16; o > 0; o >>= 1) s += __shfl_xor_sync(0xffffffffu, s, o);
    if ((tid & 31) == 0) red[tid >> 5] = s;
    __syncthreads();
    float tot = 0.f;
#pragma unroll
    for (int i = 0; i < 8; ++i) tot += red[i];
    const float mean = tot * (1.f / DD);

    const float dx = v.x - mean, dy = v.y - mean, dz = v.z - mean, dw = v.w - mean;
    float q = dx * dx + dy * dy + dz * dz + dw * dw;
#pragma unroll
    for (int o = 16; o > 0; o >>= 1) q += __shfl_xor_sync(0xffffffffu, q, o);
    __syncthreads();
    if ((tid & 31) == 0) red[tid >> 5] = q;
    __syncthreads();
    float qtot = 0.f;
#pragma unroll
    for (int i = 0; i < 8; ++i) qtot += red[i];
    const float r = rsqrtf(qtot * (1.f / DD) + 1e-5f);

    const float4 g4 = reinterpret_cast<const float4*>(gg)[tid];
    const float4 b4 = reinterpret_cast<const float4*>(bb)[tid];
    const float4 xv = reinterpret_cast<const float4*>(xres + (size_t)row * DD)[tid];
    float4 o;
    o.x = fmaxf(dx * r * g4.x + b4.x + xv.x, 0.f);
    o.y = fmaxf(dy * r * g4.y + b4.y + xv.y, 0.f);
    o.z = fmaxf(dz * r * g4.z + b4.z + xv.z, 0.f);
    o.w = fmaxf(dw * r * g4.w + b4.w + xv.w, 0.f);
    reinterpret_cast<float4*>(out + (size_t)row * DD)[tid] = o;
}

// ---------------- softmax over positions (axis=N), 3 passes ----------------
__global__ void softmax_pass1(const float* __restrict__ logits) {
    const int b = blockIdx.x;
    const int c = blockIdx.y;
    const int k = threadIdx.x;  // 128
    const float* p = logits + ((size_t)b * NN + (size_t)c * 128) * KSLOT + k;
    float m = NEG_INF, s = 0.f;
#pragma unroll 4
    for (int r = 0; r < 128; ++r) {
        const float v = p[(size_t)r * KSLOT];
        const float mn = fmaxf(m, v);
        s = s * expf(m - mn) + expf(v - mn);
        m = mn;
    }
    g_pm[(b * NCHUNK + c) * KSLOT + k] = m;
    g_ps[(b * NCHUNK + c) * KSLOT + k] = s;
}

__global__ void softmax_pass2() {
    const int b = blockIdx.x;
    const int k = threadIdx.x;  // 128
    float M = NEG_INF;
#pragma unroll
    for (int c = 0; c < NCHUNK; ++c) M = fmaxf(M, g_pm[(b * NCHUNK + c) * KSLOT + k]);
    float S = 0.f;
#pragma unroll
    for (int c = 0; c < NCHUNK; ++c)
        S += g_ps[(b * NCHUNK + c) * KSLOT + k] * expf(g_pm[(b * NCHUNK + c) * KSLOT + k] - M);
    g_M[b * KSLOT + k] = M;
    g_S[b * KSLOT + k] = S;
}

__global__ void softmax_pass3(float* __restrict__ logits) {
    const int idx = blockIdx.x;
    const int b = idx >> 12;
    const int k = threadIdx.x;  // 128
    const size_t off = (size_t)idx * KSLOT + k;
    const float p = expf(logits[off] - g_M[b * KSLOT + k]) / g_S[b * KSLOT + k];

    float s = p;
#pragma unroll
    for (int o = 16; o > 0; o >>= 1) s += __shfl_xor_sync(0xffffffffu, s, o);
    __shared__ float red[4];
    if ((k & 31) == 0) red[k >> 5] = s;
    __syncthreads();
    const float tot = red[0] + red[1] + red[2] + red[3];
    logits[off] = p / (1e-9f + tot);
}

// ---------------- launch ----------------
extern "C" void kernel_launch(void* const* d_in, const int* in_sizes, int n_in,
                              void* d_out, int out_size) {
    const float* x     = (const float*)d_in[0];
    const float* ln_g  = (const float*)d_in[1];
    const float* ln_b  = (const float*)d_in[2];
    const float* w_in  = (const float*)d_in[3];
    const float* b_in  = (const float*)d_in[4];
    const float* w0    = (const float*)d_in[5];
    const float* w1    = (const float*)d_in[6];
    const float* w_out = (const float*)d_in[7];
    const float* og    = (const float*)d_in[8];
    const float* ob    = (const float*)d_in[9];
    float* out = (float*)d_out;

    static float* bufB = nullptr; static float* logits = nullptr;
    static float* winT = nullptr; static float* Wa = nullptr; static float* Wag = nullptr;
    static float* ba = nullptr; static float* wsum = nullptr; static float* cb = nullptr;
    static float* w1t = nullptr; static float* Wb = nullptr;
    if (!bufB) {
        cudaGetSymbolAddress((void**)&bufB, g_bufB);
        cudaGetSymbolAddress((void**)&logits, g_logits);
        cudaGetSymbolAddress((void**)&winT, g_winT);
        cudaGetSymbolAddress((void**)&Wa, g_Wa);
        cudaGetSymbolAddress((void**)&Wag, g_Wag);
        cudaGetSymbolAddress((void**)&ba, g_ba);
        cudaGetSymbolAddress((void**)&wsum, g_wsum);
        cudaGetSymbolAddress((void**)&cb, g_cb);
        cudaGetSymbolAddress((void**)&w1t, g_w1t);
        cudaGetSymbolAddress((void**)&Wb, g_Wb);
    }

    // ---- weight fusion ----
    transpose_kernel<<<dim3(DD / 32, DD / 32), dim3(32, 32)>>>(w_in, winT, DD, DD);
    gemm3x_kernel<3><<<dim3(DD / 128, 1), 256>>>(w0, winT, nullptr, Wa, KSLOT, DD, DD);
    fuse_bias_kernel<<<1, 128>>>(w0, b_in, ba);
    prep_wag_kernel<<<KSLOT, 256>>>(Wa, ln_g, ln_b, ba, Wag, wsum, cb);
    transpose_kernel<<<dim3(KSLOT / 32, DD / 32), dim3(32, 32)>>>(w1, w1t, DD, KSLOT);
    gemm3x_kernel<3><<<dim3(KSLOT / 128, DD / 128), 256>>>(w_out, w1t, nullptr, Wb, DD, KSLOT, DD);

    // ---- main path ----
    // 1) logits = LN(x) @ Wa^T + ba, fused (32768 x 128 x 1024)
    gemm_ln_logits<<<dim3(1, MTOT / 128), 256>>>(x, Wag, wsum, cb, logits);
    // 2) softmax over N, then L1 over K
    softmax_pass1<<<dim3(BB, NCHUNK), 128>>>(logits);
    softmax_pass2<<<BB, 128>>>();
    softmax_pass3<<<MTOT, 128>>>(logits);
    // 3) h3 = a @ Wb^T (32768 x 1024 x 128), 2x split
    gemm3x_kernel<2><<<dim3(DD / 128, MTOT / 128), 256>>>(logits, Wb, nullptr, bufB, MTOT, DD, KSLOT);
    // 4) out = relu(LN(h3) + x)
    final_kernel<<<MTOT, 256>>>(bufB, x, og, ob, out);
}

// round 5
// speedup vs baseline: 6.1392x; 1.3272x over previous
#include <cuda_runtime.h>
#include <cstdint>
#include <cstddef>

#define BB 8
#define NN 4096
#define DD 1024
#define KSLOT 128
#define MTOT (BB * NN)        // 32768
#define NCHUNK 32             // NN / 128
#define NSPLIT 8              // split-K for weight prep

// ---------------- scratch ----------------
__device__ float g_bufB[(size_t)MTOT * DD];     // h3 — 128 MiB
__device__ float g_logits[(size_t)MTOT * KSLOT];// 16 MiB
__device__ float g_pm[BB * NCHUNK * KSLOT];
__device__ float g_ps[BB * NCHUNK * KSLOT];
__device__ float g_M[BB * KSLOT];
__device__ float g_S[BB * KSLOT];
// weight-prep partials + fused weights
__device__ float g_Pa[(size_t)NSPLIT * KSLOT * DD];  // Wa split-K partials
__device__ float g_Pb[(size_t)NSPLIT * DD * KSLOT];  // Wb split-K partials
__device__ float g_Wag[(size_t)KSLOT * DD];     // (w0@w_in) * g[d]   [k,d]
__device__ float g_ba[KSLOT];                   // w0 @ b_in
__device__ float g_wsum[KSLOT];                 // sum_d Wag[k,d]
__device__ float g_cb[KSLOT];                   // sum_d ln_b[d]*Wa[k,d] + ba[k]
__device__ float g_Wb[(size_t)DD * KSLOT];      // w_out @ w1 [e,k]

#define NEG_INF __int_as_float(0xff800000)

__device__ __forceinline__ uint32_t f2tf32(float x) {
    uint32_t r;
    asm("cvt.rna.tf32.f32 %0, %1;" : "=r"(r) : "f"(x));
    return r;
}

__device__ __forceinline__ void mma_tf32(float* c,
                                         uint32_t a0, uint32_t a1, uint32_t a2, uint32_t a3,
                                         uint32_t b0, uint32_t b1) {
    asm volatile(
        "mma.sync.aligned.m16n8k8.row.col.f32.tf32.tf32.f32 "
        "{%0,%1,%2,%3}, {%4,%5,%6,%7}, {%8,%9}, {%0,%1,%2,%3};"
        : "+f"(c[0]), "+f"(c[1]), "+f"(c[2]), "+f"(c[3])
        : "r"(a0), "r"(a1), "r"(a2), "r"(a3), "r"(b0), "r"(b1));
}

__device__ __forceinline__ uint32_t smem_u32(const void* p) {
    return (uint32_t)__cvta_generic_to_shared(p);
}

#define CP_ASYNC16(dst, src) \
    asm volatile("cp.async.cg.shared.global [%0], [%1], 16;\n" ::"r"(dst), "l"(src))
#define CP_COMMIT() asm volatile("cp.async.commit_group;\n")
#define CP_WAIT(N_) asm volatile("cp.async.wait_group %0;\n" ::"n"(N_))

// ---------------- split-K SIMT fp32 NN GEMM (weight prep only) ----------------
// P[s][M,N] partial = A[M, k0:k1] @ B[k0:k1, N]; A,B row-major.
// BM=BN=64, BK=16, 256 threads, 4x4 outputs/thread, grid (N/64, M/64, NSPLIT)
__global__ void __launch_bounds__(256, 1)
prep_gemm_splitk(const float* __restrict__ A, const float* __restrict__ B,
                 float* __restrict__ P, int M, int N, int K) {
    __shared__ float As[64][17];
    __shared__ float Bs[16][64];

    const int tid = threadIdx.x;
    const int tx = tid & 15;
    const int ty = tid >> 4;
    const int bm = blockIdx.y * 64;
    const int bn = blockIdx.x * 64;
    const int kchunk = K / NSPLIT;
    const int k0 = blockIdx.z * kchunk;

    float c[4][4];
#pragma unroll
    for (int q = 0; q < 4; ++q)
#pragma unroll
        for (int r = 0; r < 4; ++r) c[q][r] = 0.f;

    const int amm = tid >> 2;          // 0..63
    const int akk = (tid & 3) * 4;     // 0,4,8,12
    const int bc  = tid & 63;          // 0..63
    const int br0 = tid >> 6;          // 0..3

    for (int kt = 0; kt < kchunk; kt += 16) {
        const float4 va = *reinterpret_cast<const float4*>(
            A + (size_t)(bm + amm) * K + k0 + kt + akk);
        As[amm][akk + 0] = va.x;
        As[amm][akk + 1] = va.y;
        As[amm][akk + 2] = va.z;
        As[amm][akk + 3] = va.w;
#pragma unroll
        for (int j = 0; j < 4; ++j) {
            const int r = br0 + j * 4;
            Bs[r][bc] = B[(size_t)(k0 + kt + r) * N + bn + bc];
        }
        __syncthreads();

#pragma unroll
        for (int kk = 0; kk < 16; ++kk) {
            const float a0 = As[ty * 4 + 0][kk];
            const float a1 = As[ty * 4 + 1][kk];
            const float a2 = As[ty * 4 + 2][kk];
            const float a3 = As[ty * 4 + 3][kk];
            const float4 b = *reinterpret_cast<const float4*>(&Bs[kk][tx * 4]);
            c[0][0] += a0 * b.x; c[0][1] += a0 * b.y; c[0][2] += a0 * b.z; c[0][3] += a0 * b.w;
            c[1][0] += a1 * b.x; c[1][1] += a1 * b.y; c[1][2] += a1 * b.z; c[1][3] += a1 * b.w;
            c[2][0] += a2 * b.x; c[2][1] += a2 * b.y; c[2][2] += a2 * b.z; c[2][3] += a2 * b.w;
            c[3][0] += a3 * b.x; c[3][1] += a3 * b.y; c[3][2] += a3 * b.z; c[3][3] += a3 * b.w;
        }
        __syncthreads();
    }

    float* Pb = P + (size_t)blockIdx.z * M * N;
#pragma unroll
    for (int q = 0; q < 4; ++q) {
        const int row = bm + ty * 4 + q;
        *reinterpret_cast<float4*>(Pb + (size_t)row * N + bn + tx * 4) =
            make_float4(c[q][0], c[q][1], c[q][2], c[q][3]);
    }
}

// reduce NSPLIT partials -> C (for Wb)
__global__ void reduce_partials(const float* __restrict__ P, float* __restrict__ C, int total) {
    const int i = blockIdx.x * 256 + threadIdx.x;
    if (i >= total) return;
    float s = 0.f;
#pragma unroll
    for (int ss = 0; ss < NSPLIT; ++ss) s += P[(size_t)ss * total + i];
    C[i] = s;
}

// ---------------- NT GEMM template: C[M,N] = A[M,K] * B[N,K]^T ----------------
// SPLIT=2: hh + lh (drop a_hi*b_lo).
template <int SPLIT>
__global__ void __launch_bounds__(256, 1)
gemm3x_kernel(const float* __restrict__ A, const float* __restrict__ B,
              const float* __restrict__ bias, float* __restrict__ C,
              int M, int N, int K) {
    __shared__ float As[2][128][20];
    __shared__ float Bs[2][128][20];

    const int tid  = threadIdx.x;
    const int lane = tid & 31;
    const int warp = tid >> 5;
    const int wm   = warp & 3;
    const int wn   = warp >> 2;
    const int g    = lane >> 2;
    const int t    = lane & 3;

    const int brow = blockIdx.y * 128;
    const int bcol = blockIdx.x * 128;

    float acc[2][8][4];
#pragma unroll
    for (int i = 0; i < 2; ++i)
#pragma unroll
        for (int j = 0; j < 8; ++j)
#pragma unroll
            for (int q = 0; q < 4; ++q) acc[i][j][q] = 0.f;

    const int r0 = tid >> 2;
    const int kc = (tid & 3) * 4;
    const int ktiles = K / 16;

    auto issue = [&](int kt, int s) {
        const float* Ag = A + (size_t)(brow + r0) * K + kt * 16 + kc;
        const float* Bg = B + (size_t)(bcol + r0) * K + kt * 16 + kc;
        CP_ASYNC16(smem_u32(&As[s][r0][kc]),      Ag);
        CP_ASYNC16(smem_u32(&As[s][r0 + 64][kc]), Ag + (size_t)64 * K);
        CP_ASYNC16(smem_u32(&Bs[s][r0][kc]),      Bg);
        CP_ASYNC16(smem_u32(&Bs[s][r0 + 64][kc]), Bg + (size_t)64 * K);
    };

    issue(0, 0);
    CP_COMMIT();

    for (int kt = 0; kt < ktiles; ++kt) {
        const int cur = kt & 1;
        if (kt + 1 < ktiles) {
            issue(kt + 1, (kt + 1) & 1);
            CP_COMMIT();
            CP_WAIT(1);
        } else {
            CP_WAIT(0);
        }
        __syncthreads();

#pragma unroll
        for (int ks = 0; ks < 2; ++ks) {
            const int kb = ks * 8;

            uint32_t ah[2][4], al[2][4];
#pragma unroll
            for (int mt = 0; mt < 2; ++mt) {
                const int row = wm * 32 + mt * 16 + g;
                float v0 = As[cur][row][kb + t];
                float v1 = As[cur][row + 8][kb + t];
                float v2 = As[cur][row][kb + t + 4];
                float v3 = As[cur][row + 8][kb + t + 4];
                ah[mt][0] = f2tf32(v0); al[mt][0] = f2tf32(v0 - __uint_as_float(ah[mt][0]));
                ah[mt][1] = f2tf32(v1); al[mt][1] = f2tf32(v1 - __uint_as_float(ah[mt][1]));
                ah[mt][2] = f2tf32(v2); al[mt][2] = f2tf32(v2 - __uint_as_float(ah[mt][2]));
                ah[mt][3] = f2tf32(v3); al[mt][3] = f2tf32(v3 - __uint_as_float(ah[mt][3]));
            }

            uint32_t bh[8][2], bl[8][2];
#pragma unroll
            for (int nt = 0; nt < 8; ++nt) {
                const int col = wn * 64 + nt * 8 + g;
                float v0 = Bs[cur][col][kb + t];
                float v1 = Bs[cur][col][kb + t + 4];
                bh[nt][0] = f2tf32(v0);
                bh[nt][1] = f2tf32(v1);
                if (SPLIT == 3) {
                    bl[nt][0] = f2tf32(v0 - __uint_as_float(bh[nt][0]));
                    bl[nt][1] = f2tf32(v1 - __uint_as_float(bh[nt][1]));
                }
            }

#pragma unroll
            for (int mt = 0; mt < 2; ++mt)
#pragma unroll
                for (int nt = 0; nt < 8; ++nt) {
                    mma_tf32(acc[mt][nt], al[mt][0], al[mt][1], al[mt][2], al[mt][3],
                             bh[nt][0], bh[nt][1]);
                    if (SPLIT == 3)
                        mma_tf32(acc[mt][nt], ah[mt][0], ah[mt][1], ah[mt][2], ah[mt][3],
                                 bl[nt][0], bl[nt][1]);
                    mma_tf32(acc[mt][nt], ah[mt][0], ah[mt][1], ah[mt][2], ah[mt][3],
                             bh[nt][0], bh[nt][1]);
                }
        }
        __syncthreads();
    }

#pragma unroll
    for (int mt = 0; mt < 2; ++mt) {
        const int row = brow + wm * 32 + mt * 16 + g;
#pragma unroll
        for (int nt = 0; nt < 8; ++nt) {
            const int col = bcol + wn * 64 + nt * 8 + t * 2;
            float c0 = acc[mt][nt][0], c1 = acc[mt][nt][1];
            float c2 = acc[mt][nt][2], c3 = acc[mt][nt][3];
            if (bias) {
                float b0 = bias[col], b1 = bias[col + 1];
                c0 += b0; c1 += b1; c2 += b0; c3 += b1;
            }
            *reinterpret_cast<float2*>(C + (size_t)row * N + col) = make_float2(c0, c1);
            *reinterpret_cast<float2*>(C + (size_t)(row + 8) * N + col) = make_float2(c2, c3);
        }
    }
}

// ---------------- fused LN + logits GEMM (3x split) ----------------
__global__ void __launch_bounds__(256, 1)
gemm_ln_logits(const float* __restrict__ X, const float* __restrict__ Wag,
               const float* __restrict__ wsum, const float* __restrict__ cb,
               float* __restrict__ L) {
    __shared__ float As[2][128][20];
    __shared__ float Bs[2][128][20];
    __shared__ float sm_mean[128];
    __shared__ float sm_rstd[128];

    const int tid  = threadIdx.x;
    const int lane = tid & 31;
    const int warp = tid >> 5;
    const int wm   = warp & 3;
    const int wn   = warp >> 2;
    const int g    = lane >> 2;
    const int t    = lane & 3;

    const int brow = blockIdx.y * 128;
    const int K = DD;

    float acc[2][8][4];
#pragma unroll
    for (int i = 0; i < 2; ++i)
#pragma unroll
        for (int j = 0; j < 8; ++j)
#pragma unroll
            for (int q = 0; q < 4; ++q) acc[i][j][q] = 0.f;

    const int r0 = tid >> 2;
    const int kc = (tid & 3) * 4;
    const int ktiles = K / 16;

    float sumA = 0.f, sqA = 0.f, sumB = 0.f, sqB = 0.f;

    auto issue = [&](int kt, int s) {
        const float* Ag = X + (size_t)(brow + r0) * K + kt * 16 + kc;
        const float* Bg = Wag + (size_t)r0 * K + kt * 16 + kc;
        CP_ASYNC16(smem_u32(&As[s][r0][kc]),      Ag);
        CP_ASYNC16(smem_u32(&As[s][r0 + 64][kc]), Ag + (size_t)64 * K);
        CP_ASYNC16(smem_u32(&Bs[s][r0][kc]),      Bg);
        CP_ASYNC16(smem_u32(&Bs[s][r0 + 64][kc]), Bg + (size_t)64 * K);
    };

    issue(0, 0);
    CP_COMMIT();

    for (int kt = 0; kt < ktiles; ++kt) {
        const int cur = kt & 1;
        if (kt + 1 < ktiles) {
            issue(kt + 1, (kt + 1) & 1);
            CP_COMMIT();
            CP_WAIT(1);
        } else {
            CP_WAIT(0);
        }
        __syncthreads();

        {
            const float4 va = *reinterpret_cast<const float4*>(&As[cur][r0][kc]);
            const float4 vb = *reinterpret_cast<const float4*>(&As[cur][r0 + 64][kc]);
            sumA += va.x + va.y + va.z + va.w;
            sqA  += va.x * va.x + va.y * va.y + va.z * va.z + va.w * va.w;
            sumB += vb.x + vb.y + vb.z + vb.w;
            sqB  += vb.x * vb.x + vb.y * vb.y + vb.z * vb.z + vb.w * vb.w;
        }

#pragma unroll
        for (int ks = 0; ks < 2; ++ks) {
            const int kb = ks * 8;

            uint32_t ah[2][4], al[2][4];
#pragma unroll
            for (int mt = 0; mt < 2; ++mt) {
                const int row = wm * 32 + mt * 16 + g;
                float v0 = As[cur][row][kb + t];
                float v1 = As[cur][row + 8][kb + t];
                float v2 = As[cur][row][kb + t + 4];
                float v3 = As[cur][row + 8][kb + t + 4];
                ah[mt][0] = f2tf32(v0); al[mt][0] = f2tf32(v0 - __uint_as_float(ah[mt][0]));
                ah[mt][1] = f2tf32(v1); al[mt][1] = f2tf32(v1 - __uint_as_float(ah[mt][1]));
                ah[mt][2] = f2tf32(v2); al[mt][2] = f2tf32(v2 - __uint_as_float(ah[mt][2]));
                ah[mt][3] = f2tf32(v3); al[mt][3] = f2tf32(v3 - __uint_as_float(ah[mt][3]));
            }

            uint32_t bh[8][2], bl[8][2];
#pragma unroll
            for (int nt = 0; nt < 8; ++nt) {
                const int col = wn * 64 + nt * 8 + g;
                float v0 = Bs[cur][col][kb + t];
                float v1 = Bs[cur][col][kb + t + 4];
                bh[nt][0] = f2tf32(v0); bl[nt][0] = f2tf32(v0 - __uint_as_float(bh[nt][0]));
                bh[nt][1] = f2tf32(v1); bl[nt][1] = f2tf32(v1 - __uint_as_float(bh[nt][1]));
            }

#pragma unroll
            for (int mt = 0; mt < 2; ++mt)
#pragma unroll
                for (int nt = 0; nt < 8; ++nt) {
                    mma_tf32(acc[mt][nt], al[mt][0], al[mt][1], al[mt][2], al[mt][3],
                             bh[nt][0], bh[nt][1]);
                    mma_tf32(acc[mt][nt], ah[mt][0], ah[mt][1], ah[mt][2], ah[mt][3],
                             bl[nt][0], bl[nt][1]);
                    mma_tf32(acc[mt][nt], ah[mt][0], ah[mt][1], ah[mt][2], ah[mt][3],
                             bh[nt][0], bh[nt][1]);
                }
        }
        __syncthreads();
    }

#pragma unroll
    for (int o = 1; o <= 2; o <<= 1) {
        sumA += __shfl_xor_sync(0xffffffffu, sumA, o);
        sqA  += __shfl_xor_sync(0xffffffffu, sqA, o);
        sumB += __shfl_xor_sync(0xffffffffu, sumB, o);
        sqB  += __shfl_xor_sync(0xffffffffu, sqB, o);
    }
    if ((tid & 3) == 0) {
        const float mA = sumA * (1.f / DD);
        const float mB = sumB * (1.f / DD);
        sm_mean[r0]      = mA;
        sm_mean[r0 + 64] = mB;
        sm_rstd[r0]      = rsqrtf(sqA * (1.f / DD) - mA * mA + 1e-5f);
        sm_rstd[r0 + 64] = rsqrtf(sqB * (1.f / DD) - mB * mB + 1e-5f);
    }
    __syncthreads();

#pragma unroll
    for (int mt = 0; mt < 2; ++mt) {
        const int lrow0 = wm * 32 + mt * 16 + g;
        const float m0 = sm_mean[lrow0],     r0s = sm_rstd[lrow0];
        const float m1 = sm_mean[lrow0 + 8], r1s = sm_rstd[lrow0 + 8];
        const int row = brow + lrow0;
#pragma unroll
        for (int nt = 0; nt < 8; ++nt) {
            const int col = wn * 64 + nt * 8 + t * 2;
            const float ws0 = wsum[col], ws1 = wsum[col + 1];
            const float cb0 = cb[col],   cb1 = cb[col + 1];
            float c0 = r0s * (acc[mt][nt][0] - m0 * ws0) + cb0;
            float c1 = r0s * (acc[mt][nt][1] - m0 * ws1) + cb1;
            float c2 = r1s * (acc[mt][nt][2] - m1 * ws0) + cb0;
            float c3 = r1s * (acc[mt][nt][3] - m1 * ws1) + cb1;
            *reinterpret_cast<float2*>(L + (size_t)row * KSLOT + col) = make_float2(c0, c1);
            *reinterpret_cast<float2*>(L + (size_t)(row + 8) * KSLOT + col) = make_float2(c2, c3);
        }
    }
}

// ---------------- small prep ----------------
__global__ void fuse_bias_kernel(const float* __restrict__ w0, const float* __restrict__ b_in,
                                 float* __restrict__ ba) {
    const int k = threadIdx.x;  // 128
    const float4* wr = reinterpret_cast<const float4*>(w0 + (size_t)k * DD);
    const float4* br = reinterpret_cast<const float4*>(b_in);
    float s = 0.f;
#pragma unroll 4
    for (int i = 0; i < DD / 4; ++i) {
        const float4 w = wr[i];
        const float4 b = br[i];
        s += w.x * b.x + w.y * b.y + w.z * b.z + w.w * b.w;
    }
    ba[k] = s;
}

// reduce Wa partials + build Wag/wsum/cb. one block per k.
__global__ void prep_wag_kernel(const float* __restrict__ Pa, const float* __restrict__ gg,
                                const float* __restrict__ bb, const float* __restrict__ ba,
                                float* __restrict__ Wag, float* __restrict__ wsum,
                                float* __restrict__ cb) {
    const int k = blockIdx.x;
    const int tid = threadIdx.x;  // 256
    float4 w = make_float4(0.f, 0.f, 0.f, 0.f);
#pragma unroll
    for (int ss = 0; ss < NSPLIT; ++ss) {
        const float4 p = reinterpret_cast<const float4*>(
            Pa + (size_t)ss * KSLOT * DD + (size_t)k * DD)[tid];
        w.x += p.x; w.y += p.y; w.z += p.z; w.w += p.w;
    }
    const float4 g4 = reinterpret_cast<const float4*>(gg)[tid];
    const float4 b4 = reinterpret_cast<const float4*>(bb)[tid];
    float4 wg;
    wg.x = w.x * g4.x; wg.y = w.y * g4.y; wg.z = w.z * g4.z; wg.w = w.w * g4.w;
    reinterpret_cast<float4*>(Wag + (size_t)k * DD)[tid] = wg;

    float s = wg.x + wg.y + wg.z + wg.w;
    float c = w.x * b4.x + w.y * b4.y + w.z * b4.z + w.w * b4.w;
#pragma unroll
    for (int o = 16; o > 0; o >>= 1) {
        s += __shfl_xor_sync(0xffffffffu, s, o);
        c += __shfl_xor_sync(0xffffffffu, c, o);
    }
    __shared__ float rs[8], rc[8];
    if ((tid & 31) == 0) { rs[tid >> 5] = s; rc[tid >> 5] = c; }
    __syncthreads();
    if (tid == 0) {
        float S = 0.f, C = 0.f;
#pragma unroll
        for (int i = 0; i < 8; ++i) { S += rs[i]; C += rc[i]; }
        wsum[k] = S;
        cb[k] = C + ba[k];
    }
}

// ---------------- final: out = relu(LN(h) + x_residual) ----------------
__global__ void final_kernel(const float* __restrict__ h, const float* __restrict__ xres,
                             const float* __restrict__ gg, const float* __restrict__ bb,
                             float* __restrict__ out) {
    const int row = blockIdx.x;
    const int tid = threadIdx.x;  // 256
    const float4 v = reinterpret_cast<const float4*>(h + (size_t)row * DD)[tid];

    __shared__ float red[8];
    float s = v.x + v.y + v.z + v.w;
#pragma unroll
    for (int o = 16; o > 0; o >>= 1) s += __shfl_xor_sync(0xffffffffu, s, o);
    if ((tid & 31) == 0) red[tid >> 5] = s;
    __syncthreads();
    float tot = 0.f;
#pragma unroll
    for (int i = 0; i < 8; ++i) tot += red[i];
    const float mean = tot * (1.f / DD);

    const float dx = v.x - mean, dy = v.y - mean, dz = v.z - mean, dw = v.w - mean;
    float q = dx * dx + dy * dy + dz * dz + dw * dw;
#pragma unroll
    for (int o = 16; o > 0; o >>= 1) q += __shfl_xor_sync(0xffffffffu, q, o);
    __syncthreads();
    if ((tid & 31) == 0) red[tid >> 5] = q;
    __syncthreads();
    float qtot = 0.f;
#pragma unroll
    for (int i = 0; i < 8; ++i) qtot += red[i];
    const float r = rsqrtf(qtot * (1.f / DD) + 1e-5f);

    const float4 g4 = reinterpret_cast<const float4*>(gg)[tid];
    const float4 b4 = reinterpret_cast<const float4*>(bb)[tid];
    const float4 xv = reinterpret_cast<const float4*>(xres + (size_t)row * DD)[tid];
    float4 o;
    o.x = fmaxf(dx * r * g4.x + b4.x + xv.x, 0.f);
    o.y = fmaxf(dy * r * g4.y + b4.y + xv.y, 0.f);
    o.z = fmaxf(dz * r * g4.z + b4.z + xv.z, 0.f);
    o.w = fmaxf(dw * r * g4.w + b4.w + xv.w, 0.f);
    reinterpret_cast<float4*>(out + (size_t)row * DD)[tid] = o;
}

// ---------------- softmax over positions (axis=N), 3 passes ----------------
__global__ void softmax_pass1(const float* __restrict__ logits) {
    const int b = blockIdx.x;
    const int c = blockIdx.y;
    const int k = threadIdx.x;  // 128
    const float* p = logits + ((size_t)b * NN + (size_t)c * 128) * KSLOT + k;
    float m = NEG_INF, s = 0.f;
#pragma unroll 4
    for (int r = 0; r < 128; ++r) {
        const float v = p[(size_t)r * KSLOT];
        const float mn = fmaxf(m, v);
        s = s * expf(m - mn) + expf(v - mn);
        m = mn;
    }
    g_pm[(b * NCHUNK + c) * KSLOT + k] = m;
    g_ps[(b * NCHUNK + c) * KSLOT + k] = s;
}

__global__ void softmax_pass2() {
    const int b = blockIdx.x;
    const int k = threadIdx.x;  // 128
    float M = NEG_INF;
#pragma unroll
    for (int c = 0; c < NCHUNK; ++c) M = fmaxf(M, g_pm[(b * NCHUNK + c) * KSLOT + k]);
    float S = 0.f;
#pragma unroll
    for (int c = 0; c < NCHUNK; ++c)
        S += g_ps[(b * NCHUNK + c) * KSLOT + k] * expf(g_pm[(b * NCHUNK + c) * KSLOT + k] - M);
    g_M[b * KSLOT + k] = M;
    g_S[b * KSLOT + k] = S;
}

__global__ void softmax_pass3(float* __restrict__ logits) {
    const int idx = blockIdx.x;
    const int b = idx >> 12;
    const int k = threadIdx.x;  // 128
    const size_t off = (size_t)idx * KSLOT + k;
    const float p = expf(logits[off] - g_M[b * KSLOT + k]) / g_S[b * KSLOT + k];

    float s = p;
#pragma unroll
    for (int o = 16; o > 0; o >>= 1) s += __shfl_xor_sync(0xffffffffu, s, o);
    __shared__ float red[4];
    if ((k & 31) == 0) red[k >> 5] = s;
    __syncthreads();
    const float tot = red[0] + red[1] + red[2] + red[3];
    logits[off] = p / (1e-9f + tot);
}

// ---------------- launch ----------------
extern "C" void kernel_launch(void* const* d_in, const int* in_sizes, int n_in,
                              void* d_out, int out_size) {
    const float* x     = (const float*)d_in[0];
    const float* ln_g  = (const float*)d_in[1];
    const float* ln_b  = (const float*)d_in[2];
    const float* w_in  = (const float*)d_in[3];
    const float* b_in  = (const float*)d_in[4];
    const float* w0    = (const float*)d_in[5];
    const float* w1    = (const float*)d_in[6];
    const float* w_out = (const float*)d_in[7];
    const float* og    = (const float*)d_in[8];
    const float* ob    = (const float*)d_in[9];
    float* out = (float*)d_out;

    static float* bufB = nullptr; static float* logits = nullptr;
    static float* Pa = nullptr; static float* Pb = nullptr;
    static float* Wag = nullptr; static float* ba = nullptr;
    static float* wsum = nullptr; static float* cb = nullptr; static float* Wb = nullptr;
    if (!bufB) {
        cudaGetSymbolAddress((void**)&bufB, g_bufB);
        cudaGetSymbolAddress((void**)&logits, g_logits);
        cudaGetSymbolAddress((void**)&Pa, g_Pa);
        cudaGetSymbolAddress((void**)&Pb, g_Pb);
        cudaGetSymbolAddress((void**)&Wag, g_Wag);
        cudaGetSymbolAddress((void**)&ba, g_ba);
        cudaGetSymbolAddress((void**)&wsum, g_wsum);
        cudaGetSymbolAddress((void**)&cb, g_cb);
        cudaGetSymbolAddress((void**)&Wb, g_Wb);
    }

    // ---- weight fusion (full-chip split-K fp32 SIMT) ----
    // Wa partials: Wa[k,d] = sum_e w0[k,e] * w_in[e,d]   (NN GEMM, M=128, N=1024, K=1024)
    prep_gemm_splitk<<<dim3(DD / 64, KSLOT / 64, NSPLIT), 256>>>(w0, w_in, Pa, KSLOT, DD, DD);
    // Wb partials: Wb[e,k] = sum_d w_out[e,d] * w1[d,k]  (NN GEMM, M=1024, N=128, K=1024)
    prep_gemm_splitk<<<dim3(KSLOT / 64, DD / 64, NSPLIT), 256>>>(w_out, w1, Pb, DD, KSLOT, DD);
    reduce_partials<<<(DD * KSLOT + 255) / 256, 256>>>(Pb, Wb, DD * KSLOT);
    fuse_bias_kernel<<<1, 128>>>(w0, b_in, ba);
    prep_wag_kernel<<<KSLOT, 256>>>(Pa, ln_g, ln_b, ba, Wag, wsum, cb);

    // ---- main path ----
    // 1) logits = LN(x) @ Wa^T + ba, fused (32768 x 128 x 1024), 3x split
    gemm_ln_logits<<<dim3(1, MTOT / 128), 256>>>(x, Wag, wsum, cb, logits);
    // 2) softmax over N, then L1 over K
    softmax_pass1<<<dim3(BB, NCHUNK), 128>>>(logits);
    softmax_pass2<<<BB, 128>>>();
    softmax_pass3<<<MTOT, 128>>>(logits);
    // 3) h3 = a @ Wb^T (32768 x 1024 x 128), 2x split
    gemm3x_kernel<2><<<dim3(DD / 128, MTOT / 128), 256>>>(logits, Wb, nullptr, bufB, MTOT, DD, KSLOT);
    // 4) out = relu(LN(h3) + x)
    final_kernel<<<MTOT, 256>>>(bufB, x, og, ob, out);
}

// round 6
// speedup vs baseline: 7.0673x; 1.1512x over previous
#include <cuda_runtime.h>
#include <cstdint>
#include <cstddef>

#define BB 8
#define NN 4096
#define DD 1024
#define KSLOT 128
#define MTOT (BB * NN)        // 32768
#define NCHUNK 32             // NN / 128
#define NSPLIT 8              // split-K for weight prep

// ---------------- scratch ----------------
__device__ float g_bufB[(size_t)MTOT * DD];     // h3 — 128 MiB
__device__ float g_logits[(size_t)MTOT * KSLOT];// 16 MiB
__device__ float g_pm[BB * NCHUNK * KSLOT];
__device__ float g_ps[BB * NCHUNK * KSLOT];
__device__ float g_M[BB * KSLOT];
__device__ float g_S[BB * KSLOT];
// weight-prep partials + fused weights
__device__ float g_Pa[(size_t)NSPLIT * KSLOT * DD];
__device__ float g_Pb[(size_t)NSPLIT * DD * KSLOT];
__device__ float g_Wag[(size_t)KSLOT * DD];
__device__ float g_ba[KSLOT];
__device__ float g_wsum[KSLOT];
__device__ float g_cb[KSLOT];
__device__ float g_Wb[(size_t)DD * KSLOT];

#define NEG_INF __int_as_float(0xff800000)

__device__ __forceinline__ uint32_t f2tf32(float x) {
    uint32_t r;
    asm("cvt.rna.tf32.f32 %0, %1;" : "=r"(r) : "f"(x));
    return r;
}

__device__ __forceinline__ void mma_tf32(float* c,
                                         uint32_t a0, uint32_t a1, uint32_t a2, uint32_t a3,
                                         uint32_t b0, uint32_t b1) {
    asm volatile(
        "mma.sync.aligned.m16n8k8.row.col.f32.tf32.tf32.f32 "
        "{%0,%1,%2,%3}, {%4,%5,%6,%7}, {%8,%9}, {%0,%1,%2,%3};"
        : "+f"(c[0]), "+f"(c[1]), "+f"(c[2]), "+f"(c[3])
        : "r"(a0), "r"(a1), "r"(a2), "r"(a3), "r"(b0), "r"(b1));
}

__device__ __forceinline__ uint32_t smem_u32(const void* p) {
    return (uint32_t)__cvta_generic_to_shared(p);
}

#define CP_ASYNC16(dst, src) \
    asm volatile("cp.async.cg.shared.global [%0], [%1], 16;\n" ::"r"(dst), "l"(src))
#define CP_COMMIT() asm volatile("cp.async.commit_group;\n")
#define CP_WAIT(N_) asm volatile("cp.async.wait_group %0;\n" ::"n"(N_))

// ---------------- split-K SIMT fp32 NN GEMM (weight prep only) ----------------
__global__ void __launch_bounds__(256, 1)
prep_gemm_splitk(const float* __restrict__ A, const float* __restrict__ B,
                 float* __restrict__ P, int M, int N, int K) {
    __shared__ float As[64][17];
    __shared__ float Bs[16][64];

    const int tid = threadIdx.x;
    const int tx = tid & 15;
    const int ty = tid >> 4;
    const int bm = blockIdx.y * 64;
    const int bn = blockIdx.x * 64;
    const int kchunk = K / NSPLIT;
    const int k0 = blockIdx.z * kchunk;

    float c[4][4];
#pragma unroll
    for (int q = 0; q < 4; ++q)
#pragma unroll
        for (int r = 0; r < 4; ++r) c[q][r] = 0.f;

    const int amm = tid >> 2;
    const int akk = (tid & 3) * 4;
    const int bc  = tid & 63;
    const int br0 = tid >> 6;

    for (int kt = 0; kt < kchunk; kt += 16) {
        const float4 va = *reinterpret_cast<const float4*>(
            A + (size_t)(bm + amm) * K + k0 + kt + akk);
        As[amm][akk + 0] = va.x;
        As[amm][akk + 1] = va.y;
        As[amm][akk + 2] = va.z;
        As[amm][akk + 3] = va.w;
#pragma unroll
        for (int j = 0; j < 4; ++j) {
            const int r = br0 + j * 4;
            Bs[r][bc] = B[(size_t)(k0 + kt + r) * N + bn + bc];
        }
        __syncthreads();

#pragma unroll
        for (int kk = 0; kk < 16; ++kk) {
            const float a0 = As[ty * 4 + 0][kk];
            const float a1 = As[ty * 4 + 1][kk];
            const float a2 = As[ty * 4 + 2][kk];
            const float a3 = As[ty * 4 + 3][kk];
            const float4 b = *reinterpret_cast<const float4*>(&Bs[kk][tx * 4]);
            c[0][0] += a0 * b.x; c[0][1] += a0 * b.y; c[0][2] += a0 * b.z; c[0][3] += a0 * b.w;
            c[1][0] += a1 * b.x; c[1][1] += a1 * b.y; c[1][2] += a1 * b.z; c[1][3] += a1 * b.w;
            c[2][0] += a2 * b.x; c[2][1] += a2 * b.y; c[2][2] += a2 * b.z; c[2][3] += a2 * b.w;
            c[3][0] += a3 * b.x; c[3][1] += a3 * b.y; c[3][2] += a3 * b.z; c[3][3] += a3 * b.w;
        }
        __syncthreads();
    }

    float* Pb = P + (size_t)blockIdx.z * M * N;
#pragma unroll
    for (int q = 0; q < 4; ++q) {
        const int row = bm + ty * 4 + q;
        *reinterpret_cast<float4*>(Pb + (size_t)row * N + bn + tx * 4) =
            make_float4(c[q][0], c[q][1], c[q][2], c[q][3]);
    }
}

__global__ void reduce_partials(const float* __restrict__ P, float* __restrict__ C, int total) {
    const int i = blockIdx.x * 256 + threadIdx.x;
    if (i >= total) return;
    float s = 0.f;
#pragma unroll
    for (int ss = 0; ss < NSPLIT; ++ss) s += P[(size_t)ss * total + i];
    C[i] = s;
}

// ---------------- NT GEMM template: C[M,N] = A[M,K] * B[N,K]^T ----------------
template <int SPLIT>
__global__ void __launch_bounds__(256, 1)
gemm3x_kernel(const float* __restrict__ A, const float* __restrict__ B,
              const float* __restrict__ bias, float* __restrict__ C,
              int M, int N, int K) {
    __shared__ float As[2][128][20];
    __shared__ float Bs[2][128][20];

    const int tid  = threadIdx.x;
    const int lane = tid & 31;
    const int warp = tid >> 5;
    const int wm   = warp & 3;
    const int wn   = warp >> 2;
    const int g    = lane >> 2;
    const int t    = lane & 3;

    const int brow = blockIdx.y * 128;
    const int bcol = blockIdx.x * 128;

    float acc[2][8][4];
#pragma unroll
    for (int i = 0; i < 2; ++i)
#pragma unroll
        for (int j = 0; j < 8; ++j)
#pragma unroll
            for (int q = 0; q < 4; ++q) acc[i][j][q] = 0.f;

    const int r0 = tid >> 2;
    const int kc = (tid & 3) * 4;
    const int ktiles = K / 16;

    auto issue = [&](int kt, int s) {
        const float* Ag = A + (size_t)(brow + r0) * K + kt * 16 + kc;
        const float* Bg = B + (size_t)(bcol + r0) * K + kt * 16 + kc;
        CP_ASYNC16(smem_u32(&As[s][r0][kc]),      Ag);
        CP_ASYNC16(smem_u32(&As[s][r0 + 64][kc]), Ag + (size_t)64 * K);
        CP_ASYNC16(smem_u32(&Bs[s][r0][kc]),      Bg);
        CP_ASYNC16(smem_u32(&Bs[s][r0 + 64][kc]), Bg + (size_t)64 * K);
    };

    issue(0, 0);
    CP_COMMIT();

    for (int kt = 0; kt < ktiles; ++kt) {
        const int cur = kt & 1;
        if (kt + 1 < ktiles) {
            issue(kt + 1, (kt + 1) & 1);
            CP_COMMIT();
            CP_WAIT(1);
        } else {
            CP_WAIT(0);
        }
        __syncthreads();

#pragma unroll
        for (int ks = 0; ks < 2; ++ks) {
            const int kb = ks * 8;

            uint32_t ah[2][4], al[2][4];
#pragma unroll
            for (int mt = 0; mt < 2; ++mt) {
                const int row = wm * 32 + mt * 16 + g;
                float v0 = As[cur][row][kb + t];
                float v1 = As[cur][row + 8][kb + t];
                float v2 = As[cur][row][kb + t + 4];
                float v3 = As[cur][row + 8][kb + t + 4];
                ah[mt][0] = f2tf32(v0); al[mt][0] = f2tf32(v0 - __uint_as_float(ah[mt][0]));
                ah[mt][1] = f2tf32(v1); al[mt][1] = f2tf32(v1 - __uint_as_float(ah[mt][1]));
                ah[mt][2] = f2tf32(v2); al[mt][2] = f2tf32(v2 - __uint_as_float(ah[mt][2]));
                ah[mt][3] = f2tf32(v3); al[mt][3] = f2tf32(v3 - __uint_as_float(ah[mt][3]));
            }

            uint32_t bh[8][2], bl[8][2];
#pragma unroll
            for (int nt = 0; nt < 8; ++nt) {
                const int col = wn * 64 + nt * 8 + g;
                float v0 = Bs[cur][col][kb + t];
                float v1 = Bs[cur][col][kb + t + 4];
                bh[nt][0] = f2tf32(v0);
                bh[nt][1] = f2tf32(v1);
                if (SPLIT == 3) {
                    bl[nt][0] = f2tf32(v0 - __uint_as_float(bh[nt][0]));
                    bl[nt][1] = f2tf32(v1 - __uint_as_float(bh[nt][1]));
                }
            }

#pragma unroll
            for (int mt = 0; mt < 2; ++mt)
#pragma unroll
                for (int nt = 0; nt < 8; ++nt) {
                    mma_tf32(acc[mt][nt], al[mt][0], al[mt][1], al[mt][2], al[mt][3],
                             bh[nt][0], bh[nt][1]);
                    if (SPLIT == 3)
                        mma_tf32(acc[mt][nt], ah[mt][0], ah[mt][1], ah[mt][2], ah[mt][3],
                                 bl[nt][0], bl[nt][1]);
                    mma_tf32(acc[mt][nt], ah[mt][0], ah[mt][1], ah[mt][2], ah[mt][3],
                             bh[nt][0], bh[nt][1]);
                }
        }
        __syncthreads();
    }

#pragma unroll
    for (int mt = 0; mt < 2; ++mt) {
        const int row = brow + wm * 32 + mt * 16 + g;
#pragma unroll
        for (int nt = 0; nt < 8; ++nt) {
            const int col = bcol + wn * 64 + nt * 8 + t * 2;
            float c0 = acc[mt][nt][0], c1 = acc[mt][nt][1];
            float c2 = acc[mt][nt][2], c3 = acc[mt][nt][3];
            if (bias) {
                float b0 = bias[col], b1 = bias[col + 1];
                c0 += b0; c1 += b1; c2 += b0; c3 += b1;
            }
            *reinterpret_cast<float2*>(C + (size_t)row * N + col) = make_float2(c0, c1);
            *reinterpret_cast<float2*>(C + (size_t)(row + 8) * N + col) = make_float2(c2, c3);
        }
    }
}

// ---------------- fused LN + logits GEMM (2x split: al*bh + ah*bh) ----------------
__global__ void __launch_bounds__(256, 1)
gemm_ln_logits(const float* __restrict__ X, const float* __restrict__ Wag,
               const float* __restrict__ wsum, const float* __restrict__ cb,
               float* __restrict__ L) {
    __shared__ float As[2][128][20];
    __shared__ float Bs[2][128][20];
    __shared__ float sm_mean[128];
    __shared__ float sm_rstd[128];

    const int tid  = threadIdx.x;
    const int lane = tid & 31;
    const int warp = tid >> 5;
    const int wm   = warp & 3;
    const int wn   = warp >> 2;
    const int g    = lane >> 2;
    const int t    = lane & 3;

    const int brow = blockIdx.y * 128;
    const int K = DD;

    float acc[2][8][4];
#pragma unroll
    for (int i = 0; i < 2; ++i)
#pragma unroll
        for (int j = 0; j < 8; ++j)
#pragma unroll
            for (int q = 0; q < 4; ++q) acc[i][j][q] = 0.f;

    const int r0 = tid >> 2;
    const int kc = (tid & 3) * 4;
    const int ktiles = K / 16;

    float sumA = 0.f, sqA = 0.f, sumB = 0.f, sqB = 0.f;

    auto issue = [&](int kt, int s) {
        const float* Ag = X + (size_t)(brow + r0) * K + kt * 16 + kc;
        const float* Bg = Wag + (size_t)r0 * K + kt * 16 + kc;
        CP_ASYNC16(smem_u32(&As[s][r0][kc]),      Ag);
        CP_ASYNC16(smem_u32(&As[s][r0 + 64][kc]), Ag + (size_t)64 * K);
        CP_ASYNC16(smem_u32(&Bs[s][r0][kc]),      Bg);
        CP_ASYNC16(smem_u32(&Bs[s][r0 + 64][kc]), Bg + (size_t)64 * K);
    };

    issue(0, 0);
    CP_COMMIT();

    for (int kt = 0; kt < ktiles; ++kt) {
        const int cur = kt & 1;
        if (kt + 1 < ktiles) {
            issue(kt + 1, (kt + 1) & 1);
            CP_COMMIT();
            CP_WAIT(1);
        } else {
            CP_WAIT(0);
        }
        __syncthreads();

        {
            const float4 va = *reinterpret_cast<const float4*>(&As[cur][r0][kc]);
            const float4 vb = *reinterpret_cast<const float4*>(&As[cur][r0 + 64][kc]);
            sumA += va.x + va.y + va.z + va.w;
            sqA  += va.x * va.x + va.y * va.y + va.z * va.z + va.w * va.w;
            sumB += vb.x + vb.y + vb.z + vb.w;
            sqB  += vb.x * vb.x + vb.y * vb.y + vb.z * vb.z + vb.w * vb.w;
        }

#pragma unroll
        for (int ks = 0; ks < 2; ++ks) {
            const int kb = ks * 8;

            uint32_t ah[2][4], al[2][4];
#pragma unroll
            for (int mt = 0; mt < 2; ++mt) {
                const int row = wm * 32 + mt * 16 + g;
                float v0 = As[cur][row][kb + t];
                float v1 = As[cur][row + 8][kb + t];
                float v2 = As[cur][row][kb + t + 4];
                float v3 = As[cur][row + 8][kb + t + 4];
                ah[mt][0] = f2tf32(v0); al[mt][0] = f2tf32(v0 - __uint_as_float(ah[mt][0]));
                ah[mt][1] = f2tf32(v1); al[mt][1] = f2tf32(v1 - __uint_as_float(ah[mt][1]));
                ah[mt][2] = f2tf32(v2); al[mt][2] = f2tf32(v2 - __uint_as_float(ah[mt][2]));
                ah[mt][3] = f2tf32(v3); al[mt][3] = f2tf32(v3 - __uint_as_float(ah[mt][3]));
            }

            uint32_t bh[8][2];
#pragma unroll
            for (int nt = 0; nt < 8; ++nt) {
                const int col = wn * 64 + nt * 8 + g;
                bh[nt][0] = f2tf32(Bs[cur][col][kb + t]);
                bh[nt][1] = f2tf32(Bs[cur][col][kb + t + 4]);
            }

#pragma unroll
            for (int mt = 0; mt < 2; ++mt)
#pragma unroll
                for (int nt = 0; nt < 8; ++nt) {
                    mma_tf32(acc[mt][nt], al[mt][0], al[mt][1], al[mt][2], al[mt][3],
                             bh[nt][0], bh[nt][1]);
                    mma_tf32(acc[mt][nt], ah[mt][0], ah[mt][1], ah[mt][2], ah[mt][3],
                             bh[nt][0], bh[nt][1]);
                }
        }
        __syncthreads();
    }

#pragma unroll
    for (int o = 1; o <= 2; o <<= 1) {
        sumA += __shfl_xor_sync(0xffffffffu, sumA, o);
        sqA  += __shfl_xor_sync(0xffffffffu, sqA, o);
        sumB += __shfl_xor_sync(0xffffffffu, sumB, o);
        sqB  += __shfl_xor_sync(0xffffffffu, sqB, o);
    }
    if ((tid & 3) == 0) {
        const float mA = sumA * (1.f / DD);
        const float mB = sumB * (1.f / DD);
        sm_mean[r0]      = mA;
        sm_mean[r0 + 64] = mB;
        sm_rstd[r0]      = rsqrtf(sqA * (1.f / DD) - mA * mA + 1e-5f);
        sm_rstd[r0 + 64] = rsqrtf(sqB * (1.f / DD) - mB * mB + 1e-5f);
    }
    __syncthreads();

#pragma unroll
    for (int mt = 0; mt < 2; ++mt) {
        const int lrow0 = wm * 32 + mt * 16 + g;
        const float m0 = sm_mean[lrow0],     r0s = sm_rstd[lrow0];
        const float m1 = sm_mean[lrow0 + 8], r1s = sm_rstd[lrow0 + 8];
        const int row = brow + lrow0;
#pragma unroll
        for (int nt = 0; nt < 8; ++nt) {
            const int col = wn * 64 + nt * 8 + t * 2;
            const float ws0 = wsum[col], ws1 = wsum[col + 1];
            const float cb0 = cb[col],   cb1 = cb[col + 1];
            float c0 = r0s * (acc[mt][nt][0] - m0 * ws0) + cb0;
            float c1 = r0s * (acc[mt][nt][1] - m0 * ws1) + cb1;
            float c2 = r1s * (acc[mt][nt][2] - m1 * ws0) + cb0;
            float c3 = r1s * (acc[mt][nt][3] - m1 * ws1) + cb1;
            *reinterpret_cast<float2*>(L + (size_t)row * KSLOT + col) = make_float2(c0, c1);
            *reinterpret_cast<float2*>(L + (size_t)(row + 8) * KSLOT + col) = make_float2(c2, c3);
        }
    }
}

// ---------------- small prep ----------------
// ba[k] = sum_e w0[k,e]*b_in[e]; one block (256 thr) per k
__global__ void fuse_bias_kernel(const float* __restrict__ w0, const float* __restrict__ b_in,
                                 float* __restrict__ ba) {
    const int k = blockIdx.x;
    const int tid = threadIdx.x;  // 256
    const float4 w = reinterpret_cast<const float4*>(w0 + (size_t)k * DD)[tid];
    const float4 b = reinterpret_cast<const float4*>(b_in)[tid];
    float s = w.x * b.x + w.y * b.y + w.z * b.z + w.w * b.w;
#pragma unroll
    for (int o = 16; o > 0; o >>= 1) s += __shfl_xor_sync(0xffffffffu, s, o);
    __shared__ float red[8];
    if ((tid & 31) == 0) red[tid >> 5] = s;
    __syncthreads();
    if (tid == 0) {
        float S = 0.f;
#pragma unroll
        for (int i = 0; i < 8; ++i) S += red[i];
        ba[k] = S;
    }
}

// reduce Wa partials + build Wag/wsum/cb. one block per k.
__global__ void prep_wag_kernel(const float* __restrict__ Pa, const float* __restrict__ gg,
                                const float* __restrict__ bb, const float* __restrict__ ba,
                                float* __restrict__ Wag, float* __restrict__ wsum,
                                float* __restrict__ cb) {
    const int k = blockIdx.x;
    const int tid = threadIdx.x;  // 256
    float4 w = make_float4(0.f, 0.f, 0.f, 0.f);
#pragma unroll
    for (int ss = 0; ss < NSPLIT; ++ss) {
        const float4 p = reinterpret_cast<const float4*>(
            Pa + (size_t)ss * KSLOT * DD + (size_t)k * DD)[tid];
        w.x += p.x; w.y += p.y; w.z += p.z; w.w += p.w;
    }
    const float4 g4 = reinterpret_cast<const float4*>(gg)[tid];
    const float4 b4 = reinterpret_cast<const float4*>(bb)[tid];
    float4 wg;
    wg.x = w.x * g4.x; wg.y = w.y * g4.y; wg.z = w.z * g4.z; wg.w = w.w * g4.w;
    reinterpret_cast<float4*>(Wag + (size_t)k * DD)[tid] = wg;

    float s = wg.x + wg.y + wg.z + wg.w;
    float c = w.x * b4.x + w.y * b4.y + w.z * b4.z + w.w * b4.w;
#pragma unroll
    for (int o = 16; o > 0; o >>= 1) {
        s += __shfl_xor_sync(0xffffffffu, s, o);
        c += __shfl_xor_sync(0xffffffffu, c, o);
    }
    __shared__ float rs[8], rc[8];
    if ((tid & 31) == 0) { rs[tid >> 5] = s; rc[tid >> 5] = c; }
    __syncthreads();
    if (tid == 0) {
        float S = 0.f, C = 0.f;
#pragma unroll
        for (int i = 0; i < 8; ++i) { S += rs[i]; C += rc[i]; }
        wsum[k] = S;
        cb[k] = C + ba[k];
    }
}

// ---------------- final: out = relu(LN(h) + x_residual) ----------------
__global__ void final_kernel(const float* __restrict__ h, const float* __restrict__ xres,
                             const float* __restrict__ gg, const float* __restrict__ bb,
                             float* __restrict__ out) {
    const int row = blockIdx.x;
    const int tid = threadIdx.x;  // 256
    const float4 v = reinterpret_cast<const float4*>(h + (size_t)row * DD)[tid];

    __shared__ float red[8];
    float s = v.x + v.y + v.z + v.w;
#pragma unroll
    for (int o = 16; o > 0; o >>= 1) s += __shfl_xor_sync(0xffffffffu, s, o);
    if ((tid & 31) == 0) red[tid >> 5] = s;
    __syncthreads();
    float tot = 0.f;
#pragma unroll
    for (int i = 0; i < 8; ++i) tot += red[i];
    const float mean = tot * (1.f / DD);

    const float dx = v.x - mean, dy = v.y - mean, dz = v.z - mean, dw = v.w - mean;
    float q = dx * dx + dy * dy + dz * dz + dw * dw;
#pragma unroll
    for (int o = 16; o > 0; o >>= 1) q += __shfl_xor_sync(0xffffffffu, q, o);
    __syncthreads();
    if ((tid & 31) == 0) red[tid >> 5] = q;
    __syncthreads();
    float qtot = 0.f;
#pragma unroll
    for (int i = 0; i < 8; ++i) qtot += red[i];
    const float r = rsqrtf(qtot * (1.f / DD) + 1e-5f);

    const float4 g4 = reinterpret_cast<const float4*>(gg)[tid];
    const float4 b4 = reinterpret_cast<const float4*>(bb)[tid];
    const float4 xv = reinterpret_cast<const float4*>(xres + (size_t)row * DD)[tid];
    float4 o;
    o.x = fmaxf(dx * r * g4.x + b4.x + xv.x, 0.f);
    o.y = fmaxf(dy * r * g4.y + b4.y + xv.y, 0.f);
    o.z = fmaxf(dz * r * g4.z + b4.z + xv.z, 0.f);
    o.w = fmaxf(dw * r * g4.w + b4.w + xv.w, 0.f);
    reinterpret_cast<float4*>(out + (size_t)row * DD)[tid] = o;
}

// ---------------- softmax over positions (axis=N), 3 passes ----------------
// pass1: 1-exp-per-element online update
__global__ void softmax_pass1(const float* __restrict__ logits) {
    const int b = blockIdx.x;
    const int c = blockIdx.y;
    const int k = threadIdx.x;  // 128
    const float* p = logits + ((size_t)b * NN + (size_t)c * 128) * KSLOT + k;
    float m = p[0], s = 1.f;
#pragma unroll 4
    for (int r = 1; r < 128; ++r) {
        const float v = p[(size_t)r * KSLOT];
        if (v <= m) {
            s += __expf(v - m);
        } else {
            s = s * __expf(m - v) + 1.f;
            m = v;
        }
    }
    g_pm[(b * NCHUNK + c) * KSLOT + k] = m;
    g_ps[(b * NCHUNK + c) * KSLOT + k] = s;
}

__global__ void softmax_pass2() {
    const int b = blockIdx.x;
    const int k = threadIdx.x;  // 128
    float M = NEG_INF;
#pragma unroll
    for (int c = 0; c < NCHUNK; ++c) M = fmaxf(M, g_pm[(b * NCHUNK + c) * KSLOT + k]);
    float S = 0.f;
#pragma unroll
    for (int c = 0; c < NCHUNK; ++c)
        S += g_ps[(b * NCHUNK + c) * KSLOT + k] * expf(g_pm[(b * NCHUNK + c) * KSLOT + k] - M);
    g_M[b * KSLOT + k] = M;
    g_S[b * KSLOT + k] = S;
}

__global__ void softmax_pass3(float* __restrict__ logits) {
    const int idx = blockIdx.x;
    const int b = idx >> 12;
    const int k = threadIdx.x;  // 128
    const size_t off = (size_t)idx * KSLOT + k;
    const float p = expf(logits[off] - g_M[b * KSLOT + k]) / g_S[b * KSLOT + k];

    float s = p;
#pragma unroll
    for (int o = 16; o > 0; o >>= 1) s += __shfl_xor_sync(0xffffffffu, s, o);
    __shared__ float red[4];
    if ((k & 31) == 0) red[k >> 5] = s;
    __syncthreads();
    const float tot = red[0] + red[1] + red[2] + red[3];
    logits[off] = p / (1e-9f + tot);
}

// ---------------- launch ----------------
extern "C" void kernel_launch(void* const* d_in, const int* in_sizes, int n_in,
                              void* d_out, int out_size) {
    const float* x     = (const float*)d_in[0];
    const float* ln_g  = (const float*)d_in[1];
    const float* ln_b  = (const float*)d_in[2];
    const float* w_in  = (const float*)d_in[3];
    const float* b_in  = (const float*)d_in[4];
    const float* w0    = (const float*)d_in[5];
    const float* w1    = (const float*)d_in[6];
    const float* w_out = (const float*)d_in[7];
    const float* og    = (const float*)d_in[8];
    const float* ob    = (const float*)d_in[9];
    float* out = (float*)d_out;

    static float* bufB = nullptr; static float* logits = nullptr;
    static float* Pa = nullptr; static float* Pb = nullptr;
    static float* Wag = nullptr; static float* ba = nullptr;
    static float* wsum = nullptr; static float* cb = nullptr; static float* Wb = nullptr;
    if (!bufB) {
        cudaGetSymbolAddress((void**)&bufB, g_bufB);
        cudaGetSymbolAddress((void**)&logits, g_logits);
        cudaGetSymbolAddress((void**)&Pa, g_Pa);
        cudaGetSymbolAddress((void**)&Pb, g_Pb);
        cudaGetSymbolAddress((void**)&Wag, g_Wag);
        cudaGetSymbolAddress((void**)&ba, g_ba);
        cudaGetSymbolAddress((void**)&wsum, g_wsum);
        cudaGetSymbolAddress((void**)&cb, g_cb);
        cudaGetSymbolAddress((void**)&Wb, g_Wb);
    }

    // ---- weight fusion (full-chip split-K fp32 SIMT) ----
    prep_gemm_splitk<<<dim3(DD / 64, KSLOT / 64, NSPLIT), 256>>>(w0, w_in, Pa, KSLOT, DD, DD);
    prep_gemm_splitk<<<dim3(KSLOT / 64, DD / 64, NSPLIT), 256>>>(w_out, w1, Pb, DD, KSLOT, DD);
    reduce_partials<<<(DD * KSLOT + 255) / 256, 256>>>(Pb, Wb, DD * KSLOT);
    fuse_bias_kernel<<<KSLOT, 256>>>(w0, b_in, ba);
    prep_wag_kernel<<<KSLOT, 256>>>(Pa, ln_g, ln_b, ba, Wag, wsum, cb);

    // ---- main path ----
    gemm_ln_logits<<<dim3(1, MTOT / 128), 256>>>(x, Wag, wsum, cb, logits);
    softmax_pass1<<<dim3(BB, NCHUNK), 128>>>(logits);
    softmax_pass2<<<BB, 128>>>();
    softmax_pass3<<<MTOT, 128>>>(logits);
    gemm3x_kernel<2><<<dim3(DD / 128, MTOT / 128), 256>>>(logits, Wb, nullptr, bufB, MTOT, DD, KSLOT);
    final_kernel<<<MTOT, 256>>>(bufB, x, og, ob, out);
}

// round 8
// speedup vs baseline: 8.9426x; 1.2654x over previous
#include <cuda_runtime.h>
#include <cuda_fp16.h>
#include <cstdint>
#include <cstddef>

#define BB 8
#define NN 4096
#define DD 1024
#define KSLOT 128
#define MTOT (BB * NN)        // 32768
#define NCHUNK 32             // NN / 128
#define NSPLIT 8              // split-K for weight prep

// ---------------- scratch ----------------
__device__ float g_bufB[(size_t)MTOT * DD];     // h3 — 128 MiB
__device__ float g_logits[(size_t)MTOT * KSLOT];// 16 MiB
__device__ float g_pm[BB * NCHUNK * KSLOT];
__device__ float g_ps[BB * NCHUNK * KSLOT];
__device__ float g_M[BB * KSLOT];
__device__ float g_S[BB * KSLOT];
__device__ float g_Pa[(size_t)NSPLIT * KSLOT * DD];
__device__ float g_Pb[(size_t)NSPLIT * DD * KSLOT];
__device__ float g_Wag[(size_t)KSLOT * DD];
__device__ float g_ba[KSLOT];
__device__ float g_wsum[KSLOT];
__device__ float g_cb[KSLOT];
__device__ float g_Wb[(size_t)DD * KSLOT];

#define NEG_INF __int_as_float(0xff800000)

// ---------------- fp16 split helpers ----------------
__device__ __forceinline__ uint32_t pack_f16(float2 v) {
    __half2 h = __floats2half2_rn(v.x, v.y);
    return *reinterpret_cast<uint32_t*>(&h);
}

__device__ __forceinline__ void split_f16(float2 v, uint32_t& hi, uint32_t& lo) {
    __half2 h = __floats2half2_rn(v.x, v.y);
    hi = *reinterpret_cast<uint32_t*>(&h);
    const float2 hf = __half22float2(h);
    __half2 l = __floats2half2_rn(v.x - hf.x, v.y - hf.y);
    lo = *reinterpret_cast<uint32_t*>(&l);
}

// m16n8k16 fp16 MMA, fp32 accumulate
__device__ __forceinline__ void mma_f16(float* c,
                                        uint32_t a0, uint32_t a1, uint32_t a2, uint32_t a3,
                                        uint32_t b0, uint32_t b1) {
    asm volatile(
        "mma.sync.aligned.m16n8k16.row.col.f32.f16.f16.f32 "
        "{%0,%1,%2,%3}, {%4,%5,%6,%7}, {%8,%9}, {%0,%1,%2,%3};"
        : "+f"(c[0]), "+f"(c[1]), "+f"(c[2]), "+f"(c[3])
        : "r"(a0), "r"(a1), "r"(a2), "r"(a3), "r"(b0), "r"(b1));
}

__device__ __forceinline__ uint32_t smem_u32(const void* p) {
    uint32_t addr;
    asm("{ .reg .u64 tmp; cvta.to.shared.u64 tmp, %1; cvt.u32.u64 %0, tmp; }"
        : "=r"(addr) : "l"(p));
    return addr;
}

#define CP_ASYNC16(dst, src) \
    asm volatile("cp.async.cg.shared.global [%0], [%1], 16;\n" ::"r"(dst), "l"(src))
#define CP_COMMIT() asm volatile("cp.async.commit_group;\n")
#define CP_WAIT(N_) asm volatile("cp.async.wait_group %0;\n" ::"n"(N_))

// ---------------- split-K SIMT fp32 NN GEMM (weight prep only) ----------------
__global__ void __launch_bounds__(256, 1)
prep_gemm_splitk(const float* __restrict__ A, const float* __restrict__ B,
                 float* __restrict__ P, int M, int N, int K) {
    __shared__ float As[64][17];
    __shared__ float Bs[16][64];

    const int tid = threadIdx.x;
    const int tx = tid & 15;
    const int ty = tid >> 4;
    const int bm = blockIdx.y * 64;
    const int bn = blockIdx.x * 64;
    const int kchunk = K / NSPLIT;
    const int k0 = blockIdx.z * kchunk;

    float c[4][4];
#pragma unroll
    for (int q = 0; q < 4; ++q)
#pragma unroll
        for (int r = 0; r < 4; ++r) c[q][r] = 0.f;

    const int amm = tid >> 2;
    const int akk = (tid & 3) * 4;
    const int bc  = tid & 63;
    const int br0 = tid >> 6;

    for (int kt = 0; kt < kchunk; kt += 16) {
        const float4 va = *reinterpret_cast<const float4*>(
            A + (size_t)(bm + amm) * K + k0 + kt + akk);
        As[amm][akk + 0] = va.x;
        As[amm][akk + 1] = va.y;
        As[amm][akk + 2] = va.z;
        As[amm][akk + 3] = va.w;
#pragma unroll
        for (int j = 0; j < 4; ++j) {
            const int r = br0 + j * 4;
            Bs[r][bc] = B[(size_t)(k0 + kt + r) * N + bn + bc];
        }
        __syncthreads();

#pragma unroll
        for (int kk = 0; kk < 16; ++kk) {
            const float a0 = As[ty * 4 + 0][kk];
            const float a1 = As[ty * 4 + 1][kk];
            const float a2 = As[ty * 4 + 2][kk];
            const float a3 = As[ty * 4 + 3][kk];
            const float4 b = *reinterpret_cast<const float4*>(&Bs[kk][tx * 4]);
            c[0][0] += a0 * b.x; c[0][1] += a0 * b.y; c[0][2] += a0 * b.z; c[0][3] += a0 * b.w;
            c[1][0] += a1 * b.x; c[1][1] += a1 * b.y; c[1][2] += a1 * b.z; c[1][3] += a1 * b.w;
            c[2][0] += a2 * b.x; c[2][1] += a2 * b.y; c[2][2] += a2 * b.z; c[2][3] += a2 * b.w;
            c[3][0] += a3 * b.x; c[3][1] += a3 * b.y; c[3][2] += a3 * b.z; c[3][3] += a3 * b.w;
        }
        __syncthreads();
    }

    float* Pb = P + (size_t)blockIdx.z * M * N;
#pragma unroll
    for (int q = 0; q < 4; ++q) {
        const int row = bm + ty * 4 + q;
        *reinterpret_cast<float4*>(Pb + (size_t)row * N + bn + tx * 4) =
            make_float4(c[q][0], c[q][1], c[q][2], c[q][3]);
    }
}

__global__ void reduce_partials(const float* __restrict__ P, float* __restrict__ C, int total) {
    const int i = blockIdx.x * 256 + threadIdx.x;
    if (i >= total) return;
    float s = 0.f;
#pragma unroll
    for (int ss = 0; ss < NSPLIT; ++ss) s += P[(size_t)ss * total + i];
    C[i] = s;
}

// ---------------- fp16 2-term NT GEMM: C[M,N] = A[M,K] * B[N,K]^T ----------------
// BM=128 BN=128 BK=16, 256 threads, warps 4(m) x 2(n), warp tile 32x64
__global__ void __launch_bounds__(256, 1)
gemm_f16_kernel(const float* __restrict__ A, const float* __restrict__ B,
                float* __restrict__ C, int M, int N, int K) {
    __shared__ float As[2][128][20];
    __shared__ float Bs[2][128][20];

    const int tid  = threadIdx.x;
    const int lane = tid & 31;
    const int warp = tid >> 5;
    const int wm   = warp & 3;
    const int wn   = warp >> 2;
    const int g    = lane >> 2;
    const int t    = lane & 3;

    const int brow = blockIdx.y * 128;
    const int bcol = blockIdx.x * 128;

    float acc[2][8][4];
#pragma unroll
    for (int i = 0; i < 2; ++i)
#pragma unroll
        for (int j = 0; j < 8; ++j)
#pragma unroll
            for (int q = 0; q < 4; ++q) acc[i][j][q] = 0.f;

    const int r0 = tid >> 2;
    const int kc = (tid & 3) * 4;
    const int ktiles = K / 16;

    auto issue = [&](int kt, int s) {
        const float* Ag = A + (size_t)(brow + r0) * K + kt * 16 + kc;
        const float* Bg = B + (size_t)(bcol + r0) * K + kt * 16 + kc;
        CP_ASYNC16(smem_u32(&As[s][r0][kc]),      Ag);
        CP_ASYNC16(smem_u32(&As[s][r0 + 64][kc]), Ag + (size_t)64 * K);
        CP_ASYNC16(smem_u32(&Bs[s][r0][kc]),      Bg);
        CP_ASYNC16(smem_u32(&Bs[s][r0 + 64][kc]), Bg + (size_t)64 * K);
    };

    issue(0, 0);
    CP_COMMIT();

    for (int kt = 0; kt < ktiles; ++kt) {
        const int cur = kt & 1;
        if (kt + 1 < ktiles) {
            issue(kt + 1, (kt + 1) & 1);
            CP_COMMIT();
            CP_WAIT(1);
        } else {
            CP_WAIT(0);
        }
        __syncthreads();

        uint32_t ah[2][4], al[2][4];
#pragma unroll
        for (int mt = 0; mt < 2; ++mt) {
            const int row = wm * 32 + mt * 16 + g;
            const float2 v0 = *reinterpret_cast<const float2*>(&As[cur][row][2 * t]);
            const float2 v1 = *reinterpret_cast<const float2*>(&As[cur][row + 8][2 * t]);
            const float2 v2 = *reinterpret_cast<const float2*>(&As[cur][row][2 * t + 8]);
            const float2 v3 = *reinterpret_cast<const float2*>(&As[cur][row + 8][2 * t + 8]);
            split_f16(v0, ah[mt][0], al[mt][0]);
            split_f16(v1, ah[mt][1], al[mt][1]);
            split_f16(v2, ah[mt][2], al[mt][2]);
            split_f16(v3, ah[mt][3], al[mt][3]);
        }

        uint32_t bh[8][2];
#pragma unroll
        for (int nt = 0; nt < 8; ++nt) {
            const int col = wn * 64 + nt * 8 + g;
            bh[nt][0] = pack_f16(*reinterpret_cast<const float2*>(&Bs[cur][col][2 * t]));
            bh[nt][1] = pack_f16(*reinterpret_cast<const float2*>(&Bs[cur][col][2 * t + 8]));
        }

#pragma unroll
        for (int mt = 0; mt < 2; ++mt)
#pragma unroll
            for (int nt = 0; nt < 8; ++nt) {
                mma_f16(acc[mt][nt], al[mt][0], al[mt][1], al[mt][2], al[mt][3],
                        bh[nt][0], bh[nt][1]);
                mma_f16(acc[mt][nt], ah[mt][0], ah[mt][1], ah[mt][2], ah[mt][3],
                        bh[nt][0], bh[nt][1]);
            }
        __syncthreads();
    }

#pragma unroll
    for (int mt = 0; mt < 2; ++mt) {
        const int row = brow + wm * 32 + mt * 16 + g;
#pragma unroll
        for (int nt = 0; nt < 8; ++nt) {
            const int col = bcol + wn * 64 + nt * 8 + t * 2;
            *reinterpret_cast<float2*>(C + (size_t)row * N + col) =
                make_float2(acc[mt][nt][0], acc[mt][nt][1]);
            *reinterpret_cast<float2*>(C + (size_t)(row + 8) * N + col) =
                make_float2(acc[mt][nt][2], acc[mt][nt][3]);
        }
    }
}

// ---------------- fused LN + logits GEMM (fp16 2-term) ----------------
__global__ void __launch_bounds__(256, 1)
gemm_ln_logits(const float* __restrict__ X, const float* __restrict__ Wag,
               const float* __restrict__ wsum, const float* __restrict__ cb,
               float* __restrict__ L) {
    __shared__ float As[2][128][20];
    __shared__ float Bs[2][128][20];
    __shared__ float sm_mean[128];
    __shared__ float sm_rstd[128];

    const int tid  = threadIdx.x;
    const int lane = tid & 31;
    const int warp = tid >> 5;
    const int wm   = warp & 3;
    const int wn   = warp >> 2;
    const int g    = lane >> 2;
    const int t    = lane & 3;

    const int brow = blockIdx.y * 128;
    const int K = DD;

    float acc[2][8][4];
#pragma unroll
    for (int i = 0; i < 2; ++i)
#pragma unroll
        for (int j = 0; j < 8; ++j)
#pragma unroll
            for (int q = 0; q < 4; ++q) acc[i][j][q] = 0.f;

    const int r0 = tid >> 2;
    const int kc = (tid & 3) * 4;
    const int ktiles = K / 16;

    float sumA = 0.f, sqA = 0.f, sumB = 0.f, sqB = 0.f;

    auto issue = [&](int kt, int s) {
        const float* Ag = X + (size_t)(brow + r0) * K + kt * 16 + kc;
        const float* Bg = Wag + (size_t)r0 * K + kt * 16 + kc;
        CP_ASYNC16(smem_u32(&As[s][r0][kc]),      Ag);
        CP_ASYNC16(smem_u32(&As[s][r0 + 64][kc]), Ag + (size_t)64 * K);
        CP_ASYNC16(smem_u32(&Bs[s][r0][kc]),      Bg);
        CP_ASYNC16(smem_u32(&Bs[s][r0 + 64][kc]), Bg + (size_t)64 * K);
    };

    issue(0, 0);
    CP_COMMIT();

    for (int kt = 0; kt < ktiles; ++kt) {
        const int cur = kt & 1;
        if (kt + 1 < ktiles) {
            issue(kt + 1, (kt + 1) & 1);
            CP_COMMIT();
            CP_WAIT(1);
        } else {
            CP_WAIT(0);
        }
        __syncthreads();

        // row-stat accumulation for LN (each thread: 4 cols of rows r0, r0+64)
        {
            const float4 va = *reinterpret_cast<const float4*>(&As[cur][r0][kc]);
            const float4 vb = *reinterpret_cast<const float4*>(&As[cur][r0 + 64][kc]);
            sumA += va.x + va.y + va.z + va.w;
            sqA  += va.x * va.x + va.y * va.y + va.z * va.z + va.w * va.w;
            sumB += vb.x + vb.y + vb.z + vb.w;
            sqB  += vb.x * vb.x + vb.y * vb.y + vb.z * vb.z + vb.w * vb.w;
        }

        uint32_t ah[2][4], al[2][4];
#pragma unroll
        for (int mt = 0; mt < 2; ++mt) {
            const int row = wm * 32 + mt * 16 + g;
            const float2 v0 = *reinterpret_cast<const float2*>(&As[cur][row][2 * t]);
            const float2 v1 = *reinterpret_cast<const float2*>(&As[cur][row + 8][2 * t]);
            const float2 v2 = *reinterpret_cast<const float2*>(&As[cur][row][2 * t + 8]);
            const float2 v3 = *reinterpret_cast<const float2*>(&As[cur][row + 8][2 * t + 8]);
            split_f16(v0, ah[mt][0], al[mt][0]);
            split_f16(v1, ah[mt][1], al[mt][1]);
            split_f16(v2, ah[mt][2], al[mt][2]);
            split_f16(v3, ah[mt][3], al[mt][3]);
        }

        uint32_t bh[8][2];
#pragma unroll
        for (int nt = 0; nt < 8; ++nt) {
            const int col = wn * 64 + nt * 8 + g;
            bh[nt][0] = pack_f16(*reinterpret_cast<const float2*>(&Bs[cur][col][2 * t]));
            bh[nt][1] = pack_f16(*reinterpret_cast<const float2*>(&Bs[cur][col][2 * t + 8]));
        }

#pragma unroll
        for (int mt = 0; mt < 2; ++mt)
#pragma unroll
            for (int nt = 0; nt < 8; ++nt) {
                mma_f16(acc[mt][nt], al[mt][0], al[mt][1], al[mt][2], al[mt][3],
                        bh[nt][0], bh[nt][1]);
                mma_f16(acc[mt][nt], ah[mt][0], ah[mt][1], ah[mt][2], ah[mt][3],
                        bh[nt][0], bh[nt][1]);
            }
        __syncthreads();
    }

#pragma unroll
    for (int o = 1; o <= 2; o <<= 1) {
        sumA += __shfl_xor_sync(0xffffffffu, sumA, o);
        sqA  += __shfl_xor_sync(0xffffffffu, sqA, o);
        sumB += __shfl_xor_sync(0xffffffffu, sumB, o);
        sqB  += __shfl_xor_sync(0xffffffffu, sqB, o);
    }
    if ((tid & 3) == 0) {
        const float mA = sumA * (1.f / DD);
        const float mB = sumB * (1.f / DD);
        sm_mean[r0]      = mA;
        sm_mean[r0 + 64] = mB;
        sm_rstd[r0]      = rsqrtf(sqA * (1.f / DD) - mA * mA + 1e-5f);
        sm_rstd[r0 + 64] = rsqrtf(sqB * (1.f / DD) - mB * mB + 1e-5f);
    }
    __syncthreads();

#pragma unroll
    for (int mt = 0; mt < 2; ++mt) {
        const int lrow0 = wm * 32 + mt * 16 + g;
        const float m0 = sm_mean[lrow0],     r0s = sm_rstd[lrow0];
        const float m1 = sm_mean[lrow0 + 8], r1s = sm_rstd[lrow0 + 8];
        const int row = brow + lrow0;
#pragma unroll
        for (int nt = 0; nt < 8; ++nt) {
            const int col = wn * 64 + nt * 8 + t * 2;
            const float ws0 = wsum[col], ws1 = wsum[col + 1];
            const float cb0 = cb[col],   cb1 = cb[col + 1];
            float c0 = r0s * (acc[mt][nt][0] - m0 * ws0) + cb0;
            float c1 = r0s * (acc[mt][nt][1] - m0 * ws1) + cb1;
            float c2 = r1s * (acc[mt][nt][2] - m1 * ws0) + cb0;
            float c3 = r1s * (acc[mt][nt][3] - m1 * ws1) + cb1;
            *reinterpret_cast<float2*>(L + (size_t)row * KSLOT + col) = make_float2(c0, c1);
            *reinterpret_cast<float2*>(L + (size_t)(row + 8) * KSLOT + col) = make_float2(c2, c3);
        }
    }
}

// ---------------- small prep ----------------
__global__ void fuse_bias_kernel(const float* __restrict__ w0, const float* __restrict__ b_in,
                                 float* __restrict__ ba) {
    const int k = blockIdx.x;
    const int tid = threadIdx.x;  // 256
    const float4 w = reinterpret_cast<const float4*>(w0 + (size_t)k * DD)[tid];
    const float4 b = reinterpret_cast<const float4*>(b_in)[tid];
    float s = w.x * b.x + w.y * b.y + w.z * b.z + w.w * b.w;
#pragma unroll
    for (int o = 16; o > 0; o >>= 1) s += __shfl_xor_sync(0xffffffffu, s, o);
    __shared__ float red[8];
    if ((tid & 31) == 0) red[tid >> 5] = s;
    __syncthreads();
    if (tid == 0) {
        float S = 0.f;
#pragma unroll
        for (int i = 0; i < 8; ++i) S += red[i];
        ba[k] = S;
    }
}

__global__ void prep_wag_kernel(const float* __restrict__ Pa, const float* __restrict__ gg,
                                const float* __restrict__ bb, const float* __restrict__ ba,
                                float* __restrict__ Wag, float* __restrict__ wsum,
                                float* __restrict__ cb) {
    const int k = blockIdx.x;
    const int tid = threadIdx.x;  // 256
    float4 w = make_float4(0.f, 0.f, 0.f, 0.f);
#pragma unroll
    for (int ss = 0; ss < NSPLIT; ++ss) {
        const float4 p = reinterpret_cast<const float4*>(
            Pa + (size_t)ss * KSLOT * DD + (size_t)k * DD)[tid];
        w.x += p.x; w.y += p.y; w.z += p.z; w.w += p.w;
    }
    const float4 g4 = reinterpret_cast<const float4*>(gg)[tid];
    const float4 b4 = reinterpret_cast<const float4*>(bb)[tid];
    float4 wg;
    wg.x = w.x * g4.x; wg.y = w.y * g4.y; wg.z = w.z * g4.z; wg.w = w.w * g4.w;
    reinterpret_cast<float4*>(Wag + (size_t)k * DD)[tid] = wg;

    float s = wg.x + wg.y + wg.z + wg.w;
    float c = w.x * b4.x + w.y * b4.y + w.z * b4.z + w.w * b4.w;
#pragma unroll
    for (int o = 16; o > 0; o >>= 1) {
        s += __shfl_xor_sync(0xffffffffu, s, o);
        c += __shfl_xor_sync(0xffffffffu, c, o);
    }
    __shared__ float rs[8], rc[8];
    if ((tid & 31) == 0) { rs[tid >> 5] = s; rc[tid >> 5] = c; }
    __syncthreads();
    if (tid == 0) {
        float S = 0.f, C = 0.f;
#pragma unroll
        for (int i = 0; i < 8; ++i) { S += rs[i]; C += rc[i]; }
        wsum[k] = S;
        cb[k] = C + ba[k];
    }
}

// ---------------- final: out = relu(LN(h) + x_residual) ----------------
__global__ void final_kernel(const float* __restrict__ h, const float* __restrict__ xres,
                             const float* __restrict__ gg, const float* __restrict__ bb,
                             float* __restrict__ out) {
    const int row = blockIdx.x;
    const int tid = threadIdx.x;  // 256
    const float4 v = reinterpret_cast<const float4*>(h + (size_t)row * DD)[tid];

    __shared__ float red[8];
    float s = v.x + v.y + v.z + v.w;
#pragma unroll
    for (int o = 16; o > 0; o >>= 1) s += __shfl_xor_sync(0xffffffffu, s, o);
    if ((tid & 31) == 0) red[tid >> 5] = s;
    __syncthreads();
    float tot = 0.f;
#pragma unroll
    for (int i = 0; i < 8; ++i) tot += red[i];
    const float mean = tot * (1.f / DD);

    const float dx = v.x - mean, dy = v.y - mean, dz = v.z - mean, dw = v.w - mean;
    float q = dx * dx + dy * dy + dz * dz + dw * dw;
#pragma unroll
    for (int o = 16; o > 0; o >>= 1) q += __shfl_xor_sync(0xffffffffu, q, o);
    __syncthreads();
    if ((tid & 31) == 0) red[tid >> 5] = q;
    __syncthreads();
    float qtot = 0.f;
#pragma unroll
    for (int i = 0; i < 8; ++i) qtot += red[i];
    const float r = rsqrtf(qtot * (1.f / DD) + 1e-5f);

    const float4 g4 = reinterpret_cast<const float4*>(gg)[tid];
    const float4 b4 = reinterpret_cast<const float4*>(bb)[tid];
    const float4 xv = reinterpret_cast<const float4*>(xres + (size_t)row * DD)[tid];
    float4 o;
    o.x = fmaxf(dx * r * g4.x + b4.x + xv.x, 0.f);
    o.y = fmaxf(dy * r * g4.y + b4.y + xv.y, 0.f);
    o.z = fmaxf(dz * r * g4.z + b4.z + xv.z, 0.f);
    o.w = fmaxf(dw * r * g4.w + b4.w + xv.w, 0.f);
    reinterpret_cast<float4*>(out + (size_t)row * DD)[tid] = o;
}

// ---------------- softmax over positions (axis=N), 3 passes ----------------
__global__ void softmax_pass1(const float* __restrict__ logits) {
    const int b = blockIdx.x;
    const int c = blockIdx.y;
    const int k = threadIdx.x;  // 128
    const float* p = logits + ((size_t)b * NN + (size_t)c * 128) * KSLOT + k;
    float m = p[0], s = 1.f;
#pragma unroll 4
    for (int r = 1; r < 128; ++r) {
        const float v = p[(size_t)r * KSLOT];
        if (v <= m) {
            s += __expf(v - m);
        } else {
            s = s * __expf(m - v) + 1.f;
            m = v;
        }
    }
    g_pm[(b * NCHUNK + c) * KSLOT + k] = m;
    g_ps[(b * NCHUNK + c) * KSLOT + k] = s;
}

__global__ void softmax_pass2() {
    const int b = blockIdx.x;
    const int k = threadIdx.x;  // 128
    float M = NEG_INF;
#pragma unroll
    for (int c = 0; c < NCHUNK; ++c) M = fmaxf(M, g_pm[(b * NCHUNK + c) * KSLOT + k]);
    float S = 0.f;
#pragma unroll
    for (int c = 0; c < NCHUNK; ++c)
        S += g_ps[(b * NCHUNK + c) * KSLOT + k] * expf(g_pm[(b * NCHUNK + c) * KSLOT + k] - M);
    g_M[b * KSLOT + k] = M;
    g_S[b * KSLOT + k] = S;
}

__global__ void softmax_pass3(float* __restrict__ logits) {
    const int idx = blockIdx.x;
    const int b = idx >> 12;
    const int k = threadIdx.x;  // 128
    const size_t off = (size_t)idx * KSLOT + k;
    const float p = expf(logits[off] - g_M[b * KSLOT + k]) / g_S[b * KSLOT + k];

    float s = p;
#pragma unroll
    for (int o = 16; o > 0; o >>= 1) s += __shfl_xor_sync(0xffffffffu, s, o);
    __shared__ float red[4];
    if ((k & 31) == 0) red[k >> 5] = s;
    __syncthreads();
    const float tot = red[0] + red[1] + red[2] + red[3];
    logits[off] = p / (1e-9f + tot);
}

// ---------------- launch ----------------
extern "C" void kernel_launch(void* const* d_in, const int* in_sizes, int n_in,
                              void* d_out, int out_size) {
    const float* x     = (const float*)d_in[0];
    const float* ln_g  = (const float*)d_in[1];
    const float* ln_b  = (const float*)d_in[2];
    const float* w_in  = (const float*)d_in[3];
    const float* b_in  = (const float*)d_in[4];
    const float* w0    = (const float*)d_in[5];
    const float* w1    = (const float*)d_in[6];
    const float* w_out = (const float*)d_in[7];
    const float* og    = (const float*)d_in[8];
    const float* ob    = (const float*)d_in[9];
    float* out = (float*)d_out;

    static float* bufB = nullptr; static float* logits = nullptr;
    static float* Pa = nullptr; static float* Pb = nullptr;
    static float* Wag = nullptr; static float* ba = nullptr;
    static float* wsum = nullptr; static float* cb = nullptr; static float* Wb = nullptr;
    if (!bufB) {
        cudaGetSymbolAddress((void**)&bufB, g_bufB);
        cudaGetSymbolAddress((void**)&logits, g_logits);
        cudaGetSymbolAddress((void**)&Pa, g_Pa);
        cudaGetSymbolAddress((void**)&Pb, g_Pb);
        cudaGetSymbolAddress((void**)&Wag, g_Wag);
        cudaGetSymbolAddress((void**)&ba, g_ba);
        cudaGetSymbolAddress((void**)&wsum, g_wsum);
        cudaGetSymbolAddress((void**)&cb, g_cb);
        cudaGetSymbolAddress((void**)&Wb, g_Wb);
    }

    // ---- weight fusion (full-chip split-K fp32 SIMT) ----
    prep_gemm_splitk<<<dim3(DD / 64, KSLOT / 64, NSPLIT), 256>>>(w0, w_in, Pa, KSLOT, DD, DD);
    prep_gemm_splitk<<<dim3(KSLOT / 64, DD / 64, NSPLIT), 256>>>(w_out, w1, Pb, DD, KSLOT, DD);
    reduce_partials<<<(DD * KSLOT + 255) / 256, 256>>>(Pb, Wb, DD * KSLOT);
    fuse_bias_kernel<<<KSLOT, 256>>>(w0, b_in, ba);
    prep_wag_kernel<<<KSLOT, 256>>>(Pa, ln_g, ln_b, ba, Wag, wsum, cb);

    // ---- main path ----
    gemm_ln_logits<<<dim3(1, MTOT / 128), 256>>>(x, Wag, wsum, cb, logits);
    softmax_pass1<<<dim3(BB, NCHUNK), 128>>>(logits);
    softmax_pass2<<<BB, 128>>>();
    softmax_pass3<<<MTOT, 128>>>(logits);
    gemm_f16_kernel<<<dim3(DD / 128, MTOT / 128), 256>>>(logits, Wb, bufB, MTOT, DD, KSLOT);
    final_kernel<<<MTOT, 256>>>(bufB, x, og, ob, out);
}

// round 9
// speedup vs baseline: 9.9062x; 1.1077x over previous
#include <cuda_runtime.h>
#include <cuda_fp16.h>
#include <cstdint>
#include <cstddef>

#define BB 8
#define NN 4096
#define DD 1024
#define KSLOT 128
#define MTOT (BB * NN)        // 32768
#define NCHUNK 32             // NN / 128
#define NSPLIT 8              // split-K for weight prep

// ---------------- scratch ----------------
__device__ float g_logits[(size_t)MTOT * KSLOT];// 16 MiB
__device__ float g_pm[BB * NCHUNK * KSLOT];
__device__ float g_ps[BB * NCHUNK * KSLOT];
__device__ float g_M[BB * KSLOT];
__device__ float g_S[BB * KSLOT];
__device__ float g_Pa[(size_t)NSPLIT * KSLOT * DD];
__device__ float g_Pb[(size_t)NSPLIT * DD * KSLOT];
__device__ float g_Wag[(size_t)KSLOT * DD];
__device__ float g_ba[KSLOT];
__device__ float g_wsum[KSLOT];
__device__ float g_cb[KSLOT];
__device__ __half g_WbH[(size_t)DD * KSLOT];    // (w_out @ w1) rounded to fp16, [e,k]

#define NEG_INF __int_as_float(0xff800000)

// ---------------- fp16 split helpers ----------------
__device__ __forceinline__ uint32_t pack_f16(float2 v) {
    __half2 h = __floats2half2_rn(v.x, v.y);
    return *reinterpret_cast<uint32_t*>(&h);
}

__device__ __forceinline__ void split_f16(float2 v, uint32_t& hi, uint32_t& lo) {
    __half2 h = __floats2half2_rn(v.x, v.y);
    hi = *reinterpret_cast<uint32_t*>(&h);
    const float2 hf = __half22float2(h);
    __half2 l = __floats2half2_rn(v.x - hf.x, v.y - hf.y);
    lo = *reinterpret_cast<uint32_t*>(&l);
}

// m16n8k16 fp16 MMA, fp32 accumulate
__device__ __forceinline__ void mma_f16(float* c,
                                        uint32_t a0, uint32_t a1, uint32_t a2, uint32_t a3,
                                        uint32_t b0, uint32_t b1) {
    asm volatile(
        "mma.sync.aligned.m16n8k16.row.col.f32.f16.f16.f32 "
        "{%0,%1,%2,%3}, {%4,%5,%6,%7}, {%8,%9}, {%0,%1,%2,%3};"
        : "+f"(c[0]), "+f"(c[1]), "+f"(c[2]), "+f"(c[3])
        : "r"(a0), "r"(a1), "r"(a2), "r"(a3), "r"(b0), "r"(b1));
}

__device__ __forceinline__ uint32_t smem_u32(const void* p) {
    uint32_t addr;
    asm("{ .reg .u64 tmp; cvta.to.shared.u64 tmp, %1; cvt.u32.u64 %0, tmp; }"
        : "=r"(addr) : "l"(p));
    return addr;
}

#define CP_ASYNC16(dst, src) \
    asm volatile("cp.async.cg.shared.global [%0], [%1], 16;\n" ::"r"(dst), "l"(src))
#define CP_COMMIT() asm volatile("cp.async.commit_group;\n")
#define CP_WAIT(N_) asm volatile("cp.async.wait_group %0;\n" ::"n"(N_))

// ================= fused h3 GEMM + LN + residual + relu =================
// block = 32 rows of a (BM=32), full N=1024 columns, K=128.
// smem layout (bytes):
#define H3S 1036                        // h3 tile row stride in floats (12 mod 32)
#define FH_A_OFF   132608               // 32*1036*4 for h3 tile before it
#define FH_A_STR   132                  // A stage row stride (floats)
#define FH_B_OFF   149504               // FH_A_OFF + 32*132*4
#define FH_B_STR   136                  // B tile row stride (halves)
#define FH_B_SZ    34816                // 128*136*2
#define FH_PART_OFF 219136              // FH_B_OFF + 2*FH_B_SZ
#define FH_STAT_OFF 220160              // + 256 floats of partials
#define FH_SMEM     220416              // + mean[32]+rstd[32]

__global__ void __launch_bounds__(256, 1)
h3_final_fused(const float* __restrict__ A, const __half* __restrict__ WbH,
               const float* __restrict__ xres, const float* __restrict__ gg,
               const float* __restrict__ bb, float* __restrict__ out) {
    extern __shared__ char sm[];
    const uint32_t sbase = smem_u32(sm);
    float* h3s = reinterpret_cast<float*>(sm);
    float* As  = reinterpret_cast<float*>(sm + FH_A_OFF);
    float* part = reinterpret_cast<float*>(sm + FH_PART_OFF);  // [0..127]=sum [128..255]=sq, idx wn*32+row
    float* stat = reinterpret_cast<float*>(sm + FH_STAT_OFF);  // [0..31]=mean [32..63]=rstd

    const int tid  = threadIdx.x;
    const int warp = tid >> 5;
    const int lane = tid & 31;
    const int wm   = warp & 1;   // 2 m-positions of 16 rows
    const int wn   = warp >> 1;  // 4 n-positions of 32 cols
    const int g    = lane >> 2;
    const int t    = lane & 3;
    const int brow = blockIdx.x * 32;

    part[tid] = 0.f;  // 256 floats

    // issue A stage (32 x 128 fp32) + B tile 0, one commit group
#pragma unroll
    for (int i = 0; i < 4; ++i) {
        const int linear = tid + i * 256;     // 0..1023
        const int row = linear >> 5;
        const int c   = linear & 31;          // 16B chunk
        CP_ASYNC16(sbase + FH_A_OFF + row * (FH_A_STR * 4) + c * 16,
                   (const char*)A + (size_t)(brow + row) * KSLOT * 4 + c * 16);
    }
#pragma unroll
    for (int i = 0; i < 8; ++i) {
        const int linear = tid + i * 256;     // 0..2047
        const int e = linear >> 4;
        const int c = linear & 15;
        CP_ASYNC16(sbase + FH_B_OFF + e * (FH_B_STR * 2) + c * 16,
                   (const char*)WbH + (size_t)e * KSLOT * 2 + c * 16);
    }
    CP_COMMIT();
    // issue B tile 1
#pragma unroll
    for (int i = 0; i < 8; ++i) {
        const int linear = tid + i * 256;
        const int e = linear >> 4;
        const int c = linear & 15;
        CP_ASYNC16(sbase + FH_B_OFF + FH_B_SZ + e * (FH_B_STR * 2) + c * 16,
                   (const char*)WbH + (size_t)(128 + e) * KSLOT * 2 + c * 16);
    }
    CP_COMMIT();

    uint32_t ah[8][4], al[8][4];
    float acc[4][4];
#pragma unroll
    for (int nf = 0; nf < 4; ++nf)
#pragma unroll
        for (int q = 0; q < 4; ++q) acc[nf][q] = 0.f;
    float s0 = 0.f, q0 = 0.f, s1 = 0.f, q1 = 0.f;

    for (int nt = 0; nt < 8; ++nt) {
        if (nt < 6) { CP_WAIT(1); } else { CP_WAIT(0); }
        __syncthreads();

        if (nt == 0) {
            // convert this warp's A fragments once (rows wm*16+g, +8; all K)
            const int r0 = wm * 16 + g;
#pragma unroll
            for (int kk = 0; kk < 8; ++kk) {
                const int kb = kk * 16 + 2 * t;
                const float2 v0 = *reinterpret_cast<const float2*>(&As[r0 * FH_A_STR + kb]);
                const float2 v1 = *reinterpret_cast<const float2*>(&As[(r0 + 8) * FH_A_STR + kb]);
                const float2 v2 = *reinterpret_cast<const float2*>(&As[r0 * FH_A_STR + kb + 8]);
                const float2 v3 = *reinterpret_cast<const float2*>(&As[(r0 + 8) * FH_A_STR + kb + 8]);
                split_f16(v0, ah[kk][0], al[kk][0]);
                split_f16(v1, ah[kk][1], al[kk][1]);
                split_f16(v2, ah[kk][2], al[kk][2]);
                split_f16(v3, ah[kk][3], al[kk][3]);
            }
        }

        // compute this column tile from buf[nt&1]
        const char* bB = sm + FH_B_OFF + (nt & 1) * FH_B_SZ;
#pragma unroll
        for (int kk = 0; kk < 8; ++kk) {
            uint32_t b0[4], b1[4];
#pragma unroll
            for (int nf = 0; nf < 4; ++nf) {
                const int e = wn * 32 + nf * 8 + g;
                const char* p = bB + e * (FH_B_STR * 2) + (kk * 16 + 2 * t) * 2;
                b0[nf] = *reinterpret_cast<const uint32_t*>(p);
                b1[nf] = *reinterpret_cast<const uint32_t*>(p + 16);
            }
#pragma unroll
            for (int nf = 0; nf < 4; ++nf) {
                mma_f16(acc[nf], al[kk][0], al[kk][1], al[kk][2], al[kk][3], b0[nf], b1[nf]);
                mma_f16(acc[nf], ah[kk][0], ah[kk][1], ah[kk][2], ah[kk][3], b0[nf], b1[nf]);
            }
        }

        // write tile to h3 smem + accumulate row stats, reset acc
        {
            const int r0 = wm * 16 + g;
#pragma unroll
            for (int nf = 0; nf < 4; ++nf) {
                const int col = nt * 128 + wn * 32 + nf * 8 + 2 * t;
                *reinterpret_cast<float2*>(&h3s[r0 * H3S + col]) =
                    make_float2(acc[nf][0], acc[nf][1]);
                *reinterpret_cast<float2*>(&h3s[(r0 + 8) * H3S + col]) =
                    make_float2(acc[nf][2], acc[nf][3]);
                s0 += acc[nf][0] + acc[nf][1];
                q0 += acc[nf][0] * acc[nf][0] + acc[nf][1] * acc[nf][1];
                s1 += acc[nf][2] + acc[nf][3];
                q1 += acc[nf][2] * acc[nf][2] + acc[nf][3] * acc[nf][3];
                acc[nf][0] = acc[nf][1] = acc[nf][2] = acc[nf][3] = 0.f;
            }
        }
        __syncthreads();

        if (nt + 2 < 8) {
            const int src_tile = nt + 2;
#pragma unroll
            for (int i = 0; i < 8; ++i) {
                const int linear = tid + i * 256;
                const int e = linear >> 4;
                const int c = linear & 15;
                CP_ASYNC16(sbase + FH_B_OFF + (src_tile & 1) * FH_B_SZ + e * (FH_B_STR * 2) + c * 16,
                           (const char*)WbH + (size_t)(src_tile * 128 + e) * KSLOT * 2 + c * 16);
            }
            CP_COMMIT();
        }
    }

    // deterministic row-stat reduction: over t via shfl, then over wn via smem
    s0 += __shfl_xor_sync(0xffffffffu, s0, 1); s0 += __shfl_xor_sync(0xffffffffu, s0, 2);
    q0 += __shfl_xor_sync(0xffffffffu, q0, 1); q0 += __shfl_xor_sync(0xffffffffu, q0, 2);
    s1 += __shfl_xor_sync(0xffffffffu, s1, 1); s1 += __shfl_xor_sync(0xffffffffu, s1, 2);
    q1 += __shfl_xor_sync(0xffffffffu, q1, 1); q1 += __shfl_xor_sync(0xffffffffu, q1, 2);
    if (t == 0) {
        const int r0 = wm * 16 + g;
        part[wn * 32 + r0]           = s0;
        part[wn * 32 + r0 + 8]       = s1;
        part[128 + wn * 32 + r0]     = q0;
        part[128 + wn * 32 + r0 + 8] = q1;
    }
    __syncthreads();

    if (tid < 32) {
        float S = 0.f, Q = 0.f;
#pragma unroll
        for (int w = 0; w < 4; ++w) {
            S += part[w * 32 + tid];
            Q += part[128 + w * 32 + tid];
        }
        const float m = S * (1.f / DD);
        stat[tid]      = m;
        stat[32 + tid] = rsqrtf(Q * (1.f / DD) - m * m + 1e-5f);
    }
    __syncthreads();

    // apply LN + residual + relu, write out. 8 threads per row.
    {
        const int row  = tid >> 3;
        const int grow = brow + row;
        const float m = stat[row];
        const float r = stat[32 + row];
        const float* h3r = &h3s[row * H3S];
        const float* xr  = xres + (size_t)grow * DD;
        float* outr      = out + (size_t)grow * DD;
#pragma unroll 4
        for (int j = 0; j < 32; ++j) {
            const int col = (tid & 7) * 4 + j * 32;
            const float4 h  = *reinterpret_cast<const float4*>(&h3r[col]);
            const float4 g4 = *reinterpret_cast<const float4*>(gg + col);
            const float4 b4 = *reinterpret_cast<const float4*>(bb + col);
            const float4 xv = *reinterpret_cast<const float4*>(xr + col);
            float4 o;
            o.x = fmaxf((h.x - m) * r * g4.x + b4.x + xv.x, 0.f);
            o.y = fmaxf((h.y - m) * r * g4.y + b4.y + xv.y, 0.f);
            o.z = fmaxf((h.z - m) * r * g4.z + b4.z + xv.z, 0.f);
            o.w = fmaxf((h.w - m) * r * g4.w + b4.w + xv.w, 0.f);
            *reinterpret_cast<float4*>(outr + col) = o;
        }
    }
}

// ---------------- split-K SIMT fp32 NN GEMM (weight prep only) ----------------
__global__ void __launch_bounds__(256, 1)
prep_gemm_splitk(const float* __restrict__ A, const float* __restrict__ B,
                 float* __restrict__ P, int M, int N, int K) {
    __shared__ float As[64][17];
    __shared__ float Bs[16][64];

    const int tid = threadIdx.x;
    const int tx = tid & 15;
    const int ty = tid >> 4;
    const int bm = blockIdx.y * 64;
    const int bn = blockIdx.x * 64;
    const int kchunk = K / NSPLIT;
    const int k0 = blockIdx.z * kchunk;

    float c[4][4];
#pragma unroll
    for (int q = 0; q < 4; ++q)
#pragma unroll
        for (int r = 0; r < 4; ++r) c[q][r] = 0.f;

    const int amm = tid >> 2;
    const int akk = (tid & 3) * 4;
    const int bc  = tid & 63;
    const int br0 = tid >> 6;

    for (int kt = 0; kt < kchunk; kt += 16) {
        const float4 va = *reinterpret_cast<const float4*>(
            A + (size_t)(bm + amm) * K + k0 + kt + akk);
        As[amm][akk + 0] = va.x;
        As[amm][akk + 1] = va.y;
        As[amm][akk + 2] = va.z;
        As[amm][akk + 3] = va.w;
#pragma unroll
        for (int j = 0; j < 4; ++j) {
            const int r = br0 + j * 4;
            Bs[r][bc] = B[(size_t)(k0 + kt + r) * N + bn + bc];
        }
        __syncthreads();

#pragma unroll
        for (int kk = 0; kk < 16; ++kk) {
            const float a0 = As[ty * 4 + 0][kk];
            const float a1 = As[ty * 4 + 1][kk];
            const float a2 = As[ty * 4 + 2][kk];
            const float a3 = As[ty * 4 + 3][kk];
            const float4 b = *reinterpret_cast<const float4*>(&Bs[kk][tx * 4]);
            c[0][0] += a0 * b.x; c[0][1] += a0 * b.y; c[0][2] += a0 * b.z; c[0][3] += a0 * b.w;
            c[1][0] += a1 * b.x; c[1][1] += a1 * b.y; c[1][2] += a1 * b.z; c[1][3] += a1 * b.w;
            c[2][0] += a2 * b.x; c[2][1] += a2 * b.y; c[2][2] += a2 * b.z; c[2][3] += a2 * b.w;
            c[3][0] += a3 * b.x; c[3][1] += a3 * b.y; c[3][2] += a3 * b.z; c[3][3] += a3 * b.w;
        }
        __syncthreads();
    }

    float* Pb = P + (size_t)blockIdx.z * M * N;
#pragma unroll
    for (int q = 0; q < 4; ++q) {
        const int row = bm + ty * 4 + q;
        *reinterpret_cast<float4*>(Pb + (size_t)row * N + bn + tx * 4) =
            make_float4(c[q][0], c[q][1], c[q][2], c[q][3]);
    }
}

// reduce NSPLIT partials -> fp16 (WbH for the fused kernel)
__global__ void reduce_partials_h(const float* __restrict__ P, __half* __restrict__ C, int total) {
    const int i = blockIdx.x * 256 + threadIdx.x;
    if (i >= total) return;
    float s = 0.f;
#pragma unroll
    for (int ss = 0; ss < NSPLIT; ++ss) s += P[(size_t)ss * total + i];
    C[i] = __float2half_rn(s);
}

// ---------------- fused LN + logits GEMM (fp16 2-term) ----------------
__global__ void __launch_bounds__(256, 1)
gemm_ln_logits(const float* __restrict__ X, const float* __restrict__ Wag,
               const float* __restrict__ wsum, const float* __restrict__ cb,
               float* __restrict__ L) {
    __shared__ float As[2][128][20];
    __shared__ float Bs[2][128][20];
    __shared__ float sm_mean[128];
    __shared__ float sm_rstd[128];

    const int tid  = threadIdx.x;
    const int lane = tid & 31;
    const int warp = tid >> 5;
    const int wm   = warp & 3;
    const int wn   = warp >> 2;
    const int g    = lane >> 2;
    const int t    = lane & 3;

    const int brow = blockIdx.y * 128;
    const int K = DD;

    float acc[2][8][4];
#pragma unroll
    for (int i = 0; i < 2; ++i)
#pragma unroll
        for (int j = 0; j < 8; ++j)
#pragma unroll
            for (int q = 0; q < 4; ++q) acc[i][j][q] = 0.f;

    const int r0 = tid >> 2;
    const int kc = (tid & 3) * 4;
    const int ktiles = K / 16;

    float sumA = 0.f, sqA = 0.f, sumB = 0.f, sqB = 0.f;

    auto issue = [&](int kt, int s) {
        const float* Ag = X + (size_t)(brow + r0) * K + kt * 16 + kc;
        const float* Bg = Wag + (size_t)r0 * K + kt * 16 + kc;
        CP_ASYNC16(smem_u32(&As[s][r0][kc]),      Ag);
        CP_ASYNC16(smem_u32(&As[s][r0 + 64][kc]), Ag + (size_t)64 * K);
        CP_ASYNC16(smem_u32(&Bs[s][r0][kc]),      Bg);
        CP_ASYNC16(smem_u32(&Bs[s][r0 + 64][kc]), Bg + (size_t)64 * K);
    };

    issue(0, 0);
    CP_COMMIT();

    for (int kt = 0; kt < ktiles; ++kt) {
        const int cur = kt & 1;
        if (kt + 1 < ktiles) {
            issue(kt + 1, (kt + 1) & 1);
            CP_COMMIT();
            CP_WAIT(1);
        } else {
            CP_WAIT(0);
        }
        __syncthreads();

        {
            const float4 va = *reinterpret_cast<const float4*>(&As[cur][r0][kc]);
            const float4 vb = *reinterpret_cast<const float4*>(&As[cur][r0 + 64][kc]);
            sumA += va.x + va.y + va.z + va.w;
            sqA  += va.x * va.x + va.y * va.y + va.z * va.z + va.w * va.w;
            sumB += vb.x + vb.y + vb.z + vb.w;
            sqB  += vb.x * vb.x + vb.y * vb.y + vb.z * vb.z + vb.w * vb.w;
        }

        uint32_t ah[2][4], al[2][4];
#pragma unroll
        for (int mt = 0; mt < 2; ++mt) {
            const int row = wm * 32 + mt * 16 + g;
            const float2 v0 = *reinterpret_cast<const float2*>(&As[cur][row][2 * t]);
            const float2 v1 = *reinterpret_cast<const float2*>(&As[cur][row + 8][2 * t]);
            const float2 v2 = *reinterpret_cast<const float2*>(&As[cur][row][2 * t + 8]);
            const float2 v3 = *reinterpret_cast<const float2*>(&As[cur][row + 8][2 * t + 8]);
            split_f16(v0, ah[mt][0], al[mt][0]);
            split_f16(v1, ah[mt][1], al[mt][1]);
            split_f16(v2, ah[mt][2], al[mt][2]);
            split_f16(v3, ah[mt][3], al[mt][3]);
        }

        uint32_t bh[8][2];
#pragma unroll
        for (int nt = 0; nt < 8; ++nt) {
            const int col = wn * 64 + nt * 8 + g;
            bh[nt][0] = pack_f16(*reinterpret_cast<const float2*>(&Bs[cur][col][2 * t]));
            bh[nt][1] = pack_f16(*reinterpret_cast<const float2*>(&Bs[cur][col][2 * t + 8]));
        }

#pragma unroll
        for (int mt = 0; mt < 2; ++mt)
#pragma unroll
            for (int nt = 0; nt < 8; ++nt) {
                mma_f16(acc[mt][nt], al[mt][0], al[mt][1], al[mt][2], al[mt][3],
                        bh[nt][0], bh[nt][1]);
                mma_f16(acc[mt][nt], ah[mt][0], ah[mt][1], ah[mt][2], ah[mt][3],
                        bh[nt][0], bh[nt][1]);
            }
        __syncthreads();
    }

#pragma unroll
    for (int o = 1; o <= 2; o <<= 1) {
        sumA += __shfl_xor_sync(0xffffffffu, sumA, o);
        sqA  += __shfl_xor_sync(0xffffffffu, sqA, o);
        sumB += __shfl_xor_sync(0xffffffffu, sumB, o);
        sqB  += __shfl_xor_sync(0xffffffffu, sqB, o);
    }
    if ((tid & 3) == 0) {
        const float mA = sumA * (1.f / DD);
        const float mB = sumB * (1.f / DD);
        sm_mean[r0]      = mA;
        sm_mean[r0 + 64] = mB;
        sm_rstd[r0]      = rsqrtf(sqA * (1.f / DD) - mA * mA + 1e-5f);
        sm_rstd[r0 + 64] = rsqrtf(sqB * (1.f / DD) - mB * mB + 1e-5f);
    }
    __syncthreads();

#pragma unroll
    for (int mt = 0; mt < 2; ++mt) {
        const int lrow0 = wm * 32 + mt * 16 + g;
        const float m0 = sm_mean[lrow0],     r0s = sm_rstd[lrow0];
        const float m1 = sm_mean[lrow0 + 8], r1s = sm_rstd[lrow0 + 8];
        const int row = brow + lrow0;
#pragma unroll
        for (int nt = 0; nt < 8; ++nt) {
            const int col = wn * 64 + nt * 8 + t * 2;
            const float ws0 = wsum[col], ws1 = wsum[col + 1];
            const float cb0 = cb[col],   cb1 = cb[col + 1];
            float c0 = r0s * (acc[mt][nt][0] - m0 * ws0) + cb0;
            float c1 = r0s * (acc[mt][nt][1] - m0 * ws1) + cb1;
            float c2 = r1s * (acc[mt][nt][2] - m1 * ws0) + cb0;
            float c3 = r1s * (acc[mt][nt][3] - m1 * ws1) + cb1;
            *reinterpret_cast<float2*>(L + (size_t)row * KSLOT + col) = make_float2(c0, c1);
            *reinterpret_cast<float2*>(L + (size_t)(row + 8) * KSLOT + col) = make_float2(c2, c3);
        }
    }
}

// ---------------- small prep ----------------
__global__ void fuse_bias_kernel(const float* __restrict__ w0, const float* __restrict__ b_in,
                                 float* __restrict__ ba) {
    const int k = blockIdx.x;
    const int tid = threadIdx.x;  // 256
    const float4 w = reinterpret_cast<const float4*>(w0 + (size_t)k * DD)[tid];
    const float4 b = reinterpret_cast<const float4*>(b_in)[tid];
    float s = w.x * b.x + w.y * b.y + w.z * b.z + w.w * b.w;
#pragma unroll
    for (int o = 16; o > 0; o >>= 1) s += __shfl_xor_sync(0xffffffffu, s, o);
    __shared__ float red[8];
    if ((tid & 31) == 0) red[tid >> 5] = s;
    __syncthreads();
    if (tid == 0) {
        float S = 0.f;
#pragma unroll
        for (int i = 0; i < 8; ++i) S += red[i];
        ba[k] = S;
    }
}

__global__ void prep_wag_kernel(const float* __restrict__ Pa, const float* __restrict__ gg,
                                const float* __restrict__ bb, const float* __restrict__ ba,
                                float* __restrict__ Wag, float* __restrict__ wsum,
                                float* __restrict__ cb) {
    const int k = blockIdx.x;
    const int tid = threadIdx.x;  // 256
    float4 w = make_float4(0.f, 0.f, 0.f, 0.f);
#pragma unroll
    for (int ss = 0; ss < NSPLIT; ++ss) {
        const float4 p = reinterpret_cast<const float4*>(
            Pa + (size_t)ss * KSLOT * DD + (size_t)k * DD)[tid];
        w.x += p.x; w.y += p.y; w.z += p.z; w.w += p.w;
    }
    const float4 g4 = reinterpret_cast<const float4*>(gg)[tid];
    const float4 b4 = reinterpret_cast<const float4*>(bb)[tid];
    float4 wg;
    wg.x = w.x * g4.x; wg.y = w.y * g4.y; wg.z = w.z * g4.z; wg.w = w.w * g4.w;
    reinterpret_cast<float4*>(Wag + (size_t)k * DD)[tid] = wg;

    float s = wg.x + wg.y + wg.z + wg.w;
    float c = w.x * b4.x + w.y * b4.y + w.z * b4.z + w.w * b4.w;
#pragma unroll
    for (int o = 16; o > 0; o >>= 1) {
        s += __shfl_xor_sync(0xffffffffu, s, o);
        c += __shfl_xor_sync(0xffffffffu, c, o);
    }
    __shared__ float rs[8], rc[8];
    if ((tid & 31) == 0) { rs[tid >> 5] = s; rc[tid >> 5] = c; }
    __syncthreads();
    if (tid == 0) {
        float S = 0.f, C = 0.f;
#pragma unroll
        for (int i = 0; i < 8; ++i) { S += rs[i]; C += rc[i]; }
        wsum[k] = S;
        cb[k] = C + ba[k];
    }
}

// ---------------- softmax over positions (axis=N), 3 passes ----------------
__global__ void softmax_pass1(const float* __restrict__ logits) {
    const int b = blockIdx.x;
    const int c = blockIdx.y;
    const int k = threadIdx.x;  // 128
    const float* p = logits + ((size_t)b * NN + (size_t)c * 128) * KSLOT + k;
    float m = p[0], s = 1.f;
#pragma unroll 4
    for (int r = 1; r < 128; ++r) {
        const float v = p[(size_t)r * KSLOT];
        if (v <= m) {
            s += __expf(v - m);
        } else {
            s = s * __expf(m - v) + 1.f;
            m = v;
        }
    }
    g_pm[(b * NCHUNK + c) * KSLOT + k] = m;
    g_ps[(b * NCHUNK + c) * KSLOT + k] = s;
}

__global__ void softmax_pass2() {
    const int b = blockIdx.x;
    const int k = threadIdx.x;  // 128
    float M = NEG_INF;
#pragma unroll
    for (int c = 0; c < NCHUNK; ++c) M = fmaxf(M, g_pm[(b * NCHUNK + c) * KSLOT + k]);
    float S = 0.f;
#pragma unroll
    for (int c = 0; c < NCHUNK; ++c)
        S += g_ps[(b * NCHUNK + c) * KSLOT + k] * expf(g_pm[(b * NCHUNK + c) * KSLOT + k] - M);
    g_M[b * KSLOT + k] = M;
    g_S[b * KSLOT + k] = S;
}

__global__ void softmax_pass3(float* __restrict__ logits) {
    const int idx = blockIdx.x;
    const int b = idx >> 12;
    const int k = threadIdx.x;  // 128
    const size_t off = (size_t)idx * KSLOT + k;
    const float p = expf(logits[off] - g_M[b * KSLOT + k]) / g_S[b * KSLOT + k];

    float s = p;
#pragma unroll
    for (int o = 16; o > 0; o >>= 1) s += __shfl_xor_sync(0xffffffffu, s, o);
    __shared__ float red[4];
    if ((k & 31) == 0) red[k >> 5] = s;
    __syncthreads();
    const float tot = red[0] + red[1] + red[2] + red[3];
    logits[off] = p / (1e-9f + tot);
}

// ---------------- launch ----------------
extern "C" void kernel_launch(void* const* d_in, const int* in_sizes, int n_in,
                              void* d_out, int out_size) {
    const float* x     = (const float*)d_in[0];
    const float* ln_g  = (const float*)d_in[1];
    const float* ln_b  = (const float*)d_in[2];
    const float* w_in  = (const float*)d_in[3];
    const float* b_in  = (const float*)d_in[4];
    const float* w0    = (const float*)d_in[5];
    const float* w1    = (const float*)d_in[6];
    const float* w_out = (const float*)d_in[7];
    const float* og    = (const float*)d_in[8];
    const float* ob    = (const float*)d_in[9];
    float* out = (float*)d_out;

    static float* logits = nullptr;
    static float* Pa = nullptr; static float* Pb = nullptr;
    static float* Wag = nullptr; static float* ba = nullptr;
    static float* wsum = nullptr; static float* cb = nullptr;
    static __half* WbH = nullptr;
    if (!logits) {
        cudaGetSymbolAddress((void**)&logits, g_logits);
        cudaGetSymbolAddress((void**)&Pa, g_Pa);
        cudaGetSymbolAddress((void**)&Pb, g_Pb);
        cudaGetSymbolAddress((void**)&Wag, g_Wag);
        cudaGetSymbolAddress((void**)&ba, g_ba);
        cudaGetSymbolAddress((void**)&wsum, g_wsum);
        cudaGetSymbolAddress((void**)&cb, g_cb);
        cudaGetSymbolAddress((void**)&WbH, g_WbH);
        cudaFuncSetAttribute(h3_final_fused, cudaFuncAttributeMaxDynamicSharedMemorySize, FH_SMEM);
    }

    // ---- weight fusion (full-chip split-K fp32 SIMT) ----
    prep_gemm_splitk<<<dim3(DD / 64, KSLOT / 64, NSPLIT), 256>>>(w0, w_in, Pa, KSLOT, DD, DD);
    prep_gemm_splitk<<<dim3(KSLOT / 64, DD / 64, NSPLIT), 256>>>(w_out, w1, Pb, DD, KSLOT, DD);
    reduce_partials_h<<<(DD * KSLOT + 255) / 256, 256>>>(Pb, WbH, DD * KSLOT);
    fuse_bias_kernel<<<KSLOT, 256>>>(w0, b_in, ba);
    prep_wag_kernel<<<KSLOT, 256>>>(Pa, ln_g, ln_b, ba, Wag, wsum, cb);

    // ---- main path ----
    gemm_ln_logits<<<dim3(1, MTOT / 128), 256>>>(x, Wag, wsum, cb, logits);
    softmax_pass1<<<dim3(BB, NCHUNK), 128>>>(logits);
    softmax_pass2<<<BB, 128>>>();
    softmax_pass3<<<MTOT, 128>>>(logits);
    // fused: h3 = a @ WbH^T, LN, +x, relu -> out  (h3 never hits DRAM)
    h3_final_fused<<<MTOT / 32, 256, FH_SMEM>>>(logits, WbH, x, og, ob, out);
}

// round 10
// speedup vs baseline: 10.1320x; 1.0228x over previous
#include <cuda_runtime.h>
#include <cuda_fp16.h>
#include <cstdint>
#include <cstddef>

#define BB 8
#define NN 4096
#define DD 1024
#define KSLOT 128
#define MTOT (BB * NN)        // 32768
#define NCHUNK 32             // NN / 128
#define NSPLIT 8              // split-K for weight prep

// ---------------- scratch ----------------
__device__ float g_logits[(size_t)MTOT * KSLOT];// 16 MiB (raw logits)
__device__ float g_pm[BB * NCHUNK * KSLOT];
__device__ float g_ps[BB * NCHUNK * KSLOT];
__device__ float g_M[BB * KSLOT];
__device__ float g_S[BB * KSLOT];
__device__ float g_Pa[(size_t)NSPLIT * KSLOT * DD];
__device__ float g_Pb[(size_t)NSPLIT * DD * KSLOT];
__device__ float g_Wag[(size_t)KSLOT * DD];
__device__ float g_ba[KSLOT];
__device__ float g_wsum[KSLOT];
__device__ float g_cb[KSLOT];
__device__ __half g_WbH[(size_t)DD * KSLOT];    // (w_out @ w1) rounded to fp16, [e,k]

#define NEG_INF __int_as_float(0xff800000)

// ---------------- fp16 split helpers ----------------
__device__ __forceinline__ uint32_t pack_f16(float2 v) {
    __half2 h = __floats2half2_rn(v.x, v.y);
    return *reinterpret_cast<uint32_t*>(&h);
}

__device__ __forceinline__ void split_f16(float2 v, uint32_t& hi, uint32_t& lo) {
    __half2 h = __floats2half2_rn(v.x, v.y);
    hi = *reinterpret_cast<uint32_t*>(&h);
    const float2 hf = __half22float2(h);
    __half2 l = __floats2half2_rn(v.x - hf.x, v.y - hf.y);
    lo = *reinterpret_cast<uint32_t*>(&l);
}

// m16n8k16 fp16 MMA, fp32 accumulate
__device__ __forceinline__ void mma_f16(float* c,
                                        uint32_t a0, uint32_t a1, uint32_t a2, uint32_t a3,
                                        uint32_t b0, uint32_t b1) {
    asm volatile(
        "mma.sync.aligned.m16n8k16.row.col.f32.f16.f16.f32 "
        "{%0,%1,%2,%3}, {%4,%5,%6,%7}, {%8,%9}, {%0,%1,%2,%3};"
        : "+f"(c[0]), "+f"(c[1]), "+f"(c[2]), "+f"(c[3])
        : "r"(a0), "r"(a1), "r"(a2), "r"(a3), "r"(b0), "r"(b1));
}

__device__ __forceinline__ uint32_t smem_u32(const void* p) {
    uint32_t addr;
    asm("{ .reg .u64 tmp; cvta.to.shared.u64 tmp, %1; cvt.u32.u64 %0, tmp; }"
        : "=r"(addr) : "l"(p));
    return addr;
}

#define CP_ASYNC16(dst, src) \
    asm volatile("cp.async.cg.shared.global [%0], [%1], 16;\n" ::"r"(dst), "l"(src))
#define CP_COMMIT() asm volatile("cp.async.commit_group;\n")
#define CP_WAIT(N_) asm volatile("cp.async.wait_group %0;\n" ::"n"(N_))

// ================= fused h3 GEMM + softmax-normalize + LN + residual + relu =================
// block = 32 rows of logits (BM=32), full N=1024 columns, K=128.
#define H3S 1036
#define FH_A_OFF   132608               // 32*1036*4
#define FH_A_STR   132
#define FH_B_OFF   149504               // FH_A_OFF + 32*132*4
#define FH_B_STR   136
#define FH_B_SZ    34816                // 128*136*2
#define FH_PART_OFF 219136
#define FH_STAT_OFF 220160
#define FH_SMEM     220416

__global__ void __launch_bounds__(256, 1)
h3_final_fused(const float* __restrict__ A, const __half* __restrict__ WbH,
               const float* __restrict__ xres, const float* __restrict__ gg,
               const float* __restrict__ bb, float* __restrict__ out) {
    extern __shared__ char sm[];
    const uint32_t sbase = smem_u32(sm);
    float* h3s = reinterpret_cast<float*>(sm);
    float* As  = reinterpret_cast<float*>(sm + FH_A_OFF);
    float* part = reinterpret_cast<float*>(sm + FH_PART_OFF);
    float* stat = reinterpret_cast<float*>(sm + FH_STAT_OFF);

    const int tid  = threadIdx.x;
    const int warp = tid >> 5;
    const int lane = tid & 31;
    const int wm   = warp & 1;
    const int wn   = warp >> 1;
    const int g    = lane >> 2;
    const int t    = lane & 3;
    const int brow = blockIdx.x * 32;

    part[tid] = 0.f;

    // issue A stage (32 x 128 fp32 raw logits) + B tile 0
#pragma unroll
    for (int i = 0; i < 4; ++i) {
        const int linear = tid + i * 256;
        const int row = linear >> 5;
        const int c   = linear & 31;
        CP_ASYNC16(sbase + FH_A_OFF + row * (FH_A_STR * 4) + c * 16,
                   (const char*)A + (size_t)(brow + row) * KSLOT * 4 + c * 16);
    }
#pragma unroll
    for (int i = 0; i < 8; ++i) {
        const int linear = tid + i * 256;
        const int e = linear >> 4;
        const int c = linear & 15;
        CP_ASYNC16(sbase + FH_B_OFF + e * (FH_B_STR * 2) + c * 16,
                   (const char*)WbH + (size_t)e * KSLOT * 2 + c * 16);
    }
    CP_COMMIT();
#pragma unroll
    for (int i = 0; i < 8; ++i) {
        const int linear = tid + i * 256;
        const int e = linear >> 4;
        const int c = linear & 15;
        CP_ASYNC16(sbase + FH_B_OFF + FH_B_SZ + e * (FH_B_STR * 2) + c * 16,
                   (const char*)WbH + (size_t)(128 + e) * KSLOT * 2 + c * 16);
    }
    CP_COMMIT();

    uint32_t ah[8][4], al[8][4];
    float acc[4][4];
#pragma unroll
    for (int nf = 0; nf < 4; ++nf)
#pragma unroll
        for (int q = 0; q < 4; ++q) acc[nf][q] = 0.f;
    float s0 = 0.f, q0 = 0.f, s1 = 0.f, q1 = 0.f;

    for (int nt = 0; nt < 8; ++nt) {
        if (nt < 6) { CP_WAIT(1); } else { CP_WAIT(0); }
        __syncthreads();

        if (nt == 0) {
            // softmax-normalize A tile in place: p = exp(l - M)/S, then L1 over k
            {
                const int b = brow >> 12;
                const int row = tid >> 3;
                const int c0 = (tid & 7) * 16;
                float* ar = &As[row * FH_A_STR + c0];
                float pv[16];
                float tot = 0.f;
#pragma unroll
                for (int j = 0; j < 16; ++j) {
                    const int k = c0 + j;
                    pv[j] = __expf(ar[j] - g_M[b * KSLOT + k]) / g_S[b * KSLOT + k];
                    tot += pv[j];
                }
                tot += __shfl_xor_sync(0xffffffffu, tot, 1);
                tot += __shfl_xor_sync(0xffffffffu, tot, 2);
                tot += __shfl_xor_sync(0xffffffffu, tot, 4);
                const float inv = 1.f / (1e-9f + tot);
#pragma unroll
                for (int j = 0; j < 16; ++j) ar[j] = pv[j] * inv;
            }
            __syncthreads();

            // convert this warp's A fragments once (rows wm*16+g, +8; all K)
            const int r0 = wm * 16 + g;
#pragma unroll
            for (int kk = 0; kk < 8; ++kk) {
                const int kb = kk * 16 + 2 * t;
                const float2 v0 = *reinterpret_cast<const float2*>(&As[r0 * FH_A_STR + kb]);
                const float2 v1 = *reinterpret_cast<const float2*>(&As[(r0 + 8) * FH_A_STR + kb]);
                const float2 v2 = *reinterpret_cast<const float2*>(&As[r0 * FH_A_STR + kb + 8]);
                const float2 v3 = *reinterpret_cast<const float2*>(&As[(r0 + 8) * FH_A_STR + kb + 8]);
                split_f16(v0, ah[kk][0], al[kk][0]);
                split_f16(v1, ah[kk][1], al[kk][1]);
                split_f16(v2, ah[kk][2], al[kk][2]);
                split_f16(v3, ah[kk][3], al[kk][3]);
            }
        }

        const char* bB = sm + FH_B_OFF + (nt & 1) * FH_B_SZ;
#pragma unroll
        for (int kk = 0; kk < 8; ++kk) {
            uint32_t b0[4], b1[4];
#pragma unroll
            for (int nf = 0; nf < 4; ++nf) {
                const int e = wn * 32 + nf * 8 + g;
                const char* p = bB + e * (FH_B_STR * 2) + (kk * 16 + 2 * t) * 2;
                b0[nf] = *reinterpret_cast<const uint32_t*>(p);
                b1[nf] = *reinterpret_cast<const uint32_t*>(p + 16);
            }
#pragma unroll
            for (int nf = 0; nf < 4; ++nf) {
                mma_f16(acc[nf], al[kk][0], al[kk][1], al[kk][2], al[kk][3], b0[nf], b1[nf]);
                mma_f16(acc[nf], ah[kk][0], ah[kk][1], ah[kk][2], ah[kk][3], b0[nf], b1[nf]);
            }
        }

        {
            const int r0 = wm * 16 + g;
#pragma unroll
            for (int nf = 0; nf < 4; ++nf) {
                const int col = nt * 128 + wn * 32 + nf * 8 + 2 * t;
                *reinterpret_cast<float2*>(&h3s[r0 * H3S + col]) =
                    make_float2(acc[nf][0], acc[nf][1]);
                *reinterpret_cast<float2*>(&h3s[(r0 + 8) * H3S + col]) =
                    make_float2(acc[nf][2], acc[nf][3]);
                s0 += acc[nf][0] + acc[nf][1];
                q0 += acc[nf][0] * acc[nf][0] + acc[nf][1] * acc[nf][1];
                s1 += acc[nf][2] + acc[nf][3];
                q1 += acc[nf][2] * acc[nf][2] + acc[nf][3] * acc[nf][3];
                acc[nf][0] = acc[nf][1] = acc[nf][2] = acc[nf][3] = 0.f;
            }
        }
        __syncthreads();

        if (nt + 2 < 8) {
            const int src_tile = nt + 2;
#pragma unroll
            for (int i = 0; i < 8; ++i) {
                const int linear = tid + i * 256;
                const int e = linear >> 4;
                const int c = linear & 15;
                CP_ASYNC16(sbase + FH_B_OFF + (src_tile & 1) * FH_B_SZ + e * (FH_B_STR * 2) + c * 16,
                           (const char*)WbH + (size_t)(src_tile * 128 + e) * KSLOT * 2 + c * 16);
            }
            CP_COMMIT();
        }
    }

    // deterministic row-stat reduction
    s0 += __shfl_xor_sync(0xffffffffu, s0, 1); s0 += __shfl_xor_sync(0xffffffffu, s0, 2);
    q0 += __shfl_xor_sync(0xffffffffu, q0, 1); q0 += __shfl_xor_sync(0xffffffffu, q0, 2);
    s1 += __shfl_xor_sync(0xffffffffu, s1, 1); s1 += __shfl_xor_sync(0xffffffffu, s1, 2);
    q1 += __shfl_xor_sync(0xffffffffu, q1, 1); q1 += __shfl_xor_sync(0xffffffffu, q1, 2);
    if (t == 0) {
        const int r0 = wm * 16 + g;
        part[wn * 32 + r0]           = s0;
        part[wn * 32 + r0 + 8]       = s1;
        part[128 + wn * 32 + r0]     = q0;
        part[128 + wn * 32 + r0 + 8] = q1;
    }
    __syncthreads();

    if (tid < 32) {
        float S = 0.f, Q = 0.f;
#pragma unroll
        for (int w = 0; w < 4; ++w) {
            S += part[w * 32 + tid];
            Q += part[128 + w * 32 + tid];
        }
        const float m = S * (1.f / DD);
        stat[tid]      = m;
        stat[32 + tid] = rsqrtf(Q * (1.f / DD) - m * m + 1e-5f);
    }
    __syncthreads();

    {
        const int row  = tid >> 3;
        const int grow = brow + row;
        const float m = stat[row];
        const float r = stat[32 + row];
        const float* h3r = &h3s[row * H3S];
        const float* xr  = xres + (size_t)grow * DD;
        float* outr      = out + (size_t)grow * DD;
#pragma unroll 4
        for (int j = 0; j < 32; ++j) {
            const int col = (tid & 7) * 4 + j * 32;
            const float4 h  = *reinterpret_cast<const float4*>(&h3r[col]);
            const float4 g4 = *reinterpret_cast<const float4*>(gg + col);
            const float4 b4 = *reinterpret_cast<const float4*>(bb + col);
            const float4 xv = *reinterpret_cast<const float4*>(xr + col);
            float4 o;
            o.x = fmaxf((h.x - m) * r * g4.x + b4.x + xv.x, 0.f);
            o.y = fmaxf((h.y - m) * r * g4.y + b4.y + xv.y, 0.f);
            o.z = fmaxf((h.z - m) * r * g4.z + b4.z + xv.z, 0.f);
            o.w = fmaxf((h.w - m) * r * g4.w + b4.w + xv.w, 0.f);
            *reinterpret_cast<float4*>(outr + col) = o;
        }
    }
}

// ---------------- split-K SIMT fp32 NN GEMM (weight prep only) ----------------
__global__ void __launch_bounds__(256, 1)
prep_gemm_splitk(const float* __restrict__ A, const float* __restrict__ B,
                 float* __restrict__ P, int M, int N, int K) {
    __shared__ float As[64][17];
    __shared__ float Bs[16][64];

    const int tid = threadIdx.x;
    const int tx = tid & 15;
    const int ty = tid >> 4;
    const int bm = blockIdx.y * 64;
    const int bn = blockIdx.x * 64;
    const int kchunk = K / NSPLIT;
    const int k0 = blockIdx.z * kchunk;

    float c[4][4];
#pragma unroll
    for (int q = 0; q < 4; ++q)
#pragma unroll
        for (int r = 0; r < 4; ++r) c[q][r] = 0.f;

    const int amm = tid >> 2;
    const int akk = (tid & 3) * 4;
    const int bc  = tid & 63;
    const int br0 = tid >> 6;

    for (int kt = 0; kt < kchunk; kt += 16) {
        const float4 va = *reinterpret_cast<const float4*>(
            A + (size_t)(bm + amm) * K + k0 + kt + akk);
        As[amm][akk + 0] = va.x;
        As[amm][akk + 1] = va.y;
        As[amm][akk + 2] = va.z;
        As[amm][akk + 3] = va.w;
#pragma unroll
        for (int j = 0; j < 4; ++j) {
            const int r = br0 + j * 4;
            Bs[r][bc] = B[(size_t)(k0 + kt + r) * N + bn + bc];
        }
        __syncthreads();

#pragma unroll
        for (int kk = 0; kk < 16; ++kk) {
            const float a0 = As[ty * 4 + 0][kk];
            const float a1 = As[ty * 4 + 1][kk];
            const float a2 = As[ty * 4 + 2][kk];
            const float a3 = As[ty * 4 + 3][kk];
            const float4 b = *reinterpret_cast<const float4*>(&Bs[kk][tx * 4]);
            c[0][0] += a0 * b.x; c[0][1] += a0 * b.y; c[0][2] += a0 * b.z; c[0][3] += a0 * b.w;
            c[1][0] += a1 * b.x; c[1][1] += a1 * b.y; c[1][2] += a1 * b.z; c[1][3] += a1 * b.w;
            c[2][0] += a2 * b.x; c[2][1] += a2 * b.y; c[2][2] += a2 * b.z; c[2][3] += a2 * b.w;
            c[3][0] += a3 * b.x; c[3][1] += a3 * b.y; c[3][2] += a3 * b.z; c[3][3] += a3 * b.w;
        }
        __syncthreads();
    }

    float* Pb = P + (size_t)blockIdx.z * M * N;
#pragma unroll
    for (int q = 0; q < 4; ++q) {
        const int row = bm + ty * 4 + q;
        *reinterpret_cast<float4*>(Pb + (size_t)row * N + bn + tx * 4) =
            make_float4(c[q][0], c[q][1], c[q][2], c[q][3]);
    }
}

__global__ void reduce_partials_h(const float* __restrict__ P, __half* __restrict__ C, int total) {
    const int i = blockIdx.x * 256 + threadIdx.x;
    if (i >= total) return;
    float s = 0.f;
#pragma unroll
    for (int ss = 0; ss < NSPLIT; ++ss) s += P[(size_t)ss * total + i];
    C[i] = __float2half_rn(s);
}

// ---------------- fused LN + logits GEMM + softmax pass1 ----------------
__global__ void __launch_bounds__(256, 1)
gemm_ln_logits(const float* __restrict__ X, const float* __restrict__ Wag,
               const float* __restrict__ wsum, const float* __restrict__ cb,
               float* __restrict__ L) {
    __shared__ float As[2][128][20];
    __shared__ float Bs[2][128][20];
    __shared__ float sm_mean[128];
    __shared__ float sm_rstd[128];
    __shared__ float pm_part[4][KSLOT];
    __shared__ float ps_part[4][KSLOT];

    const int tid  = threadIdx.x;
    const int lane = tid & 31;
    const int warp = tid >> 5;
    const int wm   = warp & 3;
    const int wn   = warp >> 2;
    const int g    = lane >> 2;
    const int t    = lane & 3;

    const int brow = blockIdx.y * 128;
    const int K = DD;

    float acc[2][8][4];
#pragma unroll
    for (int i = 0; i < 2; ++i)
#pragma unroll
        for (int j = 0; j < 8; ++j)
#pragma unroll
            for (int q = 0; q < 4; ++q) acc[i][j][q] = 0.f;

    const int r0 = tid >> 2;
    const int kc = (tid & 3) * 4;
    const int ktiles = K / 16;

    float sumA = 0.f, sqA = 0.f, sumB = 0.f, sqB = 0.f;

    auto issue = [&](int kt, int s) {
        const float* Ag = X + (size_t)(brow + r0) * K + kt * 16 + kc;
        const float* Bg = Wag + (size_t)r0 * K + kt * 16 + kc;
        CP_ASYNC16(smem_u32(&As[s][r0][kc]),      Ag);
        CP_ASYNC16(smem_u32(&As[s][r0 + 64][kc]), Ag + (size_t)64 * K);
        CP_ASYNC16(smem_u32(&Bs[s][r0][kc]),      Bg);
        CP_ASYNC16(smem_u32(&Bs[s][r0 + 64][kc]), Bg + (size_t)64 * K);
    };

    issue(0, 0);
    CP_COMMIT();

    for (int kt = 0; kt < ktiles; ++kt) {
        const int cur = kt & 1;
        if (kt + 1 < ktiles) {
            issue(kt + 1, (kt + 1) & 1);
            CP_COMMIT();
            CP_WAIT(1);
        } else {
            CP_WAIT(0);
        }
        __syncthreads();

        {
            const float4 va = *reinterpret_cast<const float4*>(&As[cur][r0][kc]);
            const float4 vb = *reinterpret_cast<const float4*>(&As[cur][r0 + 64][kc]);
            sumA += va.x + va.y + va.z + va.w;
            sqA  += va.x * va.x + va.y * va.y + va.z * va.z + va.w * va.w;
            sumB += vb.x + vb.y + vb.z + vb.w;
            sqB  += vb.x * vb.x + vb.y * vb.y + vb.z * vb.z + vb.w * vb.w;
        }

        uint32_t ah[2][4], al[2][4];
#pragma unroll
        for (int mt = 0; mt < 2; ++mt) {
            const int row = wm * 32 + mt * 16 + g;
            const float2 v0 = *reinterpret_cast<const float2*>(&As[cur][row][2 * t]);
            const float2 v1 = *reinterpret_cast<const float2*>(&As[cur][row + 8][2 * t]);
            const float2 v2 = *reinterpret_cast<const float2*>(&As[cur][row][2 * t + 8]);
            const float2 v3 = *reinterpret_cast<const float2*>(&As[cur][row + 8][2 * t + 8]);
            split_f16(v0, ah[mt][0], al[mt][0]);
            split_f16(v1, ah[mt][1], al[mt][1]);
            split_f16(v2, ah[mt][2], al[mt][2]);
            split_f16(v3, ah[mt][3], al[mt][3]);
        }

        uint32_t bh[8][2];
#pragma unroll
        for (int nt = 0; nt < 8; ++nt) {
            const int col = wn * 64 + nt * 8 + g;
            bh[nt][0] = pack_f16(*reinterpret_cast<const float2*>(&Bs[cur][col][2 * t]));
            bh[nt][1] = pack_f16(*reinterpret_cast<const float2*>(&Bs[cur][col][2 * t + 8]));
        }

#pragma unroll
        for (int mt = 0; mt < 2; ++mt)
#pragma unroll
            for (int nt = 0; nt < 8; ++nt) {
                mma_f16(acc[mt][nt], al[mt][0], al[mt][1], al[mt][2], al[mt][3],
                        bh[nt][0], bh[nt][1]);
                mma_f16(acc[mt][nt], ah[mt][0], ah[mt][1], ah[mt][2], ah[mt][3],
                        bh[nt][0], bh[nt][1]);
            }
        __syncthreads();
    }

#pragma unroll
    for (int o = 1; o <= 2; o <<= 1) {
        sumA += __shfl_xor_sync(0xffffffffu, sumA, o);
        sqA  += __shfl_xor_sync(0xffffffffu, sqA, o);
        sumB += __shfl_xor_sync(0xffffffffu, sumB, o);
        sqB  += __shfl_xor_sync(0xffffffffu, sqB, o);
    }
    if ((tid & 3) == 0) {
        const float mA = sumA * (1.f / DD);
        const float mB = sumB * (1.f / DD);
        sm_mean[r0]      = mA;
        sm_mean[r0 + 64] = mB;
        sm_rstd[r0]      = rsqrtf(sqA * (1.f / DD) - mA * mA + 1e-5f);
        sm_rstd[r0 + 64] = rsqrtf(sqB * (1.f / DD) - mB * mB + 1e-5f);
    }
    __syncthreads();

    // apply LN affine; keep transformed values in acc for the softmax partials
#pragma unroll
    for (int mt = 0; mt < 2; ++mt) {
        const int lrow0 = wm * 32 + mt * 16 + g;
        const float m0 = sm_mean[lrow0],     r0s = sm_rstd[lrow0];
        const float m1 = sm_mean[lrow0 + 8], r1s = sm_rstd[lrow0 + 8];
        const int row = brow + lrow0;
#pragma unroll
        for (int nt = 0; nt < 8; ++nt) {
            const int col = wn * 64 + nt * 8 + t * 2;
            const float ws0 = wsum[col], ws1 = wsum[col + 1];
            const float cb0 = cb[col],   cb1 = cb[col + 1];
            acc[mt][nt][0] = r0s * (acc[mt][nt][0] - m0 * ws0) + cb0;
            acc[mt][nt][1] = r0s * (acc[mt][nt][1] - m0 * ws1) + cb1;
            acc[mt][nt][2] = r1s * (acc[mt][nt][2] - m1 * ws0) + cb0;
            acc[mt][nt][3] = r1s * (acc[mt][nt][3] - m1 * ws1) + cb1;
            *reinterpret_cast<float2*>(L + (size_t)row * KSLOT + col) =
                make_float2(acc[mt][nt][0], acc[mt][nt][1]);
            *reinterpret_cast<float2*>(L + (size_t)(row + 8) * KSLOT + col) =
                make_float2(acc[mt][nt][2], acc[mt][nt][3]);
        }
    }

    // softmax pass1: per-column (k) max + scaled exp-sum over this 128-row chunk
#pragma unroll
    for (int nt = 0; nt < 8; ++nt) {
        float m0 = fmaxf(fmaxf(acc[0][nt][0], acc[0][nt][2]), fmaxf(acc[1][nt][0], acc[1][nt][2]));
        float m1 = fmaxf(fmaxf(acc[0][nt][1], acc[0][nt][3]), fmaxf(acc[1][nt][1], acc[1][nt][3]));
#pragma unroll
        for (int o = 4; o <= 16; o <<= 1) {
            m0 = fmaxf(m0, __shfl_xor_sync(0xffffffffu, m0, o));
            m1 = fmaxf(m1, __shfl_xor_sync(0xffffffffu, m1, o));
        }
        float sc0 = __expf(acc[0][nt][0] - m0) + __expf(acc[0][nt][2] - m0) +
                    __expf(acc[1][nt][0] - m0) + __expf(acc[1][nt][2] - m0);
        float sc1 = __expf(acc[0][nt][1] - m1) + __expf(acc[0][nt][3] - m1) +
                    __expf(acc[1][nt][1] - m1) + __expf(acc[1][nt][3] - m1);
#pragma unroll
        for (int o = 4; o <= 16; o <<= 1) {
            sc0 += __shfl_xor_sync(0xffffffffu, sc0, o);
            sc1 += __shfl_xor_sync(0xffffffffu, sc1, o);
        }
        if (lane < 4) {  // g == 0
            const int col = wn * 64 + nt * 8 + 2 * t;
            pm_part[wm][col]     = m0;
            ps_part[wm][col]     = sc0;
            pm_part[wm][col + 1] = m1;
            ps_part[wm][col + 1] = sc1;
        }
    }
    __syncthreads();

    if (tid < KSLOT) {
        float M = fmaxf(fmaxf(pm_part[0][tid], pm_part[1][tid]),
                        fmaxf(pm_part[2][tid], pm_part[3][tid]));
        float S = ps_part[0][tid] * __expf(pm_part[0][tid] - M) +
                  ps_part[1][tid] * __expf(pm_part[1][tid] - M) +
                  ps_part[2][tid] * __expf(pm_part[2][tid] - M) +
                  ps_part[3][tid] * __expf(pm_part[3][tid] - M);
        g_pm[blockIdx.y * KSLOT + tid] = M;
        g_ps[blockIdx.y * KSLOT + tid] = S;
    }
}

// ---------------- small prep ----------------
__global__ void fuse_bias_kernel(const float* __restrict__ w0, const float* __restrict__ b_in,
                                 float* __restrict__ ba) {
    const int k = blockIdx.x;
    const int tid = threadIdx.x;  // 256
    const float4 w = reinterpret_cast<const float4*>(w0 + (size_t)k * DD)[tid];
    const float4 b = reinterpret_cast<const float4*>(b_in)[tid];
    float s = w.x * b.x + w.y * b.y + w.z * b.z + w.w * b.w;
#pragma unroll
    for (int o = 16; o > 0; o >>= 1) s += __shfl_xor_sync(0xffffffffu, s, o);
    __shared__ float red[8];
    if ((tid & 31) == 0) red[tid >> 5] = s;
    __syncthreads();
    if (tid == 0) {
        float S = 0.f;
#pragma unroll
        for (int i = 0; i < 8; ++i) S += red[i];
        ba[k] = S;
    }
}

__global__ void prep_wag_kernel(const float* __restrict__ Pa, const float* __restrict__ gg,
                                const float* __restrict__ bb, const float* __restrict__ ba,
                                float* __restrict__ Wag, float* __restrict__ wsum,
                                float* __restrict__ cb) {
    const int k = blockIdx.x;
    const int tid = threadIdx.x;  // 256
    float4 w = make_float4(0.f, 0.f, 0.f, 0.f);
#pragma unroll
    for (int ss = 0; ss < NSPLIT; ++ss) {
        const float4 p = reinterpret_cast<const float4*>(
            Pa + (size_t)ss * KSLOT * DD + (size_t)k * DD)[tid];
        w.x += p.x; w.y += p.y; w.z += p.z; w.w += p.w;
    }
    const float4 g4 = reinterpret_cast<const float4*>(gg)[tid];
    const float4 b4 = reinterpret_cast<const float4*>(bb)[tid];
    float4 wg;
    wg.x = w.x * g4.x; wg.y = w.y * g4.y; wg.z = w.z * g4.z; wg.w = w.w * g4.w;
    reinterpret_cast<float4*>(Wag + (size_t)k * DD)[tid] = wg;

    float s = wg.x + wg.y + wg.z + wg.w;
    float c = w.x * b4.x + w.y * b4.y + w.z * b4.z + w.w * b4.w;
#pragma unroll
    for (int o = 16; o > 0; o >>= 1) {
        s += __shfl_xor_sync(0xffffffffu, s, o);
        c += __shfl_xor_sync(0xffffffffu, c, o);
    }
    __shared__ float rs[8], rc[8];
    if ((tid & 31) == 0) { rs[tid >> 5] = s; rc[tid >> 5] = c; }
    __syncthreads();
    if (tid == 0) {
        float S = 0.f, C = 0.f;
#pragma unroll
        for (int i = 0; i < 8; ++i) { S += rs[i]; C += rc[i]; }
        wsum[k] = S;
        cb[k] = C + ba[k];
    }
}

// ---------------- softmax pass2: combine chunk partials ----------------
__global__ void softmax_pass2() {
    const int b = blockIdx.x;
    const int k = threadIdx.x;  // 128
    float M = NEG_INF;
#pragma unroll
    for (int c = 0; c < NCHUNK; ++c) M = fmaxf(M, g_pm[(b * NCHUNK + c) * KSLOT + k]);
    float S = 0.f;
#pragma unroll
    for (int c = 0; c < NCHUNK; ++c)
        S += g_ps[(b * NCHUNK + c) * KSLOT + k] * expf(g_pm[(b * NCHUNK + c) * KSLOT + k] - M);
    g_M[b * KSLOT + k] = M;
    g_S[b * KSLOT + k] = S;
}

// ---------------- launch ----------------
extern "C" void kernel_launch(void* const* d_in, const int* in_sizes, int n_in,
                              void* d_out, int out_size) {
    const float* x     = (const float*)d_in[0];
    const float* ln_g  = (const float*)d_in[1];
    const float* ln_b  = (const float*)d_in[2];
    const float* w_in  = (const float*)d_in[3];
    const float* b_in  = (const float*)d_in[4];
    const float* w0    = (const float*)d_in[5];
    const float* w1    = (const float*)d_in[6];
    const float* w_out = (const float*)d_in[7];
    const float* og    = (const float*)d_in[8];
    const float* ob    = (const float*)d_in[9];
    float* out = (float*)d_out;

    static float* logits = nullptr;
    static float* Pa = nullptr; static float* Pb = nullptr;
    static float* Wag = nullptr; static float* ba = nullptr;
    static float* wsum = nullptr; static float* cb = nullptr;
    static __half* WbH = nullptr;
    static cudaStream_t s2 = nullptr;
    static cudaEvent_t evF = nullptr, evJ = nullptr;
    if (!logits) {
        cudaGetSymbolAddress((void**)&logits, g_logits);
        cudaGetSymbolAddress((void**)&Pa, g_Pa);
        cudaGetSymbolAddress((void**)&Pb, g_Pb);
        cudaGetSymbolAddress((void**)&Wag, g_Wag);
        cudaGetSymbolAddress((void**)&ba, g_ba);
        cudaGetSymbolAddress((void**)&wsum, g_wsum);
        cudaGetSymbolAddress((void**)&cb, g_cb);
        cudaGetSymbolAddress((void**)&WbH, g_WbH);
        cudaFuncSetAttribute(h3_final_fused, cudaFuncAttributeMaxDynamicSharedMemorySize, FH_SMEM);
        cudaStreamCreateWithFlags(&s2, cudaStreamNonBlocking);
        cudaEventCreateWithFlags(&evF, cudaEventDisableTiming);
        cudaEventCreateWithFlags(&evJ, cudaEventDisableTiming);
    }

    // ---- fork: WbH prep chain on s2 (independent until the fused kernel) ----
    cudaEventRecord(evF, 0);
    cudaStreamWaitEvent(s2, evF, 0);
    prep_gemm_splitk<<<dim3(KSLOT / 64, DD / 64, NSPLIT), 256, 0, s2>>>(w_out, w1, Pb, DD, KSLOT, DD);
    reduce_partials_h<<<(DD * KSLOT + 255) / 256, 256, 0, s2>>>(Pb, WbH, DD * KSLOT);
    cudaEventRecord(evJ, s2);

    // ---- main stream: Wa chain + logits path ----
    prep_gemm_splitk<<<dim3(DD / 64, KSLOT / 64, NSPLIT), 256>>>(w0, w_in, Pa, KSLOT, DD, DD);
    fuse_bias_kernel<<<KSLOT, 256>>>(w0, b_in, ba);
    prep_wag_kernel<<<KSLOT, 256>>>(Pa, ln_g, ln_b, ba, Wag, wsum, cb);

    // logits = LN(x) @ Wa^T + ba, fused, also emits softmax chunk partials
    gemm_ln_logits<<<dim3(1, MTOT / 128), 256>>>(x, Wag, wsum, cb, logits);
    softmax_pass2<<<BB, 128>>>();

    // ---- join, then fused: softmax-normalize + h3 + LN + residual + relu ----
    cudaStreamWaitEvent(0, evJ, 0);
    h3_final_fused<<<MTOT / 32, 256, FH_SMEM>>>(logits, WbH, x, og, ob, out);
}